// round 2
// baseline (speedup 1.0000x reference)
#include <cuda_runtime.h>
#include <cuda_bf16.h>
#include <math.h>

// Problem constants
#define LAYERS 2
#define DMODEL 2048
#define NHEAD  16
#define HDIM   128
#define FFDIM  5632
#define RLORA  16
#define BATCH  4
#define SEQ    512
#define BB     8            // combined batch (text + mis)
#define MTOK   (BB*SEQ)     // 4096 tokens
#define LORA_SCALE 1.4f

// ---------------- scratch (static device globals; allocation-free) ----------------
__device__ float g_h   [MTOK * DMODEL];
__device__ float g_x   [MTOK * DMODEL];
__device__ float g_q   [MTOK * DMODEL];
__device__ float g_k   [MTOK * DMODEL];
__device__ float g_v   [MTOK * DMODEL];
__device__ float g_o   [MTOK * DMODEL];
__device__ float g_sc  [BB * NHEAD * SEQ * SEQ];
__device__ float g_gate[MTOK * FFDIM];
__device__ float g_up  [MTOK * FFDIM];
__device__ float g_t   [MTOK * RLORA];
__device__ float g_reps[BB * DMODEL];

// ---------------- embedding gather ----------------
__global__ void embed_kernel(const int* __restrict__ idT, const int* __restrict__ idM,
                             const float* __restrict__ E, float* __restrict__ H)
{
    int t  = blockIdx.x;           // token 0..4095
    int bb = t >> 9;
    int s  = t & 511;
    int id = (bb < 4) ? idT[bb * SEQ + s] : idM[(bb - 4) * SEQ + s];
    const float4* src = reinterpret_cast<const float4*>(E + (size_t)id * DMODEL);
    float4*       dst = reinterpret_cast<float4*>(H + (size_t)t * DMODEL);
    for (int j = threadIdx.x; j < DMODEL / 4; j += blockDim.x) dst[j] = src[j];
}

// ---------------- rmsnorm (row per block) ----------------
__global__ void rmsnorm_kernel(const float* __restrict__ H, const float* __restrict__ W,
                               float* __restrict__ X)
{
    __shared__ float red[256];
    int row = blockIdx.x;
    const float* h = H + (size_t)row * DMODEL;
    float s = 0.f;
    for (int j = threadIdx.x; j < DMODEL; j += 256) { float v = h[j]; s += v * v; }
    red[threadIdx.x] = s; __syncthreads();
    for (int o = 128; o > 0; o >>= 1) {
        if (threadIdx.x < o) red[threadIdx.x] += red[threadIdx.x + o];
        __syncthreads();
    }
    float scale = rsqrtf(red[0] / (float)DMODEL + 1e-6f);
    float* x = X + (size_t)row * DMODEL;
    for (int j = threadIdx.x; j < DMODEL; j += 256) x[j] = h[j] * scale * W[j];
}

// ---------------- lora down-projection: T = X @ A   (M x K x 16) ----------------
__global__ void lora_t_kernel(const float* __restrict__ X, const float* __restrict__ A,
                              float* __restrict__ T, int K)
{
    int row = blockIdx.x * 16 + (threadIdx.x >> 4);
    int r   = threadIdx.x & 15;
    const float* x = X + (size_t)row * K;
    float acc = 0.f;
    #pragma unroll 4
    for (int k = 0; k < K; k++) acc += x[k] * A[k * RLORA + r];
    T[row * RLORA + r] = acc;
}

// ---------------- main SGEMM: C = A@W (+ 1.4 * T@LB) (+= if accum) ----------------
// 128x128 tile, BK=16, 256 threads, 8x8 per thread
__global__ __launch_bounds__(256)
void gemm_kernel(const float* __restrict__ A, const float* __restrict__ W,
                 float* __restrict__ C, int M, int N, int K,
                 const float* __restrict__ lT, const float* __restrict__ lB,
                 int accum)
{
    __shared__ float As[16][128];
    __shared__ float Bs[16][128];
    __shared__ float Ls[16][128];

    const int tid = threadIdx.x;
    const int tx  = tid & 15;     // n
    const int ty  = tid >> 4;     // m
    const int bm  = blockIdx.y * 128;
    const int bn  = blockIdx.x * 128;

    if (lT) {
        for (int f = tid; f < 512; f += 256) {
            int r = f >> 5;
            int c = (f & 31) << 2;
            float4 v = *reinterpret_cast<const float4*>(&lB[(size_t)r * N + bn + c]);
            *reinterpret_cast<float4*>(&Ls[r][c]) = v;
        }
    }

    float acc[8][8];
    #pragma unroll
    for (int i = 0; i < 8; i++)
        #pragma unroll
        for (int j = 0; j < 8; j++) acc[i][j] = 0.f;

    for (int k0 = 0; k0 < K; k0 += 16) {
        for (int f = tid; f < 512; f += 256) {            // A: 128x16 (transpose into smem)
            int r = f >> 2;
            int c = (f & 3) << 2;
            float4 v = *reinterpret_cast<const float4*>(&A[(size_t)(bm + r) * K + k0 + c]);
            As[c + 0][r] = v.x; As[c + 1][r] = v.y; As[c + 2][r] = v.z; As[c + 3][r] = v.w;
        }
        for (int f = tid; f < 512; f += 256) {            // W: 16x128
            int r = f >> 5;
            int c = (f & 31) << 2;
            float4 v = *reinterpret_cast<const float4*>(&W[(size_t)(k0 + r) * N + bn + c]);
            *reinterpret_cast<float4*>(&Bs[r][c]) = v;
        }
        __syncthreads();
        #pragma unroll
        for (int k = 0; k < 16; k++) {
            float4 a0 = *reinterpret_cast<const float4*>(&As[k][ty * 8]);
            float4 a1 = *reinterpret_cast<const float4*>(&As[k][ty * 8 + 4]);
            float4 b0 = *reinterpret_cast<const float4*>(&Bs[k][tx * 8]);
            float4 b1 = *reinterpret_cast<const float4*>(&Bs[k][tx * 8 + 4]);
            float ra[8] = {a0.x, a0.y, a0.z, a0.w, a1.x, a1.y, a1.z, a1.w};
            float rb[8] = {b0.x, b0.y, b0.z, b0.w, b1.x, b1.y, b1.z, b1.w};
            #pragma unroll
            for (int i = 0; i < 8; i++)
                #pragma unroll
                for (int j = 0; j < 8; j++) acc[i][j] += ra[i] * rb[j];
        }
        __syncthreads();
    }

    #pragma unroll
    for (int i = 0; i < 8; i++) {
        int row = bm + ty * 8 + i;
        if (lT) {
            float4 t0 = *reinterpret_cast<const float4*>(&lT[row * RLORA + 0]);
            float4 t1 = *reinterpret_cast<const float4*>(&lT[row * RLORA + 4]);
            float4 t2 = *reinterpret_cast<const float4*>(&lT[row * RLORA + 8]);
            float4 t3 = *reinterpret_cast<const float4*>(&lT[row * RLORA + 12]);
            float tv[16] = {t0.x, t0.y, t0.z, t0.w, t1.x, t1.y, t1.z, t1.w,
                            t2.x, t2.y, t2.z, t2.w, t3.x, t3.y, t3.z, t3.w};
            #pragma unroll
            for (int r = 0; r < 16; r++) {
                float tvr = LORA_SCALE * tv[r];
                #pragma unroll
                for (int j = 0; j < 8; j++) acc[i][j] += tvr * Ls[r][tx * 8 + j];
            }
        }
        float* Crow = &C[(size_t)row * N + bn + tx * 8];
        float4 c0 = make_float4(acc[i][0], acc[i][1], acc[i][2], acc[i][3]);
        float4 c1 = make_float4(acc[i][4], acc[i][5], acc[i][6], acc[i][7]);
        if (accum) {
            float4 o0 = *reinterpret_cast<const float4*>(Crow);
            float4 o1 = *reinterpret_cast<const float4*>(Crow + 4);
            c0.x += o0.x; c0.y += o0.y; c0.z += o0.z; c0.w += o0.w;
            c1.x += o1.x; c1.y += o1.y; c1.z += o1.z; c1.w += o1.w;
        }
        *reinterpret_cast<float4*>(Crow)     = c0;
        *reinterpret_cast<float4*>(Crow + 4) = c1;
    }
}

// ---------------- RoPE on q and k ----------------
__global__ void rope_kernel(float* __restrict__ Q, float* __restrict__ Kt)
{
    int i = blockIdx.x * blockDim.x + threadIdx.x;   // MTOK * NHEAD * 64
    if (i >= MTOK * NHEAD * 64) return;
    int d = i & 63;
    int h = (i >> 6) & 15;
    int t = i >> 10;
    int s = t & 511;
    float freq = expf(-(float)d * (logf(10000.f) / 64.f));
    float ang = (float)s * freq;
    float sn, cs;
    sincosf(ang, &sn, &cs);
    size_t base = (size_t)t * DMODEL + h * HDIM + d;
    float x1 = Q[base], x2 = Q[base + 64];
    Q[base]      = x1 * cs - x2 * sn;
    Q[base + 64] = x1 * sn + x2 * cs;
    x1 = Kt[base]; x2 = Kt[base + 64];
    Kt[base]      = x1 * cs - x2 * sn;
    Kt[base + 64] = x1 * sn + x2 * cs;
}

// ---------------- attention scores + mask bias ----------------
__global__ void scores_kernel(const float* __restrict__ Q, const float* __restrict__ Kt,
                              const int* __restrict__ mT, const int* __restrict__ mM,
                              float* __restrict__ S_)
{
    __shared__ float qs[16][132];
    __shared__ float ks[16][132];
    int z  = blockIdx.z;             // bb*16 + h
    int bb = z >> 4;
    int h  = z & 15;
    int q0 = blockIdx.y * 16;
    int k0 = blockIdx.x * 16;
    int tid = threadIdx.y * 16 + threadIdx.x;
    for (int f = tid; f < 512; f += 256) {
        int r = f >> 5;
        int c = (f & 31) << 2;
        float4 vq = *reinterpret_cast<const float4*>(
            &Q[(size_t)(bb * SEQ + q0 + r) * DMODEL + h * HDIM + c]);
        qs[r][c] = vq.x; qs[r][c + 1] = vq.y; qs[r][c + 2] = vq.z; qs[r][c + 3] = vq.w;
        float4 vk = *reinterpret_cast<const float4*>(
            &Kt[(size_t)(bb * SEQ + k0 + r) * DMODEL + h * HDIM + c]);
        ks[r][c] = vk.x; ks[r][c + 1] = vk.y; ks[r][c + 2] = vk.z; ks[r][c + 3] = vk.w;
    }
    __syncthreads();
    int qi = threadIdx.y, kj = threadIdx.x;
    float acc = 0.f;
    #pragma unroll 8
    for (int d = 0; d < HDIM; d++) acc += qs[qi][d] * ks[kj][d];
    int sq = q0 + qi, sk = k0 + kj;
    const int* mask = (bb < 4) ? (mT + bb * SEQ) : (mM + (bb - 4) * SEQ);
    bool ok = (sk <= sq) && (mask[sk] > 0);
    float val = acc * 0.08838834764831845f + (ok ? 0.f : -1e9f);
    S_[((size_t)z * SEQ + sq) * SEQ + sk] = val;
}

// ---------------- row softmax (512 per row) ----------------
__global__ void softmax_kernel(float* __restrict__ S_)
{
    __shared__ float red[256];
    float* p = S_ + (size_t)blockIdx.x * SEQ;
    int t = threadIdx.x;
    float v0 = p[t], v1 = p[t + 256];
    float m = fmaxf(v0, v1);
    red[t] = m; __syncthreads();
    for (int o = 128; o > 0; o >>= 1) {
        if (t < o) red[t] = fmaxf(red[t], red[t + o]);
        __syncthreads();
    }
    m = red[0]; __syncthreads();
    float e0 = expf(v0 - m), e1 = expf(v1 - m);
    red[t] = e0 + e1; __syncthreads();
    for (int o = 128; o > 0; o >>= 1) {
        if (t < o) red[t] += red[t + o];
        __syncthreads();
    }
    float inv = 1.f / red[0];
    p[t] = e0 * inv; p[t + 256] = e1 * inv;
}

// ---------------- O = attn @ V ----------------
__global__ void attnv_kernel(const float* __restrict__ P, const float* __restrict__ V,
                             float* __restrict__ O)
{
    __shared__ float vs[16][128];
    __shared__ float as[4][16];
    int z  = blockIdx.y;
    int bb = z >> 4;
    int h  = z & 15;
    int q0 = blockIdx.x * 4;
    int tx = threadIdx.x;    // 0..127 (head dim)
    int ty = threadIdx.y;    // 0..3  (q row)
    int tid = ty * 128 + tx;
    const float* Prow = P + ((size_t)z * SEQ + q0) * SEQ;
    float acc = 0.f;
    for (int kt = 0; kt < SEQ; kt += 16) {
        for (int f = tid; f < 2048; f += 512) {
            int r = f >> 7, c = f & 127;
            vs[r][c] = V[(size_t)(bb * SEQ + kt + r) * DMODEL + h * HDIM + c];
        }
        if (tid < 64) {
            int r = tid >> 4, c = tid & 15;
            as[r][c] = Prow[r * SEQ + kt + c];
        }
        __syncthreads();
        #pragma unroll
        for (int kk = 0; kk < 16; kk++) acc += as[ty][kk] * vs[kk][tx];
        __syncthreads();
    }
    O[(size_t)(bb * SEQ + q0 + ty) * DMODEL + h * HDIM + tx] = acc;
}

// ---------------- swiglu: G = silu(G) * U ----------------
__global__ void swiglu_kernel(float* __restrict__ G, const float* __restrict__ U)
{
    size_t i = (size_t)blockIdx.x * blockDim.x + threadIdx.x;
    if (i >= (size_t)MTOK * FFDIM) return;
    float g = G[i];
    float sig = 1.f / (1.f + expf(-g));
    G[i] = g * sig * U[i];
}

// ---------------- reps extraction + L2 normalize ----------------
__global__ void reps_kernel(const float* __restrict__ X, const int* __restrict__ mT,
                            const int* __restrict__ mM, float* __restrict__ R_)
{
    __shared__ int ired[256];
    __shared__ float fred[256];
    __shared__ int sidx;
    int bb = blockIdx.x;
    const int* mask = (bb < 4) ? mT : mM;
    int b = bb & 3;
    int t = threadIdx.x;
    int s = 0;
    for (int j = t; j < SEQ; j += 256) s += mask[b * SEQ + j];
    ired[t] = s; __syncthreads();
    for (int o = 128; o > 0; o >>= 1) {
        if (t < o) ired[t] += ired[t + o];
        __syncthreads();
    }
    if (t == 0) {
        int last = mask[0 * SEQ + 511] + mask[1 * SEQ + 511] +
                   mask[2 * SEQ + 511] + mask[3 * SEQ + 511];
        sidx = (last == BATCH) ? (SEQ - 1) : (ired[0] - 1);
    }
    __syncthreads();
    const float* row = X + (size_t)(bb * SEQ + sidx) * DMODEL;
    float ss = 0.f;
    for (int j = t; j < DMODEL; j += 256) { float v = row[j]; ss += v * v; }
    fred[t] = ss; __syncthreads();
    for (int o = 128; o > 0; o >>= 1) {
        if (t < o) fred[t] += fred[t + o];
        __syncthreads();
    }
    float inv = 1.f / sqrtf(fred[0]);
    for (int j = t; j < DMODEL; j += 256) R_[bb * DMODEL + j] = row[j] * inv;
}

// ---------------- contrastive loss ----------------
__global__ void loss_kernel(const float* __restrict__ R_, float* __restrict__ out)
{
    __shared__ float sims[16];
    int tid = threadIdx.x;
    int warp = tid >> 5, lane = tid & 31;
    for (int p = warp; p < 16; p += 8) {
        int i = p >> 2, j = p & 3;
        const float* a = R_ + i * DMODEL;
        const float* bR = R_ + (4 + j) * DMODEL;
        float d = 0.f;
        for (int k2 = lane; k2 < DMODEL; k2 += 32) d += a[k2] * bR[k2];
        #pragma unroll
        for (int o = 16; o > 0; o >>= 1) d += __shfl_xor_sync(0xffffffff, d, o);
        if (lane == 0) sims[p] = d * 20.f;     // / TEMP(0.05)
    }
    __syncthreads();
    if (tid == 0) {
        float loss = 0.f;
        for (int i = 0; i < 4; i++) {
            float m = -1e30f;
            for (int j = 0; j < 4; j++) m = fmaxf(m, sims[i * 4 + j]);
            float sum = 0.f;
            for (int j = 0; j < 4; j++) sum += expf(sims[i * 4 + j] - m);
            loss += (logf(sum) + m) - sims[i * 4 + i];
        }
        out[0] = loss * 0.25f;
    }
}

// ---------------- host driver ----------------
static float* symaddr(const void* sym)
{
    void* p = nullptr;
    cudaGetSymbolAddress(&p, sym);
    return (float*)p;
}

extern "C" void kernel_launch(void* const* d_in, const int* in_sizes, int n_in,
                              void* d_out, int out_size)
{
    const int*   idT = (const int*)d_in[0];
    const int*   mT  = (const int*)d_in[1];
    const int*   idM = (const int*)d_in[2];
    const int*   mM  = (const int*)d_in[3];
    const float* emb = (const float*)d_in[4];
    const float* ln1 = (const float*)d_in[5];
    const float* ln2 = (const float*)d_in[6];
    const float* lnf = (const float*)d_in[7];
    const float* Wq = (const float*)d_in[8],  *Aq = (const float*)d_in[9],  *Bq = (const float*)d_in[10];
    const float* Wk = (const float*)d_in[11], *Ak = (const float*)d_in[12], *Bk = (const float*)d_in[13];
    const float* Wv = (const float*)d_in[14], *Av = (const float*)d_in[15], *Bv = (const float*)d_in[16];
    const float* Wo = (const float*)d_in[17], *Ao = (const float*)d_in[18], *Bo = (const float*)d_in[19];
    const float* Wg = (const float*)d_in[20], *Ag = (const float*)d_in[21], *Bg = (const float*)d_in[22];
    const float* Wu = (const float*)d_in[23], *Au = (const float*)d_in[24], *Bu = (const float*)d_in[25];
    const float* Wd = (const float*)d_in[26], *Ad = (const float*)d_in[27], *Bd = (const float*)d_in[28];

    float* h  = symaddr(g_h);
    float* x  = symaddr(g_x);
    float* q  = symaddr(g_q);
    float* k  = symaddr(g_k);
    float* v  = symaddr(g_v);
    float* o  = symaddr(g_o);
    float* sc = symaddr(g_sc);
    float* gg = symaddr(g_gate);
    float* uu = symaddr(g_up);
    float* t  = symaddr(g_t);
    float* rp = symaddr(g_reps);

    embed_kernel<<<MTOK, 256>>>(idT, idM, emb, h);

    const dim3 gD(DMODEL / 128, MTOK / 128);   // N=2048
    const dim3 gF(FFDIM / 128, MTOK / 128);    // N=5632

    for (int l = 0; l < LAYERS; l++) {
        const float* Wq_l = Wq + (size_t)l * DMODEL * DMODEL;
        const float* Wk_l = Wk + (size_t)l * DMODEL * DMODEL;
        const float* Wv_l = Wv + (size_t)l * DMODEL * DMODEL;
        const float* Wo_l = Wo + (size_t)l * DMODEL * DMODEL;
        const float* Wg_l = Wg + (size_t)l * DMODEL * FFDIM;
        const float* Wu_l = Wu + (size_t)l * DMODEL * FFDIM;
        const float* Wd_l = Wd + (size_t)l * FFDIM * DMODEL;
        const float* Aq_l = Aq + (size_t)l * DMODEL * RLORA;
        const float* Ak_l = Ak + (size_t)l * DMODEL * RLORA;
        const float* Av_l = Av + (size_t)l * DMODEL * RLORA;
        const float* Ao_l = Ao + (size_t)l * DMODEL * RLORA;
        const float* Ag_l = Ag + (size_t)l * DMODEL * RLORA;
        const float* Au_l = Au + (size_t)l * DMODEL * RLORA;
        const float* Ad_l = Ad + (size_t)l * FFDIM * RLORA;
        const float* Bq_l = Bq + (size_t)l * RLORA * DMODEL;
        const float* Bk_l = Bk + (size_t)l * RLORA * DMODEL;
        const float* Bv_l = Bv + (size_t)l * RLORA * DMODEL;
        const float* Bo_l = Bo + (size_t)l * RLORA * DMODEL;
        const float* Bg_l = Bg + (size_t)l * RLORA * FFDIM;
        const float* Bu_l = Bu + (size_t)l * RLORA * FFDIM;
        const float* Bd_l = Bd + (size_t)l * RLORA * DMODEL;

        rmsnorm_kernel<<<MTOK, 256>>>(h, ln1 + l * DMODEL, x);

        lora_t_kernel<<<MTOK / 16, 256>>>(x, Aq_l, t, DMODEL);
        gemm_kernel<<<gD, 256>>>(x, Wq_l, q, MTOK, DMODEL, DMODEL, t, Bq_l, 0);
        lora_t_kernel<<<MTOK / 16, 256>>>(x, Ak_l, t, DMODEL);
        gemm_kernel<<<gD, 256>>>(x, Wk_l, k, MTOK, DMODEL, DMODEL, t, Bk_l, 0);
        lora_t_kernel<<<MTOK / 16, 256>>>(x, Av_l, t, DMODEL);
        gemm_kernel<<<gD, 256>>>(x, Wv_l, v, MTOK, DMODEL, DMODEL, t, Bv_l, 0);

        rope_kernel<<<(MTOK * NHEAD * 64 + 255) / 256, 256>>>(q, k);

        scores_kernel<<<dim3(SEQ / 16, SEQ / 16, BB * NHEAD), dim3(16, 16)>>>(q, k, mT, mM, sc);
        softmax_kernel<<<BB * NHEAD * SEQ, 256>>>(sc);
        attnv_kernel<<<dim3(SEQ / 4, BB * NHEAD), dim3(128, 4)>>>(sc, v, o);

        lora_t_kernel<<<MTOK / 16, 256>>>(o, Ao_l, t, DMODEL);
        gemm_kernel<<<gD, 256>>>(o, Wo_l, h, MTOK, DMODEL, DMODEL, t, Bo_l, 1);

        rmsnorm_kernel<<<MTOK, 256>>>(h, ln2 + l * DMODEL, x);

        lora_t_kernel<<<MTOK / 16, 256>>>(x, Ag_l, t, DMODEL);
        gemm_kernel<<<gF, 256>>>(x, Wg_l, gg, MTOK, FFDIM, DMODEL, t, Bg_l, 0);
        lora_t_kernel<<<MTOK / 16, 256>>>(x, Au_l, t, DMODEL);
        gemm_kernel<<<gF, 256>>>(x, Wu_l, uu, MTOK, FFDIM, DMODEL, t, Bu_l, 0);

        swiglu_kernel<<<(int)(((size_t)MTOK * FFDIM + 255) / 256), 256>>>(gg, uu);

        lora_t_kernel<<<MTOK / 16, 256>>>(gg, Ad_l, t, FFDIM);
        gemm_kernel<<<gD, 256>>>(gg, Wd_l, h, MTOK, DMODEL, FFDIM, t, Bd_l, 1);
    }

    rmsnorm_kernel<<<MTOK, 256>>>(h, lnf, x);
    reps_kernel<<<BB, 256>>>(x, mT, mM, rp);
    loss_kernel<<<1, 256>>>(rp, (float*)d_out);
}

// round 4
// speedup vs baseline: 1.4495x; 1.4495x over previous
#include <cuda_runtime.h>
#include <cuda_bf16.h>
#include <math.h>
#include <stdint.h>

// Problem constants
#define LAYERS 2
#define DMODEL 2048
#define NHEAD  16
#define HDIM   128
#define FFDIM  5632
#define RLORA  16
#define BATCH  4
#define SEQ    512
#define BB     8            // combined batch (text + mis)
#define MTOK   (BB*SEQ)     // 4096 tokens
#define LORA_SCALE 1.4f

// ---------------- scratch (static device globals; allocation-free) ----------------
__device__ float g_h   [MTOK * DMODEL];
__device__ float g_x   [MTOK * DMODEL];
__device__ float g_q   [MTOK * DMODEL];
__device__ float g_k   [MTOK * DMODEL];
__device__ float g_v   [MTOK * DMODEL];
__device__ float g_o   [MTOK * DMODEL];
__device__ float g_sc  [BB * NHEAD * SEQ * SEQ];
__device__ float g_gate[MTOK * FFDIM];
__device__ float g_up  [MTOK * FFDIM];
__device__ float g_t   [MTOK * RLORA];
__device__ float g_reps[BB * DMODEL];
// transposed weights: per layer 4*D*D + 3*D*FF floats
__device__ float g_wt  [2 * (4 * DMODEL * DMODEL + 3 * DMODEL * FFDIM)];

// =================== warp-MMA helpers (baseline PTX, works on sm_103 target) ===================
__device__ __forceinline__ uint32_t tf32_rna(float x) {
    uint32_t u;
    asm("cvt.rna.tf32.f32 %0, %1;" : "=r"(u) : "f"(x));
    return u;
}
__device__ __forceinline__ void mma8(float* d, const uint32_t* a, uint32_t b0, uint32_t b1) {
    asm volatile(
        "mma.sync.aligned.m16n8k8.row.col.f32.tf32.tf32.f32 "
        "{%0,%1,%2,%3}, {%4,%5,%6,%7}, {%8,%9}, {%0,%1,%2,%3};"
        : "+f"(d[0]), "+f"(d[1]), "+f"(d[2]), "+f"(d[3])
        : "r"(a[0]), "r"(a[1]), "r"(a[2]), "r"(a[3]), "r"(b0), "r"(b1));
}

// smem stage layout (floats): Ah[2560] Al[2560] Bh[2560] Bl[2560], row stride 20 (pad)
#define PAD    20
#define ARR    2560
#define STAGEF (4 * ARR)                 // 10240 floats per stage
#define GSMEM  (2 * STAGEF * 4)          // 81920 bytes

// =================== tensor-core GEMM, tf32x3, LoRA fused as extra K-chunk ===================
// C[M,N] = A[M,K] @ Wt^T  + 1.4 * T[M,16] @ lB[16,N]   (+= C if accum)
// Wt: [N,K] row-major (W transposed).
__global__ __launch_bounds__(256)
void gemm_tc(const float* __restrict__ A, const float* __restrict__ Wt,
             float* __restrict__ C, int M, int N, int K,
             const float* __restrict__ lT, const float* __restrict__ lB, int accum)
{
    extern __shared__ float sm[];
    const int tid  = threadIdx.x;
    const int wid  = tid >> 5;
    const int lane = tid & 31;
    const int g    = lane >> 2;      // 0..7
    const int t4   = lane & 3;       // 0..3
    const int wm   = wid >> 1;       // 0..3  (M)
    const int wn   = wid & 1;        // 0..1  (N)
    const int bm   = blockIdx.y * 128;
    const int bn   = blockIdx.x * 128;

    const int nk    = K >> 4;        // main K chunks of 16
    const int nkTot = nk + 1;        // + fused lora chunk

    float d[2][8][4];
    #pragma unroll
    for (int mt = 0; mt < 2; mt++)
        #pragma unroll
        for (int nt = 0; nt < 8; nt++)
            #pragma unroll
            for (int j = 0; j < 4; j++) d[mt][nt][j] = 0.f;

    // ---- staging regs: each thread moves 2 float4 of A and 2 of B per chunk ----
    float4 ra[2], rb[2];

    const int f0   = tid;            // element indices into the 128x16 chunk (as float4s)
    const int f1   = tid + 256;
    const int row0 = f0 >> 2, col0 = (f0 & 3) << 2;
    const int row1 = f1 >> 2, col1 = (f1 & 3) << 2;

    auto load_chunk = [&](int kt) {
        if (kt < nk) {
            const int k0 = kt << 4;
            ra[0] = *(const float4*)(A  + (size_t)(bm + row0) * K + k0 + col0);
            ra[1] = *(const float4*)(A  + (size_t)(bm + row1) * K + k0 + col1);
            rb[0] = *(const float4*)(Wt + (size_t)(bn + row0) * K + k0 + col0);
            rb[1] = *(const float4*)(Wt + (size_t)(bn + row1) * K + k0 + col1);
        } else {
            // LoRA chunk: A-part = 1.4 * T[m][0..15], B-part = lB[r][n] transposed
            float4 t0 = *(const float4*)(lT + (size_t)(bm + row0) * RLORA + col0);
            float4 t1 = *(const float4*)(lT + (size_t)(bm + row1) * RLORA + col1);
            ra[0] = make_float4(LORA_SCALE * t0.x, LORA_SCALE * t0.y,
                                LORA_SCALE * t0.z, LORA_SCALE * t0.w);
            ra[1] = make_float4(LORA_SCALE * t1.x, LORA_SCALE * t1.y,
                                LORA_SCALE * t1.z, LORA_SCALE * t1.w);
            rb[0].x = lB[(size_t)(col0 + 0) * N + bn + row0];
            rb[0].y = lB[(size_t)(col0 + 1) * N + bn + row0];
            rb[0].z = lB[(size_t)(col0 + 2) * N + bn + row0];
            rb[0].w = lB[(size_t)(col0 + 3) * N + bn + row0];
            rb[1].x = lB[(size_t)(col1 + 0) * N + bn + row1];
            rb[1].y = lB[(size_t)(col1 + 1) * N + bn + row1];
            rb[1].z = lB[(size_t)(col1 + 2) * N + bn + row1];
            rb[1].w = lB[(size_t)(col1 + 3) * N + bn + row1];
        }
    };

    auto split4 = [&](float4 v, float4& h4, float4& l4) {
        h4.x = __uint_as_float(tf32_rna(v.x)); l4.x = v.x - h4.x;
        h4.y = __uint_as_float(tf32_rna(v.y)); l4.y = v.y - h4.y;
        h4.z = __uint_as_float(tf32_rna(v.z)); l4.z = v.z - h4.z;
        h4.w = __uint_as_float(tf32_rna(v.w)); l4.w = v.w - h4.w;
    };

    auto store_chunk = [&](int buf) {
        float* Ah = sm + buf * STAGEF;
        float* Al = Ah + ARR;
        float* Bh = Ah + 2 * ARR;
        float* Bl = Ah + 3 * ARR;
        float4 h4, l4;
        split4(ra[0], h4, l4);
        *(float4*)(Ah + row0 * PAD + col0) = h4;
        *(float4*)(Al + row0 * PAD + col0) = l4;
        split4(ra[1], h4, l4);
        *(float4*)(Ah + row1 * PAD + col1) = h4;
        *(float4*)(Al + row1 * PAD + col1) = l4;
        split4(rb[0], h4, l4);
        *(float4*)(Bh + row0 * PAD + col0) = h4;
        *(float4*)(Bl + row0 * PAD + col0) = l4;
        split4(rb[1], h4, l4);
        *(float4*)(Bh + row1 * PAD + col1) = h4;
        *(float4*)(Bl + row1 * PAD + col1) = l4;
    };

    load_chunk(0);
    store_chunk(0);
    __syncthreads();

    for (int kt = 0; kt < nkTot; kt++) {
        const int buf = kt & 1;
        if (kt + 1 < nkTot) load_chunk(kt + 1);

        const float* Ah = sm + buf * STAGEF;
        const float* Al = Ah + ARR;
        const float* Bh = Ah + 2 * ARR;
        const float* Bl = Ah + 3 * ARR;

        #pragma unroll
        for (int ks = 0; ks < 16; ks += 8) {
            uint32_t ah[2][4], al[2][4];
            #pragma unroll
            for (int mt = 0; mt < 2; mt++) {
                const float* pa = Ah + (wm * 32 + mt * 16 + g) * PAD + ks + t4;
                const float* pl = Al + (wm * 32 + mt * 16 + g) * PAD + ks + t4;
                ah[mt][0] = __float_as_uint(pa[0]);
                ah[mt][1] = __float_as_uint(pa[8 * PAD]);
                ah[mt][2] = __float_as_uint(pa[4]);
                ah[mt][3] = __float_as_uint(pa[8 * PAD + 4]);
                al[mt][0] = __float_as_uint(pl[0]);
                al[mt][1] = __float_as_uint(pl[8 * PAD]);
                al[mt][2] = __float_as_uint(pl[4]);
                al[mt][3] = __float_as_uint(pl[8 * PAD + 4]);
            }
            #pragma unroll
            for (int nt = 0; nt < 8; nt++) {
                const float* pb = Bh + (wn * 64 + nt * 8 + g) * PAD + ks + t4;
                const float* pq = Bl + (wn * 64 + nt * 8 + g) * PAD + ks + t4;
                uint32_t b0h = __float_as_uint(pb[0]);
                uint32_t b1h = __float_as_uint(pb[4]);
                uint32_t b0l = __float_as_uint(pq[0]);
                uint32_t b1l = __float_as_uint(pq[4]);
                #pragma unroll
                for (int mt = 0; mt < 2; mt++) {
                    mma8(d[mt][nt], ah[mt], b0h, b1h);
                    mma8(d[mt][nt], ah[mt], b0l, b1l);
                    mma8(d[mt][nt], al[mt], b0h, b1h);
                }
            }
        }

        if (kt + 1 < nkTot) {
            __syncthreads();               // everyone done with the other buffer
            store_chunk((kt + 1) & 1);
            __syncthreads();               // stores visible
        }
    }

    // ---- epilogue: fragments -> C (optional residual accumulate) ----
    #pragma unroll
    for (int mt = 0; mt < 2; mt++) {
        const int r0 = bm + wm * 32 + mt * 16 + g;
        #pragma unroll
        for (int nt = 0; nt < 8; nt++) {
            const int c0 = bn + wn * 64 + nt * 8 + 2 * t4;
            float2 v0 = make_float2(d[mt][nt][0], d[mt][nt][1]);
            float2 v1 = make_float2(d[mt][nt][2], d[mt][nt][3]);
            float* p0 = C + (size_t)r0 * N + c0;
            float* p1 = C + (size_t)(r0 + 8) * N + c0;
            if (accum) {
                float2 o0 = *(const float2*)p0;
                float2 o1 = *(const float2*)p1;
                v0.x += o0.x; v0.y += o0.y;
                v1.x += o1.x; v1.y += o1.y;
            }
            *(float2*)p0 = v0;
            *(float2*)p1 = v1;
        }
    }
}

// ---------------- weight transpose: Wt[n*K+k] = W[k*N+n] ----------------
__global__ void transpose_kernel(const float* __restrict__ W, float* __restrict__ Wt,
                                 int Kd, int Nd)
{
    __shared__ float tile[32][33];
    int n0 = blockIdx.x * 32, k0 = blockIdx.y * 32;
    int x = threadIdx.x, y = threadIdx.y;
    #pragma unroll
    for (int dy = 0; dy < 32; dy += 8)
        tile[y + dy][x] = W[(size_t)(k0 + y + dy) * Nd + n0 + x];
    __syncthreads();
    #pragma unroll
    for (int dy = 0; dy < 32; dy += 8)
        Wt[(size_t)(n0 + y + dy) * Kd + k0 + x] = tile[x][y + dy];
}

// ---------------- embedding gather ----------------
__global__ void embed_kernel(const int* __restrict__ idT, const int* __restrict__ idM,
                             const float* __restrict__ E, float* __restrict__ H)
{
    int t  = blockIdx.x;
    int bb = t >> 9;
    int s  = t & 511;
    int id = (bb < 4) ? idT[bb * SEQ + s] : idM[(bb - 4) * SEQ + s];
    const float4* src = reinterpret_cast<const float4*>(E + (size_t)id * DMODEL);
    float4*       dst = reinterpret_cast<float4*>(H + (size_t)t * DMODEL);
    for (int j = threadIdx.x; j < DMODEL / 4; j += blockDim.x) dst[j] = src[j];
}

// ---------------- rmsnorm ----------------
__global__ void rmsnorm_kernel(const float* __restrict__ H, const float* __restrict__ W,
                               float* __restrict__ X)
{
    __shared__ float red[256];
    int row = blockIdx.x;
    const float* h = H + (size_t)row * DMODEL;
    float s = 0.f;
    for (int j = threadIdx.x; j < DMODEL; j += 256) { float v = h[j]; s += v * v; }
    red[threadIdx.x] = s; __syncthreads();
    for (int o = 128; o > 0; o >>= 1) {
        if (threadIdx.x < o) red[threadIdx.x] += red[threadIdx.x + o];
        __syncthreads();
    }
    float scale = rsqrtf(red[0] / (float)DMODEL + 1e-6f);
    float* x = X + (size_t)row * DMODEL;
    for (int j = threadIdx.x; j < DMODEL; j += 256) x[j] = h[j] * scale * W[j];
}

// ---------------- lora down-projection: T = X @ A ----------------
__global__ void lora_t_kernel(const float* __restrict__ X, const float* __restrict__ A,
                              float* __restrict__ T, int K)
{
    int row = blockIdx.x * 16 + (threadIdx.x >> 4);
    int r   = threadIdx.x & 15;
    const float* x = X + (size_t)row * K;
    float acc = 0.f;
    #pragma unroll 4
    for (int k = 0; k < K; k++) acc += x[k] * A[k * RLORA + r];
    T[row * RLORA + r] = acc;
}

// ---------------- RoPE on q and k ----------------
__global__ void rope_kernel(float* __restrict__ Q, float* __restrict__ Kt)
{
    int i = blockIdx.x * blockDim.x + threadIdx.x;
    if (i >= MTOK * NHEAD * 64) return;
    int d = i & 63;
    int h = (i >> 6) & 15;
    int t = i >> 10;
    int s = t & 511;
    float freq = expf(-(float)d * (logf(10000.f) / 64.f));
    float ang = (float)s * freq;
    float sn, cs;
    sincosf(ang, &sn, &cs);
    size_t baseo = (size_t)t * DMODEL + h * HDIM + d;
    float x1 = Q[baseo], x2 = Q[baseo + 64];
    Q[baseo]      = x1 * cs - x2 * sn;
    Q[baseo + 64] = x1 * sn + x2 * cs;
    x1 = Kt[baseo]; x2 = Kt[baseo + 64];
    Kt[baseo]      = x1 * cs - x2 * sn;
    Kt[baseo + 64] = x1 * sn + x2 * cs;
}

// ---------------- attention scores + mask bias ----------------
__global__ void scores_kernel(const float* __restrict__ Q, const float* __restrict__ Kt,
                              const int* __restrict__ mT, const int* __restrict__ mM,
                              float* __restrict__ S_)
{
    __shared__ float qs[16][132];
    __shared__ float ks[16][132];
    int z  = blockIdx.z;
    int bb = z >> 4;
    int h  = z & 15;
    int q0 = blockIdx.y * 16;
    int k0 = blockIdx.x * 16;
    int tid = threadIdx.y * 16 + threadIdx.x;
    for (int f = tid; f < 512; f += 256) {
        int r = f >> 5;
        int c = (f & 31) << 2;
        float4 vq = *reinterpret_cast<const float4*>(
            &Q[(size_t)(bb * SEQ + q0 + r) * DMODEL + h * HDIM + c]);
        qs[r][c] = vq.x; qs[r][c + 1] = vq.y; qs[r][c + 2] = vq.z; qs[r][c + 3] = vq.w;
        float4 vk = *reinterpret_cast<const float4*>(
            &Kt[(size_t)(bb * SEQ + k0 + r) * DMODEL + h * HDIM + c]);
        ks[r][c] = vk.x; ks[r][c + 1] = vk.y; ks[r][c + 2] = vk.z; ks[r][c + 3] = vk.w;
    }
    __syncthreads();
    int qi = threadIdx.y, kj = threadIdx.x;
    float acc = 0.f;
    #pragma unroll 8
    for (int d = 0; d < HDIM; d++) acc += qs[qi][d] * ks[kj][d];
    int sq = q0 + qi, sk = k0 + kj;
    const int* mask = (bb < 4) ? (mT + bb * SEQ) : (mM + (bb - 4) * SEQ);
    bool ok = (sk <= sq) && (mask[sk] > 0);
    float val = acc * 0.08838834764831845f + (ok ? 0.f : -1e9f);
    S_[((size_t)z * SEQ + sq) * SEQ + sk] = val;
}

// ---------------- row softmax ----------------
__global__ void softmax_kernel(float* __restrict__ S_)
{
    __shared__ float red[256];
    float* p = S_ + (size_t)blockIdx.x * SEQ;
    int t = threadIdx.x;
    float v0 = p[t], v1 = p[t + 256];
    float m = fmaxf(v0, v1);
    red[t] = m; __syncthreads();
    for (int o = 128; o > 0; o >>= 1) {
        if (t < o) red[t] = fmaxf(red[t], red[t + o]);
        __syncthreads();
    }
    m = red[0]; __syncthreads();
    float e0 = expf(v0 - m), e1 = expf(v1 - m);
    red[t] = e0 + e1; __syncthreads();
    for (int o = 128; o > 0; o >>= 1) {
        if (t < o) red[t] += red[t + o];
        __syncthreads();
    }
    float inv = 1.f / red[0];
    p[t] = e0 * inv; p[t + 256] = e1 * inv;
}

// ---------------- O = attn @ V ----------------
__global__ void attnv_kernel(const float* __restrict__ P, const float* __restrict__ V,
                             float* __restrict__ O)
{
    __shared__ float vs[16][128];
    __shared__ float as[4][16];
    int z  = blockIdx.y;
    int bb = z >> 4;
    int h  = z & 15;
    int q0 = blockIdx.x * 4;
    int tx = threadIdx.x;
    int ty = threadIdx.y;
    int tid = ty * 128 + tx;
    const float* Prow = P + ((size_t)z * SEQ + q0) * SEQ;
    float acc = 0.f;
    for (int kt = 0; kt < SEQ; kt += 16) {
        for (int f = tid; f < 2048; f += 512) {
            int r = f >> 7, c = f & 127;
            vs[r][c] = V[(size_t)(bb * SEQ + kt + r) * DMODEL + h * HDIM + c];
        }
        if (tid < 64) {
            int r = tid >> 4, c = tid & 15;
            as[r][c] = Prow[r * SEQ + kt + c];
        }
        __syncthreads();
        #pragma unroll
        for (int kk = 0; kk < 16; kk++) acc += as[ty][kk] * vs[kk][tx];
        __syncthreads();
    }
    O[(size_t)(bb * SEQ + q0 + ty) * DMODEL + h * HDIM + tx] = acc;
}

// ---------------- swiglu ----------------
__global__ void swiglu_kernel(float* __restrict__ G, const float* __restrict__ U)
{
    size_t i = (size_t)blockIdx.x * blockDim.x + threadIdx.x;
    if (i >= (size_t)MTOK * FFDIM) return;
    float g = G[i];
    float sig = 1.f / (1.f + expf(-g));
    G[i] = g * sig * U[i];
}

// ---------------- reps extraction + L2 normalize ----------------
__global__ void reps_kernel(const float* __restrict__ X, const int* __restrict__ mT,
                            const int* __restrict__ mM, float* __restrict__ R_)
{
    __shared__ int ired[256];
    __shared__ float fred[256];
    __shared__ int sidx;
    int bb = blockIdx.x;
    const int* mask = (bb < 4) ? mT : mM;
    int b = bb & 3;
    int t = threadIdx.x;
    int s = 0;
    for (int j = t; j < SEQ; j += 256) s += mask[b * SEQ + j];
    ired[t] = s; __syncthreads();
    for (int o = 128; o > 0; o >>= 1) {
        if (t < o) ired[t] += ired[t + o];
        __syncthreads();
    }
    if (t == 0) {
        int last = mask[0 * SEQ + 511] + mask[1 * SEQ + 511] +
                   mask[2 * SEQ + 511] + mask[3 * SEQ + 511];
        sidx = (last == BATCH) ? (SEQ - 1) : (ired[0] - 1);
    }
    __syncthreads();
    const float* row = X + (size_t)(bb * SEQ + sidx) * DMODEL;
    float ss = 0.f;
    for (int j = t; j < DMODEL; j += 256) { float v = row[j]; ss += v * v; }
    fred[t] = ss; __syncthreads();
    for (int o = 128; o > 0; o >>= 1) {
        if (t < o) fred[t] += fred[t + o];
        __syncthreads();
    }
    float inv = 1.f / sqrtf(fred[0]);
    for (int j = t; j < DMODEL; j += 256) R_[bb * DMODEL + j] = row[j] * inv;
}

// ---------------- contrastive loss ----------------
__global__ void loss_kernel(const float* __restrict__ R_, float* __restrict__ out)
{
    __shared__ float sims[16];
    int tid = threadIdx.x;
    int warp = tid >> 5, lane = tid & 31;
    for (int p = warp; p < 16; p += 8) {
        int i = p >> 2, j = p & 3;
        const float* a = R_ + i * DMODEL;
        const float* bR = R_ + (4 + j) * DMODEL;
        float d = 0.f;
        for (int k2 = lane; k2 < DMODEL; k2 += 32) d += a[k2] * bR[k2];
        #pragma unroll
        for (int o = 16; o > 0; o >>= 1) d += __shfl_xor_sync(0xffffffff, d, o);
        if (lane == 0) sims[p] = d * 20.f;
    }
    __syncthreads();
    if (tid == 0) {
        float loss = 0.f;
        for (int i = 0; i < 4; i++) {
            float m = -1e30f;
            for (int j = 0; j < 4; j++) m = fmaxf(m, sims[i * 4 + j]);
            float sum = 0.f;
            for (int j = 0; j < 4; j++) sum += expf(sims[i * 4 + j] - m);
            loss += (logf(sum) + m) - sims[i * 4 + i];
        }
        out[0] = loss * 0.25f;
    }
}

// ---------------- host driver ----------------
static float* symaddr(const void* sym)
{
    void* p = nullptr;
    cudaGetSymbolAddress(&p, sym);
    return (float*)p;
}

extern "C" void kernel_launch(void* const* d_in, const int* in_sizes, int n_in,
                              void* d_out, int out_size)
{
    const int*   idT = (const int*)d_in[0];
    const int*   mT  = (const int*)d_in[1];
    const int*   idM = (const int*)d_in[2];
    const int*   mM  = (const int*)d_in[3];
    const float* emb = (const float*)d_in[4];
    const float* ln1 = (const float*)d_in[5];
    const float* ln2 = (const float*)d_in[6];
    const float* lnf = (const float*)d_in[7];
    const float* Wq = (const float*)d_in[8],  *Aq = (const float*)d_in[9],  *Bq = (const float*)d_in[10];
    const float* Wk = (const float*)d_in[11], *Ak = (const float*)d_in[12], *Bk = (const float*)d_in[13];
    const float* Wv = (const float*)d_in[14], *Av = (const float*)d_in[15], *Bv = (const float*)d_in[16];
    const float* Wo = (const float*)d_in[17], *Ao = (const float*)d_in[18], *Bo = (const float*)d_in[19];
    const float* Wg = (const float*)d_in[20], *Ag = (const float*)d_in[21], *Bg = (const float*)d_in[22];
    const float* Wu = (const float*)d_in[23], *Au = (const float*)d_in[24], *Bu = (const float*)d_in[25];
    const float* Wd = (const float*)d_in[26], *Ad = (const float*)d_in[27], *Bd = (const float*)d_in[28];

    float* h  = symaddr(g_h);
    float* x  = symaddr(g_x);
    float* q  = symaddr(g_q);
    float* k  = symaddr(g_k);
    float* v  = symaddr(g_v);
    float* o  = symaddr(g_o);
    float* sc = symaddr(g_sc);
    float* gg = symaddr(g_gate);
    float* uu = symaddr(g_up);
    float* t  = symaddr(g_t);
    float* rp = symaddr(g_reps);
    float* wt = symaddr(g_wt);

    cudaFuncSetAttribute(gemm_tc, cudaFuncAttributeMaxDynamicSharedMemorySize, GSMEM);

    const size_t DD = (size_t)DMODEL * DMODEL;
    const size_t DF = (size_t)DMODEL * FFDIM;
    const size_t LSTR = 4 * DD + 3 * DF;

    // transpose all weights: Wt[n][k] = W[k][n]
    for (int l = 0; l < LAYERS; l++) {
        float* wl = wt + l * LSTR;
        transpose_kernel<<<dim3(DMODEL / 32, DMODEL / 32), dim3(32, 8)>>>(Wq + l * DD, wl,            DMODEL, DMODEL);
        transpose_kernel<<<dim3(DMODEL / 32, DMODEL / 32), dim3(32, 8)>>>(Wk + l * DD, wl + DD,       DMODEL, DMODEL);
        transpose_kernel<<<dim3(DMODEL / 32, DMODEL / 32), dim3(32, 8)>>>(Wv + l * DD, wl + 2 * DD,   DMODEL, DMODEL);
        transpose_kernel<<<dim3(DMODEL / 32, DMODEL / 32), dim3(32, 8)>>>(Wo + l * DD, wl + 3 * DD,   DMODEL, DMODEL);
        transpose_kernel<<<dim3(FFDIM / 32, DMODEL / 32), dim3(32, 8)>>>(Wg + l * DF, wl + 4 * DD,    DMODEL, FFDIM);
        transpose_kernel<<<dim3(FFDIM / 32, DMODEL / 32), dim3(32, 8)>>>(Wu + l * DF, wl + 4 * DD + DF, DMODEL, FFDIM);
        transpose_kernel<<<dim3(DMODEL / 32, FFDIM / 32), dim3(32, 8)>>>(Wd + l * DF, wl + 4 * DD + 2 * DF, FFDIM, DMODEL);
    }

    embed_kernel<<<MTOK, 256>>>(idT, idM, emb, h);

    const dim3 gD(DMODEL / 128, MTOK / 128);
    const dim3 gF(FFDIM / 128, MTOK / 128);

    for (int l = 0; l < LAYERS; l++) {
        float* wl = wt + l * LSTR;
        const float* Wq_t = wl;
        const float* Wk_t = wl + DD;
        const float* Wv_t = wl + 2 * DD;
        const float* Wo_t = wl + 3 * DD;
        const float* Wg_t = wl + 4 * DD;
        const float* Wu_t = wl + 4 * DD + DF;
        const float* Wd_t = wl + 4 * DD + 2 * DF;
        const float* Aq_l = Aq + (size_t)l * DMODEL * RLORA;
        const float* Ak_l = Ak + (size_t)l * DMODEL * RLORA;
        const float* Av_l = Av + (size_t)l * DMODEL * RLORA;
        const float* Ao_l = Ao + (size_t)l * DMODEL * RLORA;
        const float* Ag_l = Ag + (size_t)l * DMODEL * RLORA;
        const float* Au_l = Au + (size_t)l * DMODEL * RLORA;
        const float* Ad_l = Ad + (size_t)l * FFDIM * RLORA;
        const float* Bq_l = Bq + (size_t)l * RLORA * DMODEL;
        const float* Bk_l = Bk + (size_t)l * RLORA * DMODEL;
        const float* Bv_l = Bv + (size_t)l * RLORA * DMODEL;
        const float* Bo_l = Bo + (size_t)l * RLORA * DMODEL;
        const float* Bg_l = Bg + (size_t)l * RLORA * FFDIM;
        const float* Bu_l = Bu + (size_t)l * RLORA * FFDIM;
        const float* Bd_l = Bd + (size_t)l * RLORA * DMODEL;

        rmsnorm_kernel<<<MTOK, 256>>>(h, ln1 + l * DMODEL, x);

        lora_t_kernel<<<MTOK / 16, 256>>>(x, Aq_l, t, DMODEL);
        gemm_tc<<<gD, 256, GSMEM>>>(x, Wq_t, q, MTOK, DMODEL, DMODEL, t, Bq_l, 0);
        lora_t_kernel<<<MTOK / 16, 256>>>(x, Ak_l, t, DMODEL);
        gemm_tc<<<gD, 256, GSMEM>>>(x, Wk_t, k, MTOK, DMODEL, DMODEL, t, Bk_l, 0);
        lora_t_kernel<<<MTOK / 16, 256>>>(x, Av_l, t, DMODEL);
        gemm_tc<<<gD, 256, GSMEM>>>(x, Wv_t, v, MTOK, DMODEL, DMODEL, t, Bv_l, 0);

        rope_kernel<<<(MTOK * NHEAD * 64 + 255) / 256, 256>>>(q, k);

        scores_kernel<<<dim3(SEQ / 16, SEQ / 16, BB * NHEAD), dim3(16, 16)>>>(q, k, mT, mM, sc);
        softmax_kernel<<<BB * NHEAD * SEQ, 256>>>(sc);
        attnv_kernel<<<dim3(SEQ / 4, BB * NHEAD), dim3(128, 4)>>>(sc, v, o);

        lora_t_kernel<<<MTOK / 16, 256>>>(o, Ao_l, t, DMODEL);
        gemm_tc<<<gD, 256, GSMEM>>>(o, Wo_t, h, MTOK, DMODEL, DMODEL, t, Bo_l, 1);

        rmsnorm_kernel<<<MTOK, 256>>>(h, ln2 + l * DMODEL, x);

        lora_t_kernel<<<MTOK / 16, 256>>>(x, Ag_l, t, DMODEL);
        gemm_tc<<<gF, 256, GSMEM>>>(x, Wg_t, gg, MTOK, FFDIM, DMODEL, t, Bg_l, 0);
        lora_t_kernel<<<MTOK / 16, 256>>>(x, Au_l, t, DMODEL);
        gemm_tc<<<gF, 256, GSMEM>>>(x, Wu_t, uu, MTOK, FFDIM, DMODEL, t, Bu_l, 0);

        swiglu_kernel<<<(int)(((size_t)MTOK * FFDIM + 255) / 256), 256>>>(gg, uu);

        lora_t_kernel<<<MTOK / 16, 256>>>(gg, Ad_l, t, FFDIM);
        gemm_tc<<<gD, 256, GSMEM>>>(gg, Wd_t, h, MTOK, DMODEL, FFDIM, t, Bd_l, 1);
    }

    rmsnorm_kernel<<<MTOK, 256>>>(h, lnf, x);
    reps_kernel<<<BB, 256>>>(x, mT, mM, rp);
    loss_kernel<<<1, 256>>>(rp, (float*)d_out);
}

// round 5
// speedup vs baseline: 2.2059x; 1.5218x over previous
#include <cuda_runtime.h>
#include <cuda_bf16.h>
#include <math.h>
#include <stdint.h>

// Problem constants
#define LAYERS 2
#define DMODEL 2048
#define NHEAD  16
#define HDIM   128
#define FFDIM  5632
#define RLORA  16
#define BATCH  4
#define SEQ    512
#define BB     8            // combined batch (text + mis)
#define MTOK   (BB*SEQ)     // 4096 tokens
#define LORA_SCALE 1.4f

// ---------------- scratch (static device globals; allocation-free) ----------------
__device__ float g_h   [MTOK * DMODEL];
__device__ float g_x   [MTOK * DMODEL];
__device__ float g_q   [MTOK * DMODEL];
__device__ float g_k   [MTOK * DMODEL];
__device__ float g_v   [MTOK * DMODEL];
__device__ float g_o   [MTOK * DMODEL];
__device__ float g_sc  [BB * NHEAD * SEQ * SEQ];
__device__ float g_gate[MTOK * FFDIM];
__device__ float g_up  [MTOK * FFDIM];
__device__ float g_t   [MTOK * RLORA];
__device__ float g_reps[BB * DMODEL];
// split bf16 activations (shared across phases; sequential use)
__device__ __nv_bfloat16 g_ah[MTOK * FFDIM];
__device__ __nv_bfloat16 g_al[MTOK * FFDIM];
// split bf16 transposed weights: per layer 4*D*D + 3*D*FF elements
__device__ __nv_bfloat16 g_wh[2 * (4 * DMODEL * DMODEL + 3 * DMODEL * FFDIM)];
__device__ __nv_bfloat16 g_wl[2 * (4 * DMODEL * DMODEL + 3 * DMODEL * FFDIM)];

// =================== helpers ===================
__device__ __forceinline__ uint32_t smem_u32(const void* p) {
    uint32_t a;
    asm("{ .reg .u64 t; cvta.to.shared.u64 t, %1; cvt.u32.u64 %0, t; }" : "=r"(a) : "l"(p));
    return a;
}
__device__ __forceinline__ void cp_async16(uint32_t saddr, const void* gptr) {
    asm volatile("cp.async.cg.shared.global [%0], [%1], 16;" :: "r"(saddr), "l"(gptr));
}
__device__ __forceinline__ void cp_commit() {
    asm volatile("cp.async.commit_group;");
}
template <int NWAIT>
__device__ __forceinline__ void cp_wait() {
    asm volatile("cp.async.wait_group %0;" :: "n"(NWAIT));
}
__device__ __forceinline__ void mma16(float* d, const uint32_t* a, uint32_t b0, uint32_t b1) {
    asm volatile(
        "mma.sync.aligned.m16n8k16.row.col.f32.bf16.bf16.f32 "
        "{%0,%1,%2,%3}, {%4,%5,%6,%7}, {%8,%9}, {%0,%1,%2,%3};"
        : "+f"(d[0]), "+f"(d[1]), "+f"(d[2]), "+f"(d[3])
        : "r"(a[0]), "r"(a[1]), "r"(a[2]), "r"(a[3]), "r"(b0), "r"(b1));
}
__device__ __forceinline__ void split_bf16(float v, __nv_bfloat16& h, __nv_bfloat16& l) {
    h = __float2bfloat16(v);
    l = __float2bfloat16(v - __bfloat162float(h));
}

// smem layout (bytes): 2 stages of [Ah | Al | Bh | Bl], each array 128 rows x 40 bf16 (stride 80B)
#define SMSB   80
#define ARRB   10240
#define STGB   40960
#define LA_OFF 81920
#define LB_OFF 88064
#define GSMEM  94208

// =================== bf16x3 tensor-core GEMM, cp.async pipeline, LoRA fused tail ===================
// C[M,N] = A[M,K] @ W[K,N] + 1.4 * T[M,16] @ lB[16,N]   (+= C if accum)
// Agh/Agl: split A [M,K] bf16.  Wgh/Wgl: split W^T [N,K] bf16.
__global__ __launch_bounds__(256)
void gemm_tc(const __nv_bfloat16* __restrict__ Agh, const __nv_bfloat16* __restrict__ Agl,
             const __nv_bfloat16* __restrict__ Wgh, const __nv_bfloat16* __restrict__ Wgl,
             float* __restrict__ C, int M, int N, int K,
             const float* __restrict__ lT, const float* __restrict__ lB, int accum)
{
    extern __shared__ char smc[];
    const int tid  = threadIdx.x;
    const int wid  = tid >> 5;
    const int lane = tid & 31;
    const int g    = lane >> 2;
    const int t4   = lane & 3;
    const int wm   = wid >> 1;       // 0..3
    const int wn   = wid & 1;        // 0..1
    const int bm   = blockIdx.y * 128;
    const int bn   = blockIdx.x * 128;
    const uint32_t sb = smem_u32(smc);

    // LoRA tiles (hi-only bf16): la[128][24] = 1.4*T rows; lb[128][24] = lB^T cols
    __nv_bfloat16* la = (__nv_bfloat16*)(smc + LA_OFF);
    __nv_bfloat16* lb = (__nv_bfloat16*)(smc + LB_OFF);
    for (int i = tid; i < 2048; i += 256) {
        int row = i >> 4, r = i & 15;
        la[row * 24 + r] = __float2bfloat16(LORA_SCALE * lT[(size_t)(bm + row) * RLORA + r]);
        lb[row * 24 + r] = __float2bfloat16(lB[(size_t)r * N + bn + row]);
    }

    float d[2][8][4];
    #pragma unroll
    for (int mt = 0; mt < 2; mt++)
        #pragma unroll
        for (int nt = 0; nt < 8; nt++)
            #pragma unroll
            for (int j = 0; j < 4; j++) d[mt][nt][j] = 0.f;

    auto issue = [&](int kt) {
        const int k0  = kt << 5;
        const int buf = kt & 1;
        #pragma unroll
        for (int j = 0; j < 8; j++) {
            int e   = tid + j * 256;          // 0..2047
            int arr = e >> 9;                 // 0:Ah 1:Al 2:Bh 3:Bl
            int i   = e & 511;
            int row = i >> 2;
            int cg  = (i & 3) << 3;           // bf16 col offset 0,8,16,24
            const __nv_bfloat16* gp;
            if (arr == 0)      gp = Agh + (size_t)(bm + row) * K + k0 + cg;
            else if (arr == 1) gp = Agl + (size_t)(bm + row) * K + k0 + cg;
            else if (arr == 2) gp = Wgh + (size_t)(bn + row) * K + k0 + cg;
            else               gp = Wgl + (size_t)(bn + row) * K + k0 + cg;
            cp_async16(sb + buf * STGB + arr * ARRB + row * SMSB + cg * 2, gp);
        }
        cp_commit();
    };

    auto compute = [&](int buf) {
        const char* st = smc + buf * STGB;
        #pragma unroll
        for (int ks = 0; ks < 32; ks += 16) {
            uint32_t ah[2][4], al[2][4];
            #pragma unroll
            for (int mt = 0; mt < 2; mt++) {
                const char* pa = st + (wm * 32 + mt * 16 + g) * SMSB + (ks + 2 * t4) * 2;
                ah[mt][0] = *(const uint32_t*)(pa);
                ah[mt][1] = *(const uint32_t*)(pa + 8 * SMSB);
                ah[mt][2] = *(const uint32_t*)(pa + 16);
                ah[mt][3] = *(const uint32_t*)(pa + 8 * SMSB + 16);
                al[mt][0] = *(const uint32_t*)(pa + ARRB);
                al[mt][1] = *(const uint32_t*)(pa + ARRB + 8 * SMSB);
                al[mt][2] = *(const uint32_t*)(pa + ARRB + 16);
                al[mt][3] = *(const uint32_t*)(pa + ARRB + 8 * SMSB + 16);
            }
            #pragma unroll
            for (int nt = 0; nt < 8; nt++) {
                const char* pb = st + 2 * ARRB + (wn * 64 + nt * 8 + g) * SMSB + (ks + 2 * t4) * 2;
                uint32_t b0h = *(const uint32_t*)(pb);
                uint32_t b1h = *(const uint32_t*)(pb + 16);
                uint32_t b0l = *(const uint32_t*)(pb + ARRB);
                uint32_t b1l = *(const uint32_t*)(pb + ARRB + 16);
                #pragma unroll
                for (int mt = 0; mt < 2; mt++) {
                    mma16(d[mt][nt], ah[mt], b0h, b1h);
                    mma16(d[mt][nt], ah[mt], b0l, b1l);
                    mma16(d[mt][nt], al[mt], b0h, b1h);
                }
            }
        }
    };

    const int nk = K >> 5;   // BK = 32
    issue(0);
    for (int kt = 0; kt < nk; kt++) {
        if (kt + 1 < nk) { issue(kt + 1); cp_wait<1>(); }
        else             cp_wait<0>();
        __syncthreads();
        compute(kt & 1);
        __syncthreads();
    }

    // ---- LoRA tail: hi-only K=16 chunk from la/lb (stride 48B) ----
    {
        uint32_t a[2][4];
        #pragma unroll
        for (int mt = 0; mt < 2; mt++) {
            const char* pa = (const char*)la + (wm * 32 + mt * 16 + g) * 48 + t4 * 4;
            a[mt][0] = *(const uint32_t*)(pa);
            a[mt][1] = *(const uint32_t*)(pa + 8 * 48);
            a[mt][2] = *(const uint32_t*)(pa + 16);
            a[mt][3] = *(const uint32_t*)(pa + 8 * 48 + 16);
        }
        #pragma unroll
        for (int nt = 0; nt < 8; nt++) {
            const char* pb = (const char*)lb + (wn * 64 + nt * 8 + g) * 48 + t4 * 4;
            uint32_t b0 = *(const uint32_t*)(pb);
            uint32_t b1 = *(const uint32_t*)(pb + 16);
            #pragma unroll
            for (int mt = 0; mt < 2; mt++) mma16(d[mt][nt], a[mt], b0, b1);
        }
    }

    // ---- epilogue: fragments -> C (optional residual accumulate) ----
    #pragma unroll
    for (int mt = 0; mt < 2; mt++) {
        const int r0 = bm + wm * 32 + mt * 16 + g;
        #pragma unroll
        for (int nt = 0; nt < 8; nt++) {
            const int c0 = bn + wn * 64 + nt * 8 + 2 * t4;
            float2 v0 = make_float2(d[mt][nt][0], d[mt][nt][1]);
            float2 v1 = make_float2(d[mt][nt][2], d[mt][nt][3]);
            float* p0 = C + (size_t)r0 * N + c0;
            float* p1 = C + (size_t)(r0 + 8) * N + c0;
            if (accum) {
                float2 o0 = *(const float2*)p0;
                float2 o1 = *(const float2*)p1;
                v0.x += o0.x; v0.y += o0.y;
                v1.x += o1.x; v1.y += o1.y;
            }
            *(float2*)p0 = v0;
            *(float2*)p1 = v1;
        }
    }
}

// ---------------- weight transpose + bf16 split: Wh/Wl[n*K+k] = split(W[k*N+n]) ----------------
__global__ void transpose_split(const float* __restrict__ W,
                                __nv_bfloat16* __restrict__ Wh, __nv_bfloat16* __restrict__ Wl,
                                int Kd, int Nd)
{
    __shared__ float tile[32][33];
    int n0 = blockIdx.x * 32, k0 = blockIdx.y * 32;
    int x = threadIdx.x, y = threadIdx.y;
    #pragma unroll
    for (int dy = 0; dy < 32; dy += 8)
        tile[y + dy][x] = W[(size_t)(k0 + y + dy) * Nd + n0 + x];
    __syncthreads();
    #pragma unroll
    for (int dy = 0; dy < 32; dy += 8) {
        float v = tile[x][y + dy];
        size_t o = (size_t)(n0 + y + dy) * Kd + k0 + x;
        __nv_bfloat16 h, l;
        split_bf16(v, h, l);
        Wh[o] = h; Wl[o] = l;
    }
}

// ---------------- embedding gather ----------------
__global__ void embed_kernel(const int* __restrict__ idT, const int* __restrict__ idM,
                             const float* __restrict__ E, float* __restrict__ H)
{
    int t  = blockIdx.x;
    int bb = t >> 9;
    int s  = t & 511;
    int id = (bb < 4) ? idT[bb * SEQ + s] : idM[(bb - 4) * SEQ + s];
    const float4* src = reinterpret_cast<const float4*>(E + (size_t)id * DMODEL);
    float4*       dst = reinterpret_cast<float4*>(H + (size_t)t * DMODEL);
    for (int j = threadIdx.x; j < DMODEL / 4; j += blockDim.x) dst[j] = src[j];
}

// ---------------- rmsnorm (also emits split bf16) ----------------
__global__ void rmsnorm_kernel(const float* __restrict__ H, const float* __restrict__ W,
                               float* __restrict__ X,
                               __nv_bfloat16* __restrict__ Xh, __nv_bfloat16* __restrict__ Xl)
{
    __shared__ float red[256];
    int row = blockIdx.x;
    const float* h = H + (size_t)row * DMODEL;
    float s = 0.f;
    for (int j = threadIdx.x; j < DMODEL; j += 256) { float v = h[j]; s += v * v; }
    red[threadIdx.x] = s; __syncthreads();
    for (int o = 128; o > 0; o >>= 1) {
        if (threadIdx.x < o) red[threadIdx.x] += red[threadIdx.x + o];
        __syncthreads();
    }
    float scale = rsqrtf(red[0] / (float)DMODEL + 1e-6f);
    size_t base = (size_t)row * DMODEL;
    for (int j = threadIdx.x; j < DMODEL; j += 256) {
        float v = h[j] * scale * W[j];
        X[base + j] = v;
        __nv_bfloat16 hh, ll;
        split_bf16(v, hh, ll);
        Xh[base + j] = hh; Xl[base + j] = ll;
    }
}

// ---------------- lora down-projection: T = X @ A ----------------
__global__ void lora_t_kernel(const float* __restrict__ X, const float* __restrict__ A,
                              float* __restrict__ T, int K)
{
    int row = blockIdx.x * 16 + (threadIdx.x >> 4);
    int r   = threadIdx.x & 15;
    const float* x = X + (size_t)row * K;
    float acc = 0.f;
    #pragma unroll 4
    for (int k = 0; k < K; k++) acc += x[k] * A[k * RLORA + r];
    T[row * RLORA + r] = acc;
}

// ---------------- RoPE on q and k ----------------
__global__ void rope_kernel(float* __restrict__ Q, float* __restrict__ Kt)
{
    int i = blockIdx.x * blockDim.x + threadIdx.x;
    if (i >= MTOK * NHEAD * 64) return;
    int d = i & 63;
    int h = (i >> 6) & 15;
    int t = i >> 10;
    int s = t & 511;
    float freq = expf(-(float)d * (logf(10000.f) / 64.f));
    float ang = (float)s * freq;
    float sn, cs;
    sincosf(ang, &sn, &cs);
    size_t baseo = (size_t)t * DMODEL + h * HDIM + d;
    float x1 = Q[baseo], x2 = Q[baseo + 64];
    Q[baseo]      = x1 * cs - x2 * sn;
    Q[baseo + 64] = x1 * sn + x2 * cs;
    x1 = Kt[baseo]; x2 = Kt[baseo + 64];
    Kt[baseo]      = x1 * cs - x2 * sn;
    Kt[baseo + 64] = x1 * sn + x2 * cs;
}

// ---------------- attention scores + mask bias ----------------
__global__ void scores_kernel(const float* __restrict__ Q, const float* __restrict__ Kt,
                              const int* __restrict__ mT, const int* __restrict__ mM,
                              float* __restrict__ S_)
{
    __shared__ float qs[16][132];
    __shared__ float ks[16][132];
    int z  = blockIdx.z;
    int bb = z >> 4;
    int h  = z & 15;
    int q0 = blockIdx.y * 16;
    int k0 = blockIdx.x * 16;
    int tid = threadIdx.y * 16 + threadIdx.x;
    for (int f = tid; f < 512; f += 256) {
        int r = f >> 5;
        int c = (f & 31) << 2;
        float4 vq = *reinterpret_cast<const float4*>(
            &Q[(size_t)(bb * SEQ + q0 + r) * DMODEL + h * HDIM + c]);
        qs[r][c] = vq.x; qs[r][c + 1] = vq.y; qs[r][c + 2] = vq.z; qs[r][c + 3] = vq.w;
        float4 vk = *reinterpret_cast<const float4*>(
            &Kt[(size_t)(bb * SEQ + k0 + r) * DMODEL + h * HDIM + c]);
        ks[r][c] = vk.x; ks[r][c + 1] = vk.y; ks[r][c + 2] = vk.z; ks[r][c + 3] = vk.w;
    }
    __syncthreads();
    int qi = threadIdx.y, kj = threadIdx.x;
    float acc = 0.f;
    #pragma unroll 8
    for (int d = 0; d < HDIM; d++) acc += qs[qi][d] * ks[kj][d];
    int sq = q0 + qi, sk = k0 + kj;
    const int* mask = (bb < 4) ? (mT + bb * SEQ) : (mM + (bb - 4) * SEQ);
    bool ok = (sk <= sq) && (mask[sk] > 0);
    float val = acc * 0.08838834764831845f + (ok ? 0.f : -1e9f);
    S_[((size_t)z * SEQ + sq) * SEQ + sk] = val;
}

// ---------------- row softmax ----------------
__global__ void softmax_kernel(float* __restrict__ S_)
{
    __shared__ float red[256];
    float* p = S_ + (size_t)blockIdx.x * SEQ;
    int t = threadIdx.x;
    float v0 = p[t], v1 = p[t + 256];
    float m = fmaxf(v0, v1);
    red[t] = m; __syncthreads();
    for (int o = 128; o > 0; o >>= 1) {
        if (t < o) red[t] = fmaxf(red[t], red[t + o]);
        __syncthreads();
    }
    m = red[0]; __syncthreads();
    float e0 = expf(v0 - m), e1 = expf(v1 - m);
    red[t] = e0 + e1; __syncthreads();
    for (int o = 128; o > 0; o >>= 1) {
        if (t < o) red[t] += red[t + o];
        __syncthreads();
    }
    float inv = 1.f / red[0];
    p[t] = e0 * inv; p[t + 256] = e1 * inv;
}

// ---------------- O = attn @ V (also emits split bf16) ----------------
__global__ void attnv_kernel(const float* __restrict__ P, const float* __restrict__ V,
                             float* __restrict__ O,
                             __nv_bfloat16* __restrict__ Oh, __nv_bfloat16* __restrict__ Ol)
{
    __shared__ float vs[16][128];
    __shared__ float as[4][16];
    int z  = blockIdx.y;
    int bb = z >> 4;
    int h  = z & 15;
    int q0 = blockIdx.x * 4;
    int tx = threadIdx.x;
    int ty = threadIdx.y;
    int tid = ty * 128 + tx;
    const float* Prow = P + ((size_t)z * SEQ + q0) * SEQ;
    float acc = 0.f;
    for (int kt = 0; kt < SEQ; kt += 16) {
        for (int f = tid; f < 2048; f += 512) {
            int r = f >> 7, c = f & 127;
            vs[r][c] = V[(size_t)(bb * SEQ + kt + r) * DMODEL + h * HDIM + c];
        }
        if (tid < 64) {
            int r = tid >> 4, c = tid & 15;
            as[r][c] = Prow[r * SEQ + kt + c];
        }
        __syncthreads();
        #pragma unroll
        for (int kk = 0; kk < 16; kk++) acc += as[ty][kk] * vs[kk][tx];
        __syncthreads();
    }
    size_t oidx = (size_t)(bb * SEQ + q0 + ty) * DMODEL + h * HDIM + tx;
    O[oidx] = acc;
    __nv_bfloat16 hh, ll;
    split_bf16(acc, hh, ll);
    Oh[oidx] = hh; Ol[oidx] = ll;
}

// ---------------- swiglu (also emits split bf16) ----------------
__global__ void swiglu_kernel(float* __restrict__ G, const float* __restrict__ U,
                              __nv_bfloat16* __restrict__ Gh, __nv_bfloat16* __restrict__ Gl)
{
    size_t i = (size_t)blockIdx.x * blockDim.x + threadIdx.x;
    if (i >= (size_t)MTOK * FFDIM) return;
    float g = G[i];
    float sig = 1.f / (1.f + expf(-g));
    float v = g * sig * U[i];
    G[i] = v;
    __nv_bfloat16 hh, ll;
    split_bf16(v, hh, ll);
    Gh[i] = hh; Gl[i] = ll;
}

// ---------------- reps extraction + L2 normalize ----------------
__global__ void reps_kernel(const float* __restrict__ X, const int* __restrict__ mT,
                            const int* __restrict__ mM, float* __restrict__ R_)
{
    __shared__ int ired[256];
    __shared__ float fred[256];
    __shared__ int sidx;
    int bb = blockIdx.x;
    const int* mask = (bb < 4) ? mT : mM;
    int b = bb & 3;
    int t = threadIdx.x;
    int s = 0;
    for (int j = t; j < SEQ; j += 256) s += mask[b * SEQ + j];
    ired[t] = s; __syncthreads();
    for (int o = 128; o > 0; o >>= 1) {
        if (t < o) ired[t] += ired[t + o];
        __syncthreads();
    }
    if (t == 0) {
        int last = mask[0 * SEQ + 511] + mask[1 * SEQ + 511] +
                   mask[2 * SEQ + 511] + mask[3 * SEQ + 511];
        sidx = (last == BATCH) ? (SEQ - 1) : (ired[0] - 1);
    }
    __syncthreads();
    const float* row = X + (size_t)(bb * SEQ + sidx) * DMODEL;
    float ss = 0.f;
    for (int j = t; j < DMODEL; j += 256) { float v = row[j]; ss += v * v; }
    fred[t] = ss; __syncthreads();
    for (int o = 128; o > 0; o >>= 1) {
        if (t < o) fred[t] += fred[t + o];
        __syncthreads();
    }
    float inv = 1.f / sqrtf(fred[0]);
    for (int j = t; j < DMODEL; j += 256) R_[bb * DMODEL + j] = row[j] * inv;
}

// ---------------- contrastive loss ----------------
__global__ void loss_kernel(const float* __restrict__ R_, float* __restrict__ out)
{
    __shared__ float sims[16];
    int tid = threadIdx.x;
    int warp = tid >> 5, lane = tid & 31;
    for (int p = warp; p < 16; p += 8) {
        int i = p >> 2, j = p & 3;
        const float* a = R_ + i * DMODEL;
        const float* bR = R_ + (4 + j) * DMODEL;
        float d = 0.f;
        for (int k2 = lane; k2 < DMODEL; k2 += 32) d += a[k2] * bR[k2];
        #pragma unroll
        for (int o = 16; o > 0; o >>= 1) d += __shfl_xor_sync(0xffffffff, d, o);
        if (lane == 0) sims[p] = d * 20.f;
    }
    __syncthreads();
    if (tid == 0) {
        float loss = 0.f;
        for (int i = 0; i < 4; i++) {
            float m = -1e30f;
            for (int j = 0; j < 4; j++) m = fmaxf(m, sims[i * 4 + j]);
            float sum = 0.f;
            for (int j = 0; j < 4; j++) sum += expf(sims[i * 4 + j] - m);
            loss += (logf(sum) + m) - sims[i * 4 + i];
        }
        out[0] = loss * 0.25f;
    }
}

// ---------------- host driver ----------------
static void* symaddr_raw(const void* sym)
{
    void* p = nullptr;
    cudaGetSymbolAddress(&p, sym);
    return p;
}

extern "C" void kernel_launch(void* const* d_in, const int* in_sizes, int n_in,
                              void* d_out, int out_size)
{
    const int*   idT = (const int*)d_in[0];
    const int*   mT  = (const int*)d_in[1];
    const int*   idM = (const int*)d_in[2];
    const int*   mM  = (const int*)d_in[3];
    const float* emb = (const float*)d_in[4];
    const float* ln1 = (const float*)d_in[5];
    const float* ln2 = (const float*)d_in[6];
    const float* lnf = (const float*)d_in[7];
    const float* Wq = (const float*)d_in[8],  *Aq = (const float*)d_in[9],  *Bq = (const float*)d_in[10];
    const float* Wk = (const float*)d_in[11], *Ak = (const float*)d_in[12], *Bk = (const float*)d_in[13];
    const float* Wv = (const float*)d_in[14], *Av = (const float*)d_in[15], *Bv = (const float*)d_in[16];
    const float* Wo = (const float*)d_in[17], *Ao = (const float*)d_in[18], *Bo = (const float*)d_in[19];
    const float* Wg = (const float*)d_in[20], *Ag = (const float*)d_in[21], *Bg = (const float*)d_in[22];
    const float* Wu = (const float*)d_in[23], *Au = (const float*)d_in[24], *Bu = (const float*)d_in[25];
    const float* Wd = (const float*)d_in[26], *Ad = (const float*)d_in[27], *Bd = (const float*)d_in[28];

    float* h  = (float*)symaddr_raw(g_h);
    float* x  = (float*)symaddr_raw(g_x);
    float* q  = (float*)symaddr_raw(g_q);
    float* k  = (float*)symaddr_raw(g_k);
    float* v  = (float*)symaddr_raw(g_v);
    float* o  = (float*)symaddr_raw(g_o);
    float* sc = (float*)symaddr_raw(g_sc);
    float* gg = (float*)symaddr_raw(g_gate);
    float* uu = (float*)symaddr_raw(g_up);
    float* t  = (float*)symaddr_raw(g_t);
    float* rp = (float*)symaddr_raw(g_reps);
    __nv_bfloat16* ah = (__nv_bfloat16*)symaddr_raw(g_ah);
    __nv_bfloat16* al = (__nv_bfloat16*)symaddr_raw(g_al);
    __nv_bfloat16* wh = (__nv_bfloat16*)symaddr_raw(g_wh);
    __nv_bfloat16* wl = (__nv_bfloat16*)symaddr_raw(g_wl);

    cudaFuncSetAttribute(gemm_tc, cudaFuncAttributeMaxDynamicSharedMemorySize, GSMEM);

    const size_t DD = (size_t)DMODEL * DMODEL;
    const size_t DF = (size_t)DMODEL * FFDIM;
    const size_t LSTR = 4 * DD + 3 * DF;

    // transpose + split all weights once
    for (int l = 0; l < LAYERS; l++) {
        size_t off = (size_t)l * LSTR;
        transpose_split<<<dim3(DMODEL / 32, DMODEL / 32), dim3(32, 8)>>>(Wq + l * DD, wh + off,               wl + off,               DMODEL, DMODEL);
        transpose_split<<<dim3(DMODEL / 32, DMODEL / 32), dim3(32, 8)>>>(Wk + l * DD, wh + off + DD,          wl + off + DD,          DMODEL, DMODEL);
        transpose_split<<<dim3(DMODEL / 32, DMODEL / 32), dim3(32, 8)>>>(Wv + l * DD, wh + off + 2 * DD,      wl + off + 2 * DD,      DMODEL, DMODEL);
        transpose_split<<<dim3(DMODEL / 32, DMODEL / 32), dim3(32, 8)>>>(Wo + l * DD, wh + off + 3 * DD,      wl + off + 3 * DD,      DMODEL, DMODEL);
        transpose_split<<<dim3(FFDIM / 32, DMODEL / 32), dim3(32, 8)>>>(Wg + l * DF, wh + off + 4 * DD,       wl + off + 4 * DD,      DMODEL, FFDIM);
        transpose_split<<<dim3(FFDIM / 32, DMODEL / 32), dim3(32, 8)>>>(Wu + l * DF, wh + off + 4 * DD + DF,  wl + off + 4 * DD + DF, DMODEL, FFDIM);
        transpose_split<<<dim3(DMODEL / 32, FFDIM / 32), dim3(32, 8)>>>(Wd + l * DF, wh + off + 4 * DD + 2 * DF, wl + off + 4 * DD + 2 * DF, FFDIM, DMODEL);
    }

    embed_kernel<<<MTOK, 256>>>(idT, idM, emb, h);

    const dim3 gD(DMODEL / 128, MTOK / 128);
    const dim3 gF(FFDIM / 128, MTOK / 128);

    for (int l = 0; l < LAYERS; l++) {
        size_t off = (size_t)l * LSTR;
        const __nv_bfloat16 *Wq_h = wh + off,               *Wq_l = wl + off;
        const __nv_bfloat16 *Wk_h = wh + off + DD,          *Wk_l = wl + off + DD;
        const __nv_bfloat16 *Wv_h = wh + off + 2 * DD,      *Wv_l = wl + off + 2 * DD;
        const __nv_bfloat16 *Wo_h = wh + off + 3 * DD,      *Wo_l = wl + off + 3 * DD;
        const __nv_bfloat16 *Wg_h = wh + off + 4 * DD,      *Wg_l = wl + off + 4 * DD;
        const __nv_bfloat16 *Wu_h = wh + off + 4 * DD + DF, *Wu_l = wl + off + 4 * DD + DF;
        const __nv_bfloat16 *Wd_h = wh + off + 4 * DD + 2 * DF, *Wd_l = wl + off + 4 * DD + 2 * DF;
        const float* Aq_l = Aq + (size_t)l * DMODEL * RLORA;
        const float* Ak_l = Ak + (size_t)l * DMODEL * RLORA;
        const float* Av_l = Av + (size_t)l * DMODEL * RLORA;
        const float* Ao_l = Ao + (size_t)l * DMODEL * RLORA;
        const float* Ag_l = Ag + (size_t)l * DMODEL * RLORA;
        const float* Au_l = Au + (size_t)l * DMODEL * RLORA;
        const float* Ad_l = Ad + (size_t)l * FFDIM * RLORA;
        const float* Bq_l = Bq + (size_t)l * RLORA * DMODEL;
        const float* Bk_l = Bk + (size_t)l * RLORA * DMODEL;
        const float* Bv_l = Bv + (size_t)l * RLORA * DMODEL;
        const float* Bo_l = Bo + (size_t)l * RLORA * DMODEL;
        const float* Bg_l = Bg + (size_t)l * RLORA * FFDIM;
        const float* Bu_l = Bu + (size_t)l * RLORA * FFDIM;
        const float* Bd_l = Bd + (size_t)l * RLORA * DMODEL;

        rmsnorm_kernel<<<MTOK, 256>>>(h, ln1 + l * DMODEL, x, ah, al);

        lora_t_kernel<<<MTOK / 16, 256>>>(x, Aq_l, t, DMODEL);
        gemm_tc<<<gD, 256, GSMEM>>>(ah, al, Wq_h, Wq_l, q, MTOK, DMODEL, DMODEL, t, Bq_l, 0);
        lora_t_kernel<<<MTOK / 16, 256>>>(x, Ak_l, t, DMODEL);
        gemm_tc<<<gD, 256, GSMEM>>>(ah, al, Wk_h, Wk_l, k, MTOK, DMODEL, DMODEL, t, Bk_l, 0);
        lora_t_kernel<<<MTOK / 16, 256>>>(x, Av_l, t, DMODEL);
        gemm_tc<<<gD, 256, GSMEM>>>(ah, al, Wv_h, Wv_l, v, MTOK, DMODEL, DMODEL, t, Bv_l, 0);

        rope_kernel<<<(MTOK * NHEAD * 64 + 255) / 256, 256>>>(q, k);

        scores_kernel<<<dim3(SEQ / 16, SEQ / 16, BB * NHEAD), dim3(16, 16)>>>(q, k, mT, mM, sc);
        softmax_kernel<<<BB * NHEAD * SEQ, 256>>>(sc);
        attnv_kernel<<<dim3(SEQ / 4, BB * NHEAD), dim3(128, 4)>>>(sc, v, o, ah, al);

        lora_t_kernel<<<MTOK / 16, 256>>>(o, Ao_l, t, DMODEL);
        gemm_tc<<<gD, 256, GSMEM>>>(ah, al, Wo_h, Wo_l, h, MTOK, DMODEL, DMODEL, t, Bo_l, 1);

        rmsnorm_kernel<<<MTOK, 256>>>(h, ln2 + l * DMODEL, x, ah, al);

        lora_t_kernel<<<MTOK / 16, 256>>>(x, Ag_l, t, DMODEL);
        gemm_tc<<<gF, 256, GSMEM>>>(ah, al, Wg_h, Wg_l, gg, MTOK, FFDIM, DMODEL, t, Bg_l, 0);
        lora_t_kernel<<<MTOK / 16, 256>>>(x, Au_l, t, DMODEL);
        gemm_tc<<<gF, 256, GSMEM>>>(ah, al, Wu_h, Wu_l, uu, MTOK, FFDIM, DMODEL, t, Bu_l, 0);

        swiglu_kernel<<<(int)(((size_t)MTOK * FFDIM + 255) / 256), 256>>>(gg, uu, ah, al);

        lora_t_kernel<<<MTOK / 16, 256>>>(gg, Ad_l, t, FFDIM);
        gemm_tc<<<gD, 256, GSMEM>>>(ah, al, Wd_h, Wd_l, h, MTOK, DMODEL, FFDIM, t, Bd_l, 1);
    }

    rmsnorm_kernel<<<MTOK, 256>>>(h, lnf, x, ah, al);
    reps_kernel<<<BB, 256>>>(x, mT, mM, rp);
    loss_kernel<<<1, 256>>>(rp, (float*)d_out);
}

// round 6
// speedup vs baseline: 3.1506x; 1.4283x over previous
#include <cuda_runtime.h>
#include <cuda_bf16.h>
#include <math.h>
#include <stdint.h>

// Problem constants
#define LAYERS 2
#define DMODEL 2048
#define NHEAD  16
#define HDIM   128
#define FFDIM  5632
#define RLORA  16
#define BATCH  4
#define SEQ    512
#define BB     8
#define MTOK   (BB*SEQ)
#define LORA_SCALE 1.4f
#define SCALE_QK 0.08838834764831845f

// ---------------- scratch ----------------
__device__ float g_h   [MTOK * DMODEL];
__device__ float g_x   [MTOK * DMODEL];
__device__ float g_q   [MTOK * DMODEL];
__device__ float g_k   [MTOK * DMODEL];
__device__ float g_v   [MTOK * DMODEL];
__device__ float g_o   [MTOK * DMODEL];
__device__ float g_sc  [BB * NHEAD * SEQ * SEQ];
__device__ float g_gate[MTOK * FFDIM];
__device__ float g_up  [MTOK * FFDIM];
__device__ float g_t   [3 * MTOK * RLORA];
__device__ float g_reps[BB * DMODEL];
__device__ __nv_bfloat16 g_ah[MTOK * FFDIM];
__device__ __nv_bfloat16 g_al[MTOK * FFDIM];
__device__ __nv_bfloat16 g_wh[2 * (4 * DMODEL * DMODEL + 3 * DMODEL * FFDIM)];
__device__ __nv_bfloat16 g_wl[2 * (4 * DMODEL * DMODEL + 3 * DMODEL * FFDIM)];
// attention split buffers
__device__ __nv_bfloat16 g_qh[MTOK * DMODEL];
__device__ __nv_bfloat16 g_ql[MTOK * DMODEL];
__device__ __nv_bfloat16 g_kh[MTOK * DMODEL];
__device__ __nv_bfloat16 g_kl[MTOK * DMODEL];
__device__ __nv_bfloat16 g_ph[BB * NHEAD * SEQ * SEQ];
__device__ __nv_bfloat16 g_pl[BB * NHEAD * SEQ * SEQ];
__device__ __nv_bfloat16 g_vth[MTOK * DMODEL];
__device__ __nv_bfloat16 g_vtl[MTOK * DMODEL];

// =================== helpers ===================
__device__ __forceinline__ uint32_t smem_u32(const void* p) {
    uint32_t a;
    asm("{ .reg .u64 t; cvta.to.shared.u64 t, %1; cvt.u32.u64 %0, t; }" : "=r"(a) : "l"(p));
    return a;
}
__device__ __forceinline__ void cp_async16(uint32_t saddr, const void* gptr) {
    asm volatile("cp.async.cg.shared.global [%0], [%1], 16;" :: "r"(saddr), "l"(gptr));
}
__device__ __forceinline__ void cp_commit() { asm volatile("cp.async.commit_group;"); }
template <int NWAIT>
__device__ __forceinline__ void cp_wait() {
    asm volatile("cp.async.wait_group %0;" :: "n"(NWAIT));
}
__device__ __forceinline__ void mma16(float* d, const uint32_t* a, uint32_t b0, uint32_t b1) {
    asm volatile(
        "mma.sync.aligned.m16n8k16.row.col.f32.bf16.bf16.f32 "
        "{%0,%1,%2,%3}, {%4,%5,%6,%7}, {%8,%9}, {%0,%1,%2,%3};"
        : "+f"(d[0]), "+f"(d[1]), "+f"(d[2]), "+f"(d[3])
        : "r"(a[0]), "r"(a[1]), "r"(a[2]), "r"(a[3]), "r"(b0), "r"(b1));
}
__device__ __forceinline__ void ldm_x4(uint32_t* r, uint32_t addr) {
    asm volatile("ldmatrix.sync.aligned.m8n8.x4.shared.b16 {%0,%1,%2,%3}, [%4];"
                 : "=r"(r[0]), "=r"(r[1]), "=r"(r[2]), "=r"(r[3]) : "r"(addr));
}
__device__ __forceinline__ void split_bf16(float v, __nv_bfloat16& h, __nv_bfloat16& l) {
    h = __float2bfloat16(v);
    l = __float2bfloat16(v - __bfloat162float(h));
}

// smem stage layout: 2 stages of [Ah|Al|Bh|Bl], each 128 rows x 40 bf16 (80B stride)
#define SMSB   80
#define ARRB   10240
#define STGB   40960
#define LA_OFF 81920
#define LB_OFF 88064
#define GSMEM  94208
#define SCSM   82432   // scores: stages + mask[128]
#define AVSM   81920   // attnv: stages only

// ---- shared fragment compute: bf16x3 over one 128x32 stage ----
#define COMPUTE_STAGE(stbase)                                                     \
    _Pragma("unroll")                                                             \
    for (int ks = 0; ks < 32; ks += 16) {                                         \
        uint32_t ahf[2][4], alf[2][4];                                            \
        {                                                                         \
            int grp = lane >> 3, r8 = lane & 7;                                   \
            int mm = (grp & 1) * 8 + r8;                                          \
            int koff = (grp >> 1) * 8;                                            \
            _Pragma("unroll")                                                     \
            for (int mt = 0; mt < 2; mt++) {                                      \
                uint32_t ad = (stbase) + (wm * 32 + mt * 16 + mm) * SMSB + (ks + koff) * 2; \
                ldm_x4(ahf[mt], ad);                                              \
                ldm_x4(alf[mt], ad + ARRB);                                       \
            }                                                                     \
        }                                                                         \
        _Pragma("unroll")                                                         \
        for (int np = 0; np < 4; np++) {                                          \
            int grp = lane >> 3, r8 = lane & 7;                                   \
            int nn = (grp >> 1) * 8 + r8;                                         \
            int koff = (grp & 1) * 8;                                             \
            uint32_t bd = (stbase) + 2 * ARRB + (wn * 64 + np * 16 + nn) * SMSB + (ks + koff) * 2; \
            uint32_t bh[4], bl[4];                                                \
            ldm_x4(bh, bd);                                                       \
            ldm_x4(bl, bd + ARRB);                                                \
            _Pragma("unroll")                                                     \
            for (int mt = 0; mt < 2; mt++) {                                      \
                mma16(d[mt][np * 2],     ahf[mt], bh[0], bh[1]);                  \
                mma16(d[mt][np * 2],     ahf[mt], bl[0], bl[1]);                  \
                mma16(d[mt][np * 2],     alf[mt], bh[0], bh[1]);                  \
                mma16(d[mt][np * 2 + 1], ahf[mt], bh[2], bh[3]);                  \
                mma16(d[mt][np * 2 + 1], ahf[mt], bl[2], bl[3]);                  \
                mma16(d[mt][np * 2 + 1], alf[mt], bh[2], bh[3]);                  \
            }                                                                     \
        }                                                                         \
    }

// issue one 128x32 stage of 4 arrays via cp.async; lda/ldb in elements
#define ISSUE_STAGE(kt, aH, aL, bH, bL, LDA, LDB)                                 \
    {                                                                             \
        const int k0_ = (kt) << 5;                                                \
        const int buf_ = (kt) & 1;                                                \
        _Pragma("unroll")                                                         \
        for (int j = 0; j < 8; j++) {                                             \
            int e = tid + j * 256;                                                \
            int arr = e >> 9;                                                     \
            int i = e & 511;                                                      \
            int row = i >> 2;                                                     \
            int cg = (i & 3) << 3;                                                \
            const __nv_bfloat16* gp;                                              \
            if (arr == 0)      gp = (aH) + (size_t)row * (LDA) + k0_ + cg;        \
            else if (arr == 1) gp = (aL) + (size_t)row * (LDA) + k0_ + cg;        \
            else if (arr == 2) gp = (bH) + (size_t)row * (LDB) + k0_ + cg;        \
            else               gp = (bL) + (size_t)row * (LDB) + k0_ + cg;        \
            cp_async16(sb + buf_ * STGB + arr * ARRB + row * SMSB + cg * 2, gp);  \
        }                                                                         \
        cp_commit();                                                              \
    }

// =================== main GEMM with fused LoRA + residual ===================
__global__ __launch_bounds__(256)
void gemm_tc(const __nv_bfloat16* __restrict__ Agh, const __nv_bfloat16* __restrict__ Agl,
             const __nv_bfloat16* __restrict__ Wgh, const __nv_bfloat16* __restrict__ Wgl,
             float* __restrict__ C, int M, int N, int K,
             const float* __restrict__ lT, const float* __restrict__ lB, int accum)
{
    extern __shared__ char smc[];
    const int tid  = threadIdx.x;
    const int wid  = tid >> 5;
    const int lane = tid & 31;
    const int t4   = lane & 3;
    const int g    = lane >> 2;
    const int wm   = wid >> 1;
    const int wn   = wid & 1;
    const int bm   = blockIdx.y * 128;
    const int bn   = blockIdx.x * 128;
    const uint32_t sb = smem_u32(smc);

    __nv_bfloat16* la = (__nv_bfloat16*)(smc + LA_OFF);
    __nv_bfloat16* lb = (__nv_bfloat16*)(smc + LB_OFF);
    for (int i = tid; i < 2048; i += 256) {
        int row = i >> 4, r = i & 15;
        la[row * 24 + r] = __float2bfloat16(LORA_SCALE * lT[(size_t)(bm + row) * RLORA + r]);
        lb[row * 24 + r] = __float2bfloat16(lB[(size_t)r * N + bn + row]);
    }

    float d[2][8][4];
    #pragma unroll
    for (int mt = 0; mt < 2; mt++)
        #pragma unroll
        for (int nt = 0; nt < 8; nt++)
            #pragma unroll
            for (int j = 0; j < 4; j++) d[mt][nt][j] = 0.f;

    const __nv_bfloat16* aH = Agh + (size_t)bm * K;
    const __nv_bfloat16* aL = Agl + (size_t)bm * K;
    const __nv_bfloat16* bH = Wgh + (size_t)bn * K;
    const __nv_bfloat16* bL = Wgl + (size_t)bn * K;

    const int nk = K >> 5;
    ISSUE_STAGE(0, aH, aL, bH, bL, K, K);
    for (int kt = 0; kt < nk; kt++) {
        if (kt + 1 < nk) { ISSUE_STAGE(kt + 1, aH, aL, bH, bL, K, K); cp_wait<1>(); }
        else             cp_wait<0>();
        __syncthreads();
        const uint32_t st = sb + (kt & 1) * STGB;
        COMPUTE_STAGE(st)
        __syncthreads();
    }

    // LoRA tail (hi-only, K=16), scalar fragment loads from la/lb (stride 48B)
    {
        uint32_t a[2][4];
        #pragma unroll
        for (int mt = 0; mt < 2; mt++) {
            const char* pa = (const char*)la + (wm * 32 + mt * 16 + g) * 48 + t4 * 4;
            a[mt][0] = *(const uint32_t*)(pa);
            a[mt][1] = *(const uint32_t*)(pa + 8 * 48);
            a[mt][2] = *(const uint32_t*)(pa + 16);
            a[mt][3] = *(const uint32_t*)(pa + 8 * 48 + 16);
        }
        #pragma unroll
        for (int nt = 0; nt < 8; nt++) {
            const char* pb = (const char*)lb + (wn * 64 + nt * 8 + g) * 48 + t4 * 4;
            uint32_t b0 = *(const uint32_t*)(pb);
            uint32_t b1 = *(const uint32_t*)(pb + 16);
            #pragma unroll
            for (int mt = 0; mt < 2; mt++) mma16(d[mt][nt], a[mt], b0, b1);
        }
    }

    #pragma unroll
    for (int mt = 0; mt < 2; mt++) {
        const int r0 = bm + wm * 32 + mt * 16 + g;
        #pragma unroll
        for (int nt = 0; nt < 8; nt++) {
            const int c0 = bn + wn * 64 + nt * 8 + 2 * t4;
            float2 v0 = make_float2(d[mt][nt][0], d[mt][nt][1]);
            float2 v1 = make_float2(d[mt][nt][2], d[mt][nt][3]);
            float* p0 = C + (size_t)r0 * N + c0;
            float* p1 = C + (size_t)(r0 + 8) * N + c0;
            if (accum) {
                float2 o0 = *(const float2*)p0;
                float2 o1 = *(const float2*)p1;
                v0.x += o0.x; v0.y += o0.y;
                v1.x += o1.x; v1.y += o1.y;
            }
            *(float2*)p0 = v0;
            *(float2*)p1 = v1;
        }
    }
}

// =================== scores: S = scale*Q@K^T + mask, bf16x3 MMA ===================
// grid (4, 4, BB*NHEAD)
__global__ __launch_bounds__(256)
void scores_mma(const __nv_bfloat16* __restrict__ Qh, const __nv_bfloat16* __restrict__ Ql,
                const __nv_bfloat16* __restrict__ Kh, const __nv_bfloat16* __restrict__ Kl,
                const int* __restrict__ mT, const int* __restrict__ mM,
                float* __restrict__ S_)
{
    extern __shared__ char smc[];
    const int tid  = threadIdx.x;
    const int wid  = tid >> 5;
    const int lane = tid & 31;
    const int t4   = lane & 3;
    const int g    = lane >> 2;
    const int wm   = wid >> 1;
    const int wn   = wid & 1;
    const int z    = blockIdx.z;
    const int bb   = z >> 4;
    const int hh   = z & 15;
    const int bm   = blockIdx.y * 128;
    const int bn   = blockIdx.x * 128;
    const uint32_t sb = smem_u32(smc);
    int* msk = (int*)(smc + 2 * STGB);

    const int* mask = (bb < 4) ? (mT + bb * SEQ) : (mM + (bb - 4) * SEQ);
    if (tid < 128) msk[tid] = mask[bn + tid];

    float* Sbase = S_ + (size_t)z * SEQ * SEQ;

    if (bn > bm) {   // fully masked tile
        __syncthreads();
        for (int i = tid; i < 128 * 128; i += 256) {
            int r = i >> 7, c = i & 127;
            Sbase[(size_t)(bm + r) * SEQ + bn + c] = -1e9f;
        }
        return;
    }

    float d[2][8][4];
    #pragma unroll
    for (int mt = 0; mt < 2; mt++)
        #pragma unroll
        for (int nt = 0; nt < 8; nt++)
            #pragma unroll
            for (int j = 0; j < 4; j++) d[mt][nt][j] = 0.f;

    const __nv_bfloat16* aH = Qh + (size_t)(bb * SEQ + bm) * DMODEL + hh * HDIM;
    const __nv_bfloat16* aL = Ql + (size_t)(bb * SEQ + bm) * DMODEL + hh * HDIM;
    const __nv_bfloat16* bH = Kh + (size_t)(bb * SEQ + bn) * DMODEL + hh * HDIM;
    const __nv_bfloat16* bL = Kl + (size_t)(bb * SEQ + bn) * DMODEL + hh * HDIM;

    const int nk = HDIM >> 5;   // 4
    ISSUE_STAGE(0, aH, aL, bH, bL, DMODEL, DMODEL);
    for (int kt = 0; kt < nk; kt++) {
        if (kt + 1 < nk) { ISSUE_STAGE(kt + 1, aH, aL, bH, bL, DMODEL, DMODEL); cp_wait<1>(); }
        else             cp_wait<0>();
        __syncthreads();
        const uint32_t st = sb + (kt & 1) * STGB;
        COMPUTE_STAGE(st)
        __syncthreads();
    }

    #pragma unroll
    for (int mt = 0; mt < 2; mt++) {
        const int r0 = wm * 32 + mt * 16 + g;
        #pragma unroll
        for (int nt = 0; nt < 8; nt++) {
            const int c0 = wn * 64 + nt * 8 + 2 * t4;
            #pragma unroll
            for (int half = 0; half < 2; half++) {
                int r = r0 + half * 8;
                int sq = bm + r, sk0 = bn + c0;
                float va = d[mt][nt][half * 2], vb = d[mt][nt][half * 2 + 1];
                bool ok0 = (sk0 <= sq) && (msk[c0] > 0);
                bool ok1 = (sk0 + 1 <= sq) && (msk[c0 + 1] > 0);
                float2 out;
                out.x = va * SCALE_QK + (ok0 ? 0.f : -1e9f);
                out.y = vb * SCALE_QK + (ok1 ? 0.f : -1e9f);
                *(float2*)(Sbase + (size_t)sq * SEQ + sk0) = out;
            }
        }
    }
}

// =================== attnv: O = P@V, bf16x3 MMA ===================
// grid (1, 4, BB*NHEAD); Vt is per-head transposed [z][d][tok]
__global__ __launch_bounds__(256)
void attnv_mma(const __nv_bfloat16* __restrict__ Ph, const __nv_bfloat16* __restrict__ Pl,
               const __nv_bfloat16* __restrict__ Vth, const __nv_bfloat16* __restrict__ Vtl,
               float* __restrict__ O,
               __nv_bfloat16* __restrict__ Oh, __nv_bfloat16* __restrict__ Ol)
{
    extern __shared__ char smc[];
    const int tid  = threadIdx.x;
    const int wid  = tid >> 5;
    const int lane = tid & 31;
    const int t4   = lane & 3;
    const int g    = lane >> 2;
    const int wm   = wid >> 1;
    const int wn   = wid & 1;
    const int z    = blockIdx.z;
    const int bb   = z >> 4;
    const int hh   = z & 15;
    const int bm   = blockIdx.y * 128;
    const uint32_t sb = smem_u32(smc);

    float d[2][8][4];
    #pragma unroll
    for (int mt = 0; mt < 2; mt++)
        #pragma unroll
        for (int nt = 0; nt < 8; nt++)
            #pragma unroll
            for (int j = 0; j < 4; j++) d[mt][nt][j] = 0.f;

    const __nv_bfloat16* aH = Ph + ((size_t)z * SEQ + bm) * SEQ;
    const __nv_bfloat16* aL = Pl + ((size_t)z * SEQ + bm) * SEQ;
    const __nv_bfloat16* bH = Vth + (size_t)z * HDIM * SEQ;
    const __nv_bfloat16* bL = Vtl + (size_t)z * HDIM * SEQ;

    const int nk = SEQ >> 5;   // 16
    ISSUE_STAGE(0, aH, aL, bH, bL, SEQ, SEQ);
    for (int kt = 0; kt < nk; kt++) {
        if (kt + 1 < nk) { ISSUE_STAGE(kt + 1, aH, aL, bH, bL, SEQ, SEQ); cp_wait<1>(); }
        else             cp_wait<0>();
        __syncthreads();
        const uint32_t st = sb + (kt & 1) * STGB;
        COMPUTE_STAGE(st)
        __syncthreads();
    }

    #pragma unroll
    for (int mt = 0; mt < 2; mt++) {
        const int r0 = bm + wm * 32 + mt * 16 + g;
        #pragma unroll
        for (int nt = 0; nt < 8; nt++) {
            const int c0 = wn * 64 + nt * 8 + 2 * t4;
            #pragma unroll
            for (int half = 0; half < 2; half++) {
                int r = r0 + half * 8;
                size_t oidx = (size_t)(bb * SEQ + r) * DMODEL + hh * HDIM + c0;
                float va = d[mt][nt][half * 2], vb = d[mt][nt][half * 2 + 1];
                *(float2*)(O + oidx) = make_float2(va, vb);
                __nv_bfloat16 h0, l0, h1, l1;
                split_bf16(va, h0, l0);
                split_bf16(vb, h1, l1);
                Oh[oidx] = h0; Oh[oidx + 1] = h1;
                Ol[oidx] = l0; Ol[oidx + 1] = l1;
            }
        }
    }
}

// ---------------- weight transpose + split ----------------
__global__ void transpose_split(const float* __restrict__ W,
                                __nv_bfloat16* __restrict__ Wh, __nv_bfloat16* __restrict__ Wl,
                                int Kd, int Nd)
{
    __shared__ float tile[32][33];
    int n0 = blockIdx.x * 32, k0 = blockIdx.y * 32;
    int x = threadIdx.x, y = threadIdx.y;
    #pragma unroll
    for (int dy = 0; dy < 32; dy += 8)
        tile[y + dy][x] = W[(size_t)(k0 + y + dy) * Nd + n0 + x];
    __syncthreads();
    #pragma unroll
    for (int dy = 0; dy < 32; dy += 8) {
        float v = tile[x][y + dy];
        size_t o = (size_t)(n0 + y + dy) * Kd + k0 + x;
        __nv_bfloat16 h, l;
        split_bf16(v, h, l);
        Wh[o] = h; Wl[o] = l;
    }
}

// ---------------- V transpose + split per head: Vt[z][d][s] ----------------
__global__ void vsplit_t(const float* __restrict__ V,
                         __nv_bfloat16* __restrict__ Vth, __nv_bfloat16* __restrict__ Vtl)
{
    __shared__ float tile[32][33];
    int tok0 = blockIdx.x * 32, d0 = blockIdx.y * 32;
    int x = threadIdx.x, y = threadIdx.y;
    #pragma unroll
    for (int dy = 0; dy < 32; dy += 8)
        tile[y + dy][x] = V[(size_t)(tok0 + y + dy) * DMODEL + d0 + x];
    __syncthreads();
    int bb = tok0 >> 9, s0 = tok0 & 511;
    int hh = d0 >> 7, dd0 = d0 & 127;
    size_t zb = ((size_t)(bb * NHEAD + hh)) * HDIM * SEQ;
    #pragma unroll
    for (int dy = 0; dy < 32; dy += 8) {
        float v = tile[x][y + dy];
        size_t oidx = zb + (size_t)(dd0 + y + dy) * SEQ + s0 + x;
        __nv_bfloat16 h, l;
        split_bf16(v, h, l);
        Vth[oidx] = h; Vtl[oidx] = l;
    }
}

// ---------------- embedding gather ----------------
__global__ void embed_kernel(const int* __restrict__ idT, const int* __restrict__ idM,
                             const float* __restrict__ E, float* __restrict__ H)
{
    int t  = blockIdx.x;
    int bb = t >> 9;
    int s  = t & 511;
    int id = (bb < 4) ? idT[bb * SEQ + s] : idM[(bb - 4) * SEQ + s];
    const float4* src = reinterpret_cast<const float4*>(E + (size_t)id * DMODEL);
    float4*       dst = reinterpret_cast<float4*>(H + (size_t)t * DMODEL);
    for (int j = threadIdx.x; j < DMODEL / 4; j += blockDim.x) dst[j] = src[j];
}

// ---------------- rmsnorm (emits fp32 + split bf16) ----------------
__global__ void rmsnorm_kernel(const float* __restrict__ H, const float* __restrict__ W,
                               float* __restrict__ X,
                               __nv_bfloat16* __restrict__ Xh, __nv_bfloat16* __restrict__ Xl)
{
    __shared__ float red[256];
    int row = blockIdx.x;
    const float* h = H + (size_t)row * DMODEL;
    float s = 0.f;
    for (int j = threadIdx.x; j < DMODEL; j += 256) { float v = h[j]; s += v * v; }
    red[threadIdx.x] = s; __syncthreads();
    for (int o = 128; o > 0; o >>= 1) {
        if (threadIdx.x < o) red[threadIdx.x] += red[threadIdx.x + o];
        __syncthreads();
    }
    float scale = rsqrtf(red[0] / (float)DMODEL + 1e-6f);
    size_t base = (size_t)row * DMODEL;
    for (int j = threadIdx.x; j < DMODEL; j += 256) {
        float v = h[j] * scale * W[j];
        X[base + j] = v;
        __nv_bfloat16 hh, ll;
        split_bf16(v, hh, ll);
        Xh[base + j] = hh; Xl[base + j] = ll;
    }
}

// ---------------- lora T kernels ----------------
__global__ void lora_t_kernel(const float* __restrict__ X, const float* __restrict__ A,
                              float* __restrict__ T, int K)
{
    int row = blockIdx.x * 16 + (threadIdx.x >> 4);
    int r   = threadIdx.x & 15;
    const float* x = X + (size_t)row * K;
    float acc = 0.f;
    #pragma unroll 4
    for (int k = 0; k < K; k++) acc += x[k] * A[k * RLORA + r];
    T[row * RLORA + r] = acc;
}
__global__ void lora3_kernel(const float* __restrict__ X,
                             const float* __restrict__ A0, const float* __restrict__ A1,
                             const float* __restrict__ A2,
                             float* __restrict__ T0, float* __restrict__ T1, float* __restrict__ T2,
                             int K)
{
    int row = blockIdx.x * 16 + (threadIdx.x >> 4);
    int r   = threadIdx.x & 15;
    const float* x = X + (size_t)row * K;
    float a0 = 0.f, a1 = 0.f, a2 = 0.f;
    #pragma unroll 4
    for (int k = 0; k < K; k++) {
        float xv = x[k];
        a0 += xv * A0[k * RLORA + r];
        a1 += xv * A1[k * RLORA + r];
        a2 += xv * A2[k * RLORA + r];
    }
    T0[row * RLORA + r] = a0;
    T1[row * RLORA + r] = a1;
    T2[row * RLORA + r] = a2;
}
__global__ void lora2_kernel(const float* __restrict__ X,
                             const float* __restrict__ A0, const float* __restrict__ A1,
                             float* __restrict__ T0, float* __restrict__ T1, int K)
{
    int row = blockIdx.x * 16 + (threadIdx.x >> 4);
    int r   = threadIdx.x & 15;
    const float* x = X + (size_t)row * K;
    float a0 = 0.f, a1 = 0.f;
    #pragma unroll 4
    for (int k = 0; k < K; k++) {
        float xv = x[k];
        a0 += xv * A0[k * RLORA + r];
        a1 += xv * A1[k * RLORA + r];
    }
    T0[row * RLORA + r] = a0;
    T1[row * RLORA + r] = a1;
}

// ---------------- RoPE: reads fp32 q/k, emits split bf16 ----------------
__global__ void rope_kernel(const float* __restrict__ Q, const float* __restrict__ Kt,
                            __nv_bfloat16* __restrict__ Qh, __nv_bfloat16* __restrict__ Ql,
                            __nv_bfloat16* __restrict__ Kh, __nv_bfloat16* __restrict__ Kl)
{
    int i = blockIdx.x * blockDim.x + threadIdx.x;
    if (i >= MTOK * NHEAD * 64) return;
    int d = i & 63;
    int h = (i >> 6) & 15;
    int t = i >> 10;
    int s = t & 511;
    float freq = expf(-(float)d * (logf(10000.f) / 64.f));
    float ang = (float)s * freq;
    float sn, cs;
    sincosf(ang, &sn, &cs);
    size_t b0 = (size_t)t * DMODEL + h * HDIM + d;
    __nv_bfloat16 hh, ll;
    float x1 = Q[b0], x2 = Q[b0 + 64];
    float r1 = x1 * cs - x2 * sn;
    float r2 = x1 * sn + x2 * cs;
    split_bf16(r1, hh, ll); Qh[b0] = hh;      Ql[b0] = ll;
    split_bf16(r2, hh, ll); Qh[b0 + 64] = hh; Ql[b0 + 64] = ll;
    x1 = Kt[b0]; x2 = Kt[b0 + 64];
    r1 = x1 * cs - x2 * sn;
    r2 = x1 * sn + x2 * cs;
    split_bf16(r1, hh, ll); Kh[b0] = hh;      Kl[b0] = ll;
    split_bf16(r2, hh, ll); Kh[b0 + 64] = hh; Kl[b0 + 64] = ll;
}

// ---------------- row softmax, emits split bf16 probs ----------------
__global__ void softmax_kernel(const float* __restrict__ S_,
                               __nv_bfloat16* __restrict__ Ph, __nv_bfloat16* __restrict__ Pl)
{
    __shared__ float red[256];
    const float* p = S_ + (size_t)blockIdx.x * SEQ;
    int t = threadIdx.x;
    float v0 = p[t], v1 = p[t + 256];
    float m = fmaxf(v0, v1);
    red[t] = m; __syncthreads();
    for (int o = 128; o > 0; o >>= 1) {
        if (t < o) red[t] = fmaxf(red[t], red[t + o]);
        __syncthreads();
    }
    m = red[0]; __syncthreads();
    float e0 = expf(v0 - m), e1 = expf(v1 - m);
    red[t] = e0 + e1; __syncthreads();
    for (int o = 128; o > 0; o >>= 1) {
        if (t < o) red[t] += red[t + o];
        __syncthreads();
    }
    float inv = 1.f / red[0];
    size_t base = (size_t)blockIdx.x * SEQ;
    __nv_bfloat16 hh, ll;
    split_bf16(e0 * inv, hh, ll); Ph[base + t] = hh;       Pl[base + t] = ll;
    split_bf16(e1 * inv, hh, ll); Ph[base + t + 256] = hh; Pl[base + t + 256] = ll;
}

// ---------------- swiglu (emits split bf16) ----------------
__global__ void swiglu_kernel(float* __restrict__ G, const float* __restrict__ U,
                              __nv_bfloat16* __restrict__ Gh, __nv_bfloat16* __restrict__ Gl)
{
    size_t i = (size_t)blockIdx.x * blockDim.x + threadIdx.x;
    if (i >= (size_t)MTOK * FFDIM) return;
    float g = G[i];
    float sig = 1.f / (1.f + expf(-g));
    float v = g * sig * U[i];
    G[i] = v;
    __nv_bfloat16 hh, ll;
    split_bf16(v, hh, ll);
    Gh[i] = hh; Gl[i] = ll;
}

// ---------------- reps extraction + L2 normalize ----------------
__global__ void reps_kernel(const float* __restrict__ X, const int* __restrict__ mT,
                            const int* __restrict__ mM, float* __restrict__ R_)
{
    __shared__ int ired[256];
    __shared__ float fred[256];
    __shared__ int sidx;
    int bb = blockIdx.x;
    const int* mask = (bb < 4) ? mT : mM;
    int b = bb & 3;
    int t = threadIdx.x;
    int s = 0;
    for (int j = t; j < SEQ; j += 256) s += mask[b * SEQ + j];
    ired[t] = s; __syncthreads();
    for (int o = 128; o > 0; o >>= 1) {
        if (t < o) ired[t] += ired[t + o];
        __syncthreads();
    }
    if (t == 0) {
        int last = mask[0 * SEQ + 511] + mask[1 * SEQ + 511] +
                   mask[2 * SEQ + 511] + mask[3 * SEQ + 511];
        sidx = (last == BATCH) ? (SEQ - 1) : (ired[0] - 1);
    }
    __syncthreads();
    const float* row = X + (size_t)(bb * SEQ + sidx) * DMODEL;
    float ss = 0.f;
    for (int j = t; j < DMODEL; j += 256) { float v = row[j]; ss += v * v; }
    fred[t] = ss; __syncthreads();
    for (int o = 128; o > 0; o >>= 1) {
        if (t < o) fred[t] += fred[t + o];
        __syncthreads();
    }
    float inv = 1.f / sqrtf(fred[0]);
    for (int j = t; j < DMODEL; j += 256) R_[bb * DMODEL + j] = row[j] * inv;
}

// ---------------- contrastive loss ----------------
__global__ void loss_kernel(const float* __restrict__ R_, float* __restrict__ out)
{
    __shared__ float sims[16];
    int tid = threadIdx.x;
    int warp = tid >> 5, lane = tid & 31;
    for (int p = warp; p < 16; p += 8) {
        int i = p >> 2, j = p & 3;
        const float* a = R_ + i * DMODEL;
        const float* bR = R_ + (4 + j) * DMODEL;
        float d = 0.f;
        for (int k2 = lane; k2 < DMODEL; k2 += 32) d += a[k2] * bR[k2];
        #pragma unroll
        for (int o = 16; o > 0; o >>= 1) d += __shfl_xor_sync(0xffffffff, d, o);
        if (lane == 0) sims[p] = d * 20.f;
    }
    __syncthreads();
    if (tid == 0) {
        float loss = 0.f;
        for (int i = 0; i < 4; i++) {
            float m = -1e30f;
            for (int j = 0; j < 4; j++) m = fmaxf(m, sims[i * 4 + j]);
            float sum = 0.f;
            for (int j = 0; j < 4; j++) sum += expf(sims[i * 4 + j] - m);
            loss += (logf(sum) + m) - sims[i * 4 + i];
        }
        out[0] = loss * 0.25f;
    }
}

// ---------------- host driver ----------------
static void* symaddr_raw(const void* sym)
{
    void* p = nullptr;
    cudaGetSymbolAddress(&p, sym);
    return p;
}

extern "C" void kernel_launch(void* const* d_in, const int* in_sizes, int n_in,
                              void* d_out, int out_size)
{
    const int*   idT = (const int*)d_in[0];
    const int*   mT  = (const int*)d_in[1];
    const int*   idM = (const int*)d_in[2];
    const int*   mM  = (const int*)d_in[3];
    const float* emb = (const float*)d_in[4];
    const float* ln1 = (const float*)d_in[5];
    const float* ln2 = (const float*)d_in[6];
    const float* lnf = (const float*)d_in[7];
    const float* Wq = (const float*)d_in[8],  *Aq = (const float*)d_in[9],  *Bq = (const float*)d_in[10];
    const float* Wk = (const float*)d_in[11], *Ak = (const float*)d_in[12], *Bk = (const float*)d_in[13];
    const float* Wv = (const float*)d_in[14], *Av = (const float*)d_in[15], *Bv = (const float*)d_in[16];
    const float* Wo = (const float*)d_in[17], *Ao = (const float*)d_in[18], *Bo = (const float*)d_in[19];
    const float* Wg = (const float*)d_in[20], *Ag = (const float*)d_in[21], *Bg = (const float*)d_in[22];
    const float* Wu = (const float*)d_in[23], *Au = (const float*)d_in[24], *Bu = (const float*)d_in[25];
    const float* Wd = (const float*)d_in[26], *Ad = (const float*)d_in[27], *Bd = (const float*)d_in[28];

    float* h  = (float*)symaddr_raw(g_h);
    float* x  = (float*)symaddr_raw(g_x);
    float* q  = (float*)symaddr_raw(g_q);
    float* k  = (float*)symaddr_raw(g_k);
    float* v  = (float*)symaddr_raw(g_v);
    float* o  = (float*)symaddr_raw(g_o);
    float* sc = (float*)symaddr_raw(g_sc);
    float* gg = (float*)symaddr_raw(g_gate);
    float* uu = (float*)symaddr_raw(g_up);
    float* t0 = (float*)symaddr_raw(g_t);
    float* t1 = t0 + MTOK * RLORA;
    float* t2 = t0 + 2 * MTOK * RLORA;
    float* rp = (float*)symaddr_raw(g_reps);
    __nv_bfloat16* ah  = (__nv_bfloat16*)symaddr_raw(g_ah);
    __nv_bfloat16* al  = (__nv_bfloat16*)symaddr_raw(g_al);
    __nv_bfloat16* wh  = (__nv_bfloat16*)symaddr_raw(g_wh);
    __nv_bfloat16* wl  = (__nv_bfloat16*)symaddr_raw(g_wl);
    __nv_bfloat16* qh  = (__nv_bfloat16*)symaddr_raw(g_qh);
    __nv_bfloat16* ql  = (__nv_bfloat16*)symaddr_raw(g_ql);
    __nv_bfloat16* kh  = (__nv_bfloat16*)symaddr_raw(g_kh);
    __nv_bfloat16* kl  = (__nv_bfloat16*)symaddr_raw(g_kl);
    __nv_bfloat16* ph  = (__nv_bfloat16*)symaddr_raw(g_ph);
    __nv_bfloat16* pl  = (__nv_bfloat16*)symaddr_raw(g_pl);
    __nv_bfloat16* vth = (__nv_bfloat16*)symaddr_raw(g_vth);
    __nv_bfloat16* vtl = (__nv_bfloat16*)symaddr_raw(g_vtl);

    cudaFuncSetAttribute(gemm_tc,    cudaFuncAttributeMaxDynamicSharedMemorySize, GSMEM);
    cudaFuncSetAttribute(scores_mma, cudaFuncAttributeMaxDynamicSharedMemorySize, SCSM);
    cudaFuncSetAttribute(attnv_mma,  cudaFuncAttributeMaxDynamicSharedMemorySize, AVSM);

    const size_t DD = (size_t)DMODEL * DMODEL;
    const size_t DF = (size_t)DMODEL * FFDIM;
    const size_t LSTR = 4 * DD + 3 * DF;
    const dim3 tD(DMODEL / 32, DMODEL / 32), tB(32, 8);
    const dim3 tF(FFDIM / 32, DMODEL / 32);
    const dim3 tFd(DMODEL / 32, FFDIM / 32);
    const dim3 gD(DMODEL / 128, MTOK / 128);
    const dim3 gF(FFDIM / 128, MTOK / 128);

    // ---- prologue ordered so launch #5 (0-based) is gemm_tc for ncu ----
    transpose_split<<<tD, tB>>>(Wq, wh, wl, DMODEL, DMODEL);                          // 0
    embed_kernel<<<MTOK, 256>>>(idT, idM, emb, h);                                    // 1
    rmsnorm_kernel<<<MTOK, 256>>>(h, ln1, x, ah, al);                                 // 2
    lora3_kernel<<<MTOK / 16, 256>>>(x, Aq, Ak, Av, t0, t1, t2, DMODEL);              // 3
    transpose_split<<<tD, tB>>>(Wk, wh + DD, wl + DD, DMODEL, DMODEL);                // 4
    gemm_tc<<<gD, 256, GSMEM>>>(ah, al, wh, wl, q, MTOK, DMODEL, DMODEL, t0, Bq, 0);  // 5 <- profiled

    // remaining transposes (layer 0 rest + all of layer 1)
    transpose_split<<<tD, tB>>>(Wv, wh + 2 * DD, wl + 2 * DD, DMODEL, DMODEL);
    transpose_split<<<tD, tB>>>(Wo, wh + 3 * DD, wl + 3 * DD, DMODEL, DMODEL);
    transpose_split<<<tF, tB>>>(Wg, wh + 4 * DD, wl + 4 * DD, DMODEL, FFDIM);
    transpose_split<<<tF, tB>>>(Wu, wh + 4 * DD + DF, wl + 4 * DD + DF, DMODEL, FFDIM);
    transpose_split<<<tFd, tB>>>(Wd, wh + 4 * DD + 2 * DF, wl + 4 * DD + 2 * DF, FFDIM, DMODEL);
    for (int l = 1; l < LAYERS; l++) {
        size_t off = (size_t)l * LSTR;
        transpose_split<<<tD, tB>>>(Wq + l * DD, wh + off,          wl + off,          DMODEL, DMODEL);
        transpose_split<<<tD, tB>>>(Wk + l * DD, wh + off + DD,     wl + off + DD,     DMODEL, DMODEL);
        transpose_split<<<tD, tB>>>(Wv + l * DD, wh + off + 2 * DD, wl + off + 2 * DD, DMODEL, DMODEL);
        transpose_split<<<tD, tB>>>(Wo + l * DD, wh + off + 3 * DD, wl + off + 3 * DD, DMODEL, DMODEL);
        transpose_split<<<tF, tB>>>(Wg + l * DF, wh + off + 4 * DD, wl + off + 4 * DD, DMODEL, FFDIM);
        transpose_split<<<tF, tB>>>(Wu + l * DF, wh + off + 4 * DD + DF, wl + off + 4 * DD + DF, DMODEL, FFDIM);
        transpose_split<<<tFd, tB>>>(Wd + l * DF, wh + off + 4 * DD + 2 * DF, wl + off + 4 * DD + 2 * DF, FFDIM, DMODEL);
    }

    for (int l = 0; l < LAYERS; l++) {
        size_t off = (size_t)l * LSTR;
        const __nv_bfloat16 *Wq_h = wh + off,               *Wq_l = wl + off;
        const __nv_bfloat16 *Wk_h = wh + off + DD,          *Wk_l = wl + off + DD;
        const __nv_bfloat16 *Wv_h = wh + off + 2 * DD,      *Wv_l = wl + off + 2 * DD;
        const __nv_bfloat16 *Wo_h = wh + off + 3 * DD,      *Wo_l = wl + off + 3 * DD;
        const __nv_bfloat16 *Wg_h = wh + off + 4 * DD,      *Wg_l = wl + off + 4 * DD;
        const __nv_bfloat16 *Wu_h = wh + off + 4 * DD + DF, *Wu_l = wl + off + 4 * DD + DF;
        const __nv_bfloat16 *Wd_h = wh + off + 4 * DD + 2 * DF, *Wd_l = wl + off + 4 * DD + 2 * DF;
        const float* Bq_l = Bq + (size_t)l * RLORA * DMODEL;
        const float* Bk_l = Bk + (size_t)l * RLORA * DMODEL;
        const float* Bv_l = Bv + (size_t)l * RLORA * DMODEL;
        const float* Bo_l = Bo + (size_t)l * RLORA * DMODEL;
        const float* Bg_l = Bg + (size_t)l * RLORA * FFDIM;
        const float* Bu_l = Bu + (size_t)l * RLORA * FFDIM;
        const float* Bd_l = Bd + (size_t)l * RLORA * DMODEL;

        if (l > 0) {
            rmsnorm_kernel<<<MTOK, 256>>>(h, ln1 + l * DMODEL, x, ah, al);
            lora3_kernel<<<MTOK / 16, 256>>>(x, Aq + l * DMODEL * RLORA, Ak + l * DMODEL * RLORA,
                                             Av + l * DMODEL * RLORA, t0, t1, t2, DMODEL);
            gemm_tc<<<gD, 256, GSMEM>>>(ah, al, Wq_h, Wq_l, q, MTOK, DMODEL, DMODEL, t0, Bq_l, 0);
        }
        gemm_tc<<<gD, 256, GSMEM>>>(ah, al, Wk_h, Wk_l, k, MTOK, DMODEL, DMODEL, t1, Bk_l, 0);
        gemm_tc<<<gD, 256, GSMEM>>>(ah, al, Wv_h, Wv_l, v, MTOK, DMODEL, DMODEL, t2, Bv_l, 0);

        rope_kernel<<<(MTOK * NHEAD * 64 + 255) / 256, 256>>>(q, k, qh, ql, kh, kl);
        vsplit_t<<<dim3(MTOK / 32, DMODEL / 32), tB>>>(v, vth, vtl);

        scores_mma<<<dim3(4, 4, BB * NHEAD), 256, SCSM>>>(qh, ql, kh, kl, mT, mM, sc);
        softmax_kernel<<<BB * NHEAD * SEQ, 256>>>(sc, ph, pl);
        attnv_mma<<<dim3(1, 4, BB * NHEAD), 256, AVSM>>>(ph, pl, vth, vtl, o, ah, al);

        lora_t_kernel<<<MTOK / 16, 256>>>(o, Ao + (size_t)l * DMODEL * RLORA, t0, DMODEL);
        gemm_tc<<<gD, 256, GSMEM>>>(ah, al, Wo_h, Wo_l, h, MTOK, DMODEL, DMODEL, t0, Bo_l, 1);

        rmsnorm_kernel<<<MTOK, 256>>>(h, ln2 + l * DMODEL, x, ah, al);
        lora2_kernel<<<MTOK / 16, 256>>>(x, Ag + (size_t)l * DMODEL * RLORA,
                                         Au + (size_t)l * DMODEL * RLORA, t0, t1, DMODEL);
        gemm_tc<<<gF, 256, GSMEM>>>(ah, al, Wg_h, Wg_l, gg, MTOK, FFDIM, DMODEL, t0, Bg_l, 0);
        gemm_tc<<<gF, 256, GSMEM>>>(ah, al, Wu_h, Wu_l, uu, MTOK, FFDIM, DMODEL, t1, Bu_l, 0);

        swiglu_kernel<<<(int)(((size_t)MTOK * FFDIM + 255) / 256), 256>>>(gg, uu, ah, al);

        lora_t_kernel<<<MTOK / 16, 256>>>(gg, Ad + (size_t)l * FFDIM * RLORA, t0, FFDIM);
        gemm_tc<<<gD, 256, GSMEM>>>(ah, al, Wd_h, Wd_l, h, MTOK, DMODEL, FFDIM, t0, Bd_l, 1);
    }

    rmsnorm_kernel<<<MTOK, 256>>>(h, lnf, x, ah, al);
    reps_kernel<<<BB, 256>>>(x, mT, mM, rp);
    loss_kernel<<<1, 256>>>(rp, (float*)d_out);
}

// round 7
// speedup vs baseline: 3.7828x; 1.2007x over previous
#include <cuda_runtime.h>
#include <cuda_bf16.h>
#include <math.h>
#include <stdint.h>

// Problem constants
#define LAYERS 2
#define DMODEL 2048
#define NHEAD  16
#define HDIM   128
#define FFDIM  5632
#define RLORA  16
#define BATCH  4
#define SEQ    512
#define BB     8
#define MTOK   (BB*SEQ)
#define LORA_SCALE 1.4f
#define SCALE_QK 0.08838834764831845f

// ---------------- scratch ----------------
__device__ float g_h   [MTOK * DMODEL];
__device__ float g_x   [MTOK * DMODEL];
__device__ float g_q   [MTOK * DMODEL];
__device__ float g_k   [MTOK * DMODEL];
__device__ float g_v   [MTOK * DMODEL];
__device__ float g_o   [MTOK * DMODEL];
__device__ float g_sc  [BB * NHEAD * SEQ * SEQ];
__device__ float g_gate[MTOK * FFDIM];
__device__ float g_up  [MTOK * FFDIM];
__device__ float g_t   [3 * MTOK * RLORA];
__device__ float g_reps[BB * DMODEL];
__device__ __nv_bfloat16 g_ah[MTOK * FFDIM];
__device__ __nv_bfloat16 g_al[MTOK * FFDIM];
__device__ __nv_bfloat16 g_wh[2 * (4 * DMODEL * DMODEL + 3 * DMODEL * FFDIM)];
__device__ __nv_bfloat16 g_wl[2 * (4 * DMODEL * DMODEL + 3 * DMODEL * FFDIM)];
__device__ __nv_bfloat16 g_qh[MTOK * DMODEL];
__device__ __nv_bfloat16 g_ql[MTOK * DMODEL];
__device__ __nv_bfloat16 g_kh[MTOK * DMODEL];
__device__ __nv_bfloat16 g_kl[MTOK * DMODEL];
__device__ __nv_bfloat16 g_ph[BB * NHEAD * SEQ * SEQ];
__device__ __nv_bfloat16 g_pl[BB * NHEAD * SEQ * SEQ];
__device__ __nv_bfloat16 g_vth[MTOK * DMODEL];
__device__ __nv_bfloat16 g_vtl[MTOK * DMODEL];

// =================== helpers ===================
__device__ __forceinline__ uint32_t smem_u32(const void* p) {
    uint32_t a;
    asm("{ .reg .u64 t; cvta.to.shared.u64 t, %1; cvt.u32.u64 %0, t; }" : "=r"(a) : "l"(p));
    return a;
}
__device__ __forceinline__ void cp_async16(uint32_t saddr, const void* gptr) {
    asm volatile("cp.async.cg.shared.global [%0], [%1], 16;" :: "r"(saddr), "l"(gptr));
}
__device__ __forceinline__ void cp_commit() { asm volatile("cp.async.commit_group;"); }
template <int NWAIT>
__device__ __forceinline__ void cp_wait() {
    asm volatile("cp.async.wait_group %0;" :: "n"(NWAIT));
}
__device__ __forceinline__ void mma16(float* d, const uint32_t* a, uint32_t b0, uint32_t b1) {
    asm volatile(
        "mma.sync.aligned.m16n8k16.row.col.f32.bf16.bf16.f32 "
        "{%0,%1,%2,%3}, {%4,%5,%6,%7}, {%8,%9}, {%0,%1,%2,%3};"
        : "+f"(d[0]), "+f"(d[1]), "+f"(d[2]), "+f"(d[3])
        : "r"(a[0]), "r"(a[1]), "r"(a[2]), "r"(a[3]), "r"(b0), "r"(b1));
}
__device__ __forceinline__ void ldm_x4(uint32_t* r, uint32_t addr) {
    asm volatile("ldmatrix.sync.aligned.m8n8.x4.shared.b16 {%0,%1,%2,%3}, [%4];"
                 : "=r"(r[0]), "=r"(r[1]), "=r"(r[2]), "=r"(r[3]) : "r"(addr));
}
__device__ __forceinline__ void split_bf16(float v, __nv_bfloat16& h, __nv_bfloat16& l) {
    h = __float2bfloat16(v);
    l = __float2bfloat16(v - __bfloat162float(h));
}

#define SMSB   80
#define ARRB   10240
#define STGB   40960
#define LA_OFF 81920
#define LB_OFF 88064
#define GSMEM  94208
#define SCSM   82432
#define AVSM   81920

#define COMPUTE_STAGE(stbase)                                                     \
    _Pragma("unroll")                                                             \
    for (int ks = 0; ks < 32; ks += 16) {                                         \
        uint32_t ahf[2][4], alf[2][4];                                            \
        {                                                                         \
            int grp = lane >> 3, r8 = lane & 7;                                   \
            int mm = (grp & 1) * 8 + r8;                                          \
            int koff = (grp >> 1) * 8;                                            \
            _Pragma("unroll")                                                     \
            for (int mt = 0; mt < 2; mt++) {                                      \
                uint32_t ad = (stbase) + (wm * 32 + mt * 16 + mm) * SMSB + (ks + koff) * 2; \
                ldm_x4(ahf[mt], ad);                                              \
                ldm_x4(alf[mt], ad + ARRB);                                       \
            }                                                                     \
        }                                                                         \
        _Pragma("unroll")                                                         \
        for (int np = 0; np < 4; np++) {                                          \
            int grp = lane >> 3, r8 = lane & 7;                                   \
            int nn = (grp >> 1) * 8 + r8;                                         \
            int koff = (grp & 1) * 8;                                             \
            uint32_t bd = (stbase) + 2 * ARRB + (wn * 64 + np * 16 + nn) * SMSB + (ks + koff) * 2; \
            uint32_t bh[4], bl[4];                                                \
            ldm_x4(bh, bd);                                                       \
            ldm_x4(bl, bd + ARRB);                                                \
            _Pragma("unroll")                                                     \
            for (int mt = 0; mt < 2; mt++) {                                      \
                mma16(d[mt][np * 2],     ahf[mt], bh[0], bh[1]);                  \
                mma16(d[mt][np * 2],     ahf[mt], bl[0], bl[1]);                  \
                mma16(d[mt][np * 2],     alf[mt], bh[0], bh[1]);                  \
                mma16(d[mt][np * 2 + 1], ahf[mt], bh[2], bh[3]);                  \
                mma16(d[mt][np * 2 + 1], ahf[mt], bl[2], bl[3]);                  \
                mma16(d[mt][np * 2 + 1], alf[mt], bh[2], bh[3]);                  \
            }                                                                     \
        }                                                                         \
    }

#define ISSUE_STAGE(kt, aH, aL, bH, bL, LDA, LDB)                                 \
    {                                                                             \
        const int k0_ = (kt) << 5;                                                \
        const int buf_ = (kt) & 1;                                                \
        _Pragma("unroll")                                                         \
        for (int j = 0; j < 8; j++) {                                             \
            int e = tid + j * 256;                                                \
            int arr = e >> 9;                                                     \
            int i = e & 511;                                                      \
            int row = i >> 2;                                                     \
            int cg = (i & 3) << 3;                                                \
            const __nv_bfloat16* gp;                                              \
            if (arr == 0)      gp = (aH) + (size_t)row * (LDA) + k0_ + cg;        \
            else if (arr == 1) gp = (aL) + (size_t)row * (LDA) + k0_ + cg;        \
            else if (arr == 2) gp = (bH) + (size_t)row * (LDB) + k0_ + cg;        \
            else               gp = (bL) + (size_t)row * (LDB) + k0_ + cg;        \
            cp_async16(sb + buf_ * STGB + arr * ARRB + row * SMSB + cg * 2, gp);  \
        }                                                                         \
        cp_commit();                                                              \
    }

// =================== main GEMM with fused LoRA + residual ===================
__global__ __launch_bounds__(256)
void gemm_tc(const __nv_bfloat16* __restrict__ Agh, const __nv_bfloat16* __restrict__ Agl,
             const __nv_bfloat16* __restrict__ Wgh, const __nv_bfloat16* __restrict__ Wgl,
             float* __restrict__ C, int M, int N, int K,
             const float* __restrict__ lT, const float* __restrict__ lB, int accum)
{
    extern __shared__ char smc[];
    const int tid  = threadIdx.x;
    const int wid  = tid >> 5;
    const int lane = tid & 31;
    const int t4   = lane & 3;
    const int g    = lane >> 2;
    const int wm   = wid >> 1;
    const int wn   = wid & 1;
    const int bm   = blockIdx.y * 128;
    const int bn   = blockIdx.x * 128;
    const uint32_t sb = smem_u32(smc);

    __nv_bfloat16* la = (__nv_bfloat16*)(smc + LA_OFF);
    __nv_bfloat16* lb = (__nv_bfloat16*)(smc + LB_OFF);
    for (int i = tid; i < 2048; i += 256) {
        int row = i >> 4, r = i & 15;
        la[row * 24 + r] = __float2bfloat16(LORA_SCALE * lT[(size_t)(bm + row) * RLORA + r]);
        lb[row * 24 + r] = __float2bfloat16(lB[(size_t)r * N + bn + row]);
    }

    float d[2][8][4];
    #pragma unroll
    for (int mt = 0; mt < 2; mt++)
        #pragma unroll
        for (int nt = 0; nt < 8; nt++)
            #pragma unroll
            for (int j = 0; j < 4; j++) d[mt][nt][j] = 0.f;

    const __nv_bfloat16* aH = Agh + (size_t)bm * K;
    const __nv_bfloat16* aL = Agl + (size_t)bm * K;
    const __nv_bfloat16* bH = Wgh + (size_t)bn * K;
    const __nv_bfloat16* bL = Wgl + (size_t)bn * K;

    const int nk = K >> 5;
    ISSUE_STAGE(0, aH, aL, bH, bL, K, K);
    for (int kt = 0; kt < nk; kt++) {
        if (kt + 1 < nk) { ISSUE_STAGE(kt + 1, aH, aL, bH, bL, K, K); cp_wait<1>(); }
        else             cp_wait<0>();
        __syncthreads();
        const uint32_t st = sb + (kt & 1) * STGB;
        COMPUTE_STAGE(st)
        __syncthreads();
    }

    // LoRA tail (hi-only, K=16)
    {
        uint32_t a[2][4];
        #pragma unroll
        for (int mt = 0; mt < 2; mt++) {
            const char* pa = (const char*)la + (wm * 32 + mt * 16 + g) * 48 + t4 * 4;
            a[mt][0] = *(const uint32_t*)(pa);
            a[mt][1] = *(const uint32_t*)(pa + 8 * 48);
            a[mt][2] = *(const uint32_t*)(pa + 16);
            a[mt][3] = *(const uint32_t*)(pa + 8 * 48 + 16);
        }
        #pragma unroll
        for (int nt = 0; nt < 8; nt++) {
            const char* pb = (const char*)lb + (wn * 64 + nt * 8 + g) * 48 + t4 * 4;
            uint32_t b0 = *(const uint32_t*)(pb);
            uint32_t b1 = *(const uint32_t*)(pb + 16);
            #pragma unroll
            for (int mt = 0; mt < 2; mt++) mma16(d[mt][nt], a[mt], b0, b1);
        }
    }

    #pragma unroll
    for (int mt = 0; mt < 2; mt++) {
        const int r0 = bm + wm * 32 + mt * 16 + g;
        #pragma unroll
        for (int nt = 0; nt < 8; nt++) {
            const int c0 = bn + wn * 64 + nt * 8 + 2 * t4;
            float2 v0 = make_float2(d[mt][nt][0], d[mt][nt][1]);
            float2 v1 = make_float2(d[mt][nt][2], d[mt][nt][3]);
            float* p0 = C + (size_t)r0 * N + c0;
            float* p1 = C + (size_t)(r0 + 8) * N + c0;
            if (accum) {
                float2 o0 = *(const float2*)p0;
                float2 o1 = *(const float2*)p1;
                v0.x += o0.x; v0.y += o0.y;
                v1.x += o1.x; v1.y += o1.y;
            }
            *(float2*)p0 = v0;
            *(float2*)p1 = v1;
        }
    }
}

// =================== scores ===================
__global__ __launch_bounds__(256)
void scores_mma(const __nv_bfloat16* __restrict__ Qh, const __nv_bfloat16* __restrict__ Ql,
                const __nv_bfloat16* __restrict__ Kh, const __nv_bfloat16* __restrict__ Kl,
                const int* __restrict__ mT, const int* __restrict__ mM,
                float* __restrict__ S_)
{
    extern __shared__ char smc[];
    const int tid  = threadIdx.x;
    const int wid  = tid >> 5;
    const int lane = tid & 31;
    const int t4   = lane & 3;
    const int g    = lane >> 2;
    const int wm   = wid >> 1;
    const int wn   = wid & 1;
    const int z    = blockIdx.z;
    const int bb   = z >> 4;
    const int hh   = z & 15;
    const int bm   = blockIdx.y * 128;
    const int bn   = blockIdx.x * 128;
    const uint32_t sb = smem_u32(smc);
    int* msk = (int*)(smc + 2 * STGB);

    const int* mask = (bb < 4) ? (mT + bb * SEQ) : (mM + (bb - 4) * SEQ);
    if (tid < 128) msk[tid] = mask[bn + tid];

    float* Sbase = S_ + (size_t)z * SEQ * SEQ;

    if (bn > bm) {
        __syncthreads();
        for (int i = tid; i < 128 * 128; i += 256) {
            int r = i >> 7, c = i & 127;
            Sbase[(size_t)(bm + r) * SEQ + bn + c] = -1e9f;
        }
        return;
    }

    float d[2][8][4];
    #pragma unroll
    for (int mt = 0; mt < 2; mt++)
        #pragma unroll
        for (int nt = 0; nt < 8; nt++)
            #pragma unroll
            for (int j = 0; j < 4; j++) d[mt][nt][j] = 0.f;

    const __nv_bfloat16* aH = Qh + (size_t)(bb * SEQ + bm) * DMODEL + hh * HDIM;
    const __nv_bfloat16* aL = Ql + (size_t)(bb * SEQ + bm) * DMODEL + hh * HDIM;
    const __nv_bfloat16* bH = Kh + (size_t)(bb * SEQ + bn) * DMODEL + hh * HDIM;
    const __nv_bfloat16* bL = Kl + (size_t)(bb * SEQ + bn) * DMODEL + hh * HDIM;

    const int nk = HDIM >> 5;
    ISSUE_STAGE(0, aH, aL, bH, bL, DMODEL, DMODEL);
    for (int kt = 0; kt < nk; kt++) {
        if (kt + 1 < nk) { ISSUE_STAGE(kt + 1, aH, aL, bH, bL, DMODEL, DMODEL); cp_wait<1>(); }
        else             cp_wait<0>();
        __syncthreads();
        const uint32_t st = sb + (kt & 1) * STGB;
        COMPUTE_STAGE(st)
        __syncthreads();
    }

    #pragma unroll
    for (int mt = 0; mt < 2; mt++) {
        const int r0 = wm * 32 + mt * 16 + g;
        #pragma unroll
        for (int nt = 0; nt < 8; nt++) {
            const int c0 = wn * 64 + nt * 8 + 2 * t4;
            #pragma unroll
            for (int half = 0; half < 2; half++) {
                int r = r0 + half * 8;
                int sq = bm + r, sk0 = bn + c0;
                float va = d[mt][nt][half * 2], vb = d[mt][nt][half * 2 + 1];
                bool ok0 = (sk0 <= sq) && (msk[c0] > 0);
                bool ok1 = (sk0 + 1 <= sq) && (msk[c0 + 1] > 0);
                float2 out;
                out.x = va * SCALE_QK + (ok0 ? 0.f : -1e9f);
                out.y = vb * SCALE_QK + (ok1 ? 0.f : -1e9f);
                *(float2*)(Sbase + (size_t)sq * SEQ + sk0) = out;
            }
        }
    }
}

// =================== attnv ===================
__global__ __launch_bounds__(256)
void attnv_mma(const __nv_bfloat16* __restrict__ Ph, const __nv_bfloat16* __restrict__ Pl,
               const __nv_bfloat16* __restrict__ Vth, const __nv_bfloat16* __restrict__ Vtl,
               float* __restrict__ O,
               __nv_bfloat16* __restrict__ Oh, __nv_bfloat16* __restrict__ Ol)
{
    extern __shared__ char smc[];
    const int tid  = threadIdx.x;
    const int wid  = tid >> 5;
    const int lane = tid & 31;
    const int t4   = lane & 3;
    const int g    = lane >> 2;
    const int wm   = wid >> 1;
    const int wn   = wid & 1;
    const int z    = blockIdx.z;
    const int bb   = z >> 4;
    const int hh   = z & 15;
    const int bm   = blockIdx.y * 128;
    const uint32_t sb = smem_u32(smc);

    float d[2][8][4];
    #pragma unroll
    for (int mt = 0; mt < 2; mt++)
        #pragma unroll
        for (int nt = 0; nt < 8; nt++)
            #pragma unroll
            for (int j = 0; j < 4; j++) d[mt][nt][j] = 0.f;

    const __nv_bfloat16* aH = Ph + ((size_t)z * SEQ + bm) * SEQ;
    const __nv_bfloat16* aL = Pl + ((size_t)z * SEQ + bm) * SEQ;
    const __nv_bfloat16* bH = Vth + (size_t)z * HDIM * SEQ;
    const __nv_bfloat16* bL = Vtl + (size_t)z * HDIM * SEQ;

    const int nk = SEQ >> 5;
    ISSUE_STAGE(0, aH, aL, bH, bL, SEQ, SEQ);
    for (int kt = 0; kt < nk; kt++) {
        if (kt + 1 < nk) { ISSUE_STAGE(kt + 1, aH, aL, bH, bL, SEQ, SEQ); cp_wait<1>(); }
        else             cp_wait<0>();
        __syncthreads();
        const uint32_t st = sb + (kt & 1) * STGB;
        COMPUTE_STAGE(st)
        __syncthreads();
    }

    #pragma unroll
    for (int mt = 0; mt < 2; mt++) {
        const int r0 = bm + wm * 32 + mt * 16 + g;
        #pragma unroll
        for (int nt = 0; nt < 8; nt++) {
            const int c0 = wn * 64 + nt * 8 + 2 * t4;
            #pragma unroll
            for (int half = 0; half < 2; half++) {
                int r = r0 + half * 8;
                size_t oidx = (size_t)(bb * SEQ + r) * DMODEL + hh * HDIM + c0;
                float va = d[mt][nt][half * 2], vb = d[mt][nt][half * 2 + 1];
                *(float2*)(O + oidx) = make_float2(va, vb);
                __nv_bfloat16 h0, l0, h1, l1;
                split_bf16(va, h0, l0);
                split_bf16(vb, h1, l1);
                Oh[oidx] = h0; Oh[oidx + 1] = h1;
                Ol[oidx] = l0; Ol[oidx + 1] = l1;
            }
        }
    }
}

// =================== fast LoRA-T: T_m = X @ A_m for up to 3 matrices ===================
// grid = MTOK/8, block = 256 (warp per row)
#define LCH 512
template <int NM>
__global__ __launch_bounds__(256)
void lora_fast(const float* __restrict__ X, int K,
               const float* __restrict__ A0, const float* __restrict__ A1,
               const float* __restrict__ A2,
               float* __restrict__ T0, float* __restrict__ T1, float* __restrict__ T2)
{
    __shared__ float At[16 * 513];
    const int tid  = threadIdx.x;
    const int lane = tid & 31;
    const int warp = tid >> 5;
    const int row  = blockIdx.x * 8 + warp;

    const float* As[3] = {A0, A1, A2};
    float acc[NM][16];
    #pragma unroll
    for (int m = 0; m < NM; m++)
        #pragma unroll
        for (int r = 0; r < 16; r++) acc[m][r] = 0.f;

    for (int k0 = 0; k0 < K; k0 += LCH) {
        float xs[16];
        #pragma unroll
        for (int j = 0; j < 16; j++)
            xs[j] = X[(size_t)row * K + k0 + lane + 32 * j];
        #pragma unroll
        for (int m = 0; m < NM; m++) {
            __syncthreads();
            const float* Am = As[m];
            for (int i = tid; i < 16 * LCH; i += 256) {
                int k = i >> 4, r = i & 15;
                At[r * 513 + k] = Am[(size_t)(k0 + k) * RLORA + r];
            }
            __syncthreads();
            #pragma unroll
            for (int j = 0; j < 16; j++) {
                int k = lane + 32 * j;
                float xv = xs[j];
                #pragma unroll
                for (int r = 0; r < 16; r++)
                    acc[m][r] += xv * At[r * 513 + k];
            }
        }
    }

    float* Ts[3] = {T0, T1, T2};
    #pragma unroll
    for (int m = 0; m < NM; m++) {
        #pragma unroll
        for (int r = 0; r < 16; r++) {
            float v = acc[m][r];
            #pragma unroll
            for (int o = 16; o > 0; o >>= 1) v += __shfl_xor_sync(0xffffffffu, v, o);
            if (lane == 0) Ts[m][row * RLORA + r] = v;
        }
    }
}

// ---------------- weight transpose + split ----------------
__global__ void transpose_split(const float* __restrict__ W,
                                __nv_bfloat16* __restrict__ Wh, __nv_bfloat16* __restrict__ Wl,
                                int Kd, int Nd)
{
    __shared__ float tile[32][33];
    int n0 = blockIdx.x * 32, k0 = blockIdx.y * 32;
    int x = threadIdx.x, y = threadIdx.y;
    #pragma unroll
    for (int dy = 0; dy < 32; dy += 8)
        tile[y + dy][x] = W[(size_t)(k0 + y + dy) * Nd + n0 + x];
    __syncthreads();
    #pragma unroll
    for (int dy = 0; dy < 32; dy += 8) {
        float v = tile[x][y + dy];
        size_t o = (size_t)(n0 + y + dy) * Kd + k0 + x;
        __nv_bfloat16 h, l;
        split_bf16(v, h, l);
        Wh[o] = h; Wl[o] = l;
    }
}

// ---------------- V transpose + split per head ----------------
__global__ void vsplit_t(const float* __restrict__ V,
                         __nv_bfloat16* __restrict__ Vth, __nv_bfloat16* __restrict__ Vtl)
{
    __shared__ float tile[32][33];
    int tok0 = blockIdx.x * 32, d0 = blockIdx.y * 32;
    int x = threadIdx.x, y = threadIdx.y;
    #pragma unroll
    for (int dy = 0; dy < 32; dy += 8)
        tile[y + dy][x] = V[(size_t)(tok0 + y + dy) * DMODEL + d0 + x];
    __syncthreads();
    int bb = tok0 >> 9, s0 = tok0 & 511;
    int hh = d0 >> 7, dd0 = d0 & 127;
    size_t zb = ((size_t)(bb * NHEAD + hh)) * HDIM * SEQ;
    #pragma unroll
    for (int dy = 0; dy < 32; dy += 8) {
        float v = tile[x][y + dy];
        size_t oidx = zb + (size_t)(dd0 + y + dy) * SEQ + s0 + x;
        __nv_bfloat16 h, l;
        split_bf16(v, h, l);
        Vth[oidx] = h; Vtl[oidx] = l;
    }
}

// ---------------- fused embed + rmsnorm(ln1 layer0) ----------------
__global__ void embed_rms(const int* __restrict__ idT, const int* __restrict__ idM,
                          const float* __restrict__ E, const float* __restrict__ W,
                          float* __restrict__ H, float* __restrict__ X,
                          __nv_bfloat16* __restrict__ Xh, __nv_bfloat16* __restrict__ Xl)
{
    __shared__ float red[256];
    int t  = blockIdx.x;
    int bb = t >> 9;
    int s  = t & 511;
    int id = (bb < 4) ? idT[bb * SEQ + s] : idM[(bb - 4) * SEQ + s];
    const float* src = E + (size_t)id * DMODEL;
    int tid = threadIdx.x;
    float vals[8];
    float ss = 0.f;
    #pragma unroll
    for (int j = 0; j < 8; j++) {
        float v = src[tid + 256 * j];
        vals[j] = v;
        ss += v * v;
    }
    red[tid] = ss; __syncthreads();
    for (int o = 128; o > 0; o >>= 1) {
        if (tid < o) red[tid] += red[tid + o];
        __syncthreads();
    }
    float scale = rsqrtf(red[0] / (float)DMODEL + 1e-6f);
    size_t base = (size_t)t * DMODEL;
    #pragma unroll
    for (int j = 0; j < 8; j++) {
        int idx = tid + 256 * j;
        float v = vals[j];
        H[base + idx] = v;
        float xv = v * scale * W[idx];
        X[base + idx] = xv;
        __nv_bfloat16 hh, ll;
        split_bf16(xv, hh, ll);
        Xh[base + idx] = hh; Xl[base + idx] = ll;
    }
}

// ---------------- rmsnorm ----------------
__global__ void rmsnorm_kernel(const float* __restrict__ H, const float* __restrict__ W,
                               float* __restrict__ X,
                               __nv_bfloat16* __restrict__ Xh, __nv_bfloat16* __restrict__ Xl)
{
    __shared__ float red[256];
    int row = blockIdx.x;
    const float* h = H + (size_t)row * DMODEL;
    int tid = threadIdx.x;
    float vals[8];
    float s = 0.f;
    #pragma unroll
    for (int j = 0; j < 8; j++) {
        float v = h[tid + 256 * j];
        vals[j] = v;
        s += v * v;
    }
    red[tid] = s; __syncthreads();
    for (int o = 128; o > 0; o >>= 1) {
        if (tid < o) red[tid] += red[tid + o];
        __syncthreads();
    }
    float scale = rsqrtf(red[0] / (float)DMODEL + 1e-6f);
    size_t base = (size_t)row * DMODEL;
    #pragma unroll
    for (int j = 0; j < 8; j++) {
        int idx = tid + 256 * j;
        float v = vals[j] * scale * W[idx];
        X[base + idx] = v;
        __nv_bfloat16 hh, ll;
        split_bf16(v, hh, ll);
        Xh[base + idx] = hh; Xl[base + idx] = ll;
    }
}

// ---------------- RoPE ----------------
__global__ void rope_kernel(const float* __restrict__ Q, const float* __restrict__ Kt,
                            __nv_bfloat16* __restrict__ Qh, __nv_bfloat16* __restrict__ Ql,
                            __nv_bfloat16* __restrict__ Kh, __nv_bfloat16* __restrict__ Kl)
{
    int i = blockIdx.x * blockDim.x + threadIdx.x;
    if (i >= MTOK * NHEAD * 64) return;
    int d = i & 63;
    int h = (i >> 6) & 15;
    int t = i >> 10;
    int s = t & 511;
    float freq = expf(-(float)d * (logf(10000.f) / 64.f));
    float ang = (float)s * freq;
    float sn, cs;
    sincosf(ang, &sn, &cs);
    size_t b0 = (size_t)t * DMODEL + h * HDIM + d;
    __nv_bfloat16 hh, ll;
    float x1 = Q[b0], x2 = Q[b0 + 64];
    float r1 = x1 * cs - x2 * sn;
    float r2 = x1 * sn + x2 * cs;
    split_bf16(r1, hh, ll); Qh[b0] = hh;      Ql[b0] = ll;
    split_bf16(r2, hh, ll); Qh[b0 + 64] = hh; Ql[b0 + 64] = ll;
    x1 = Kt[b0]; x2 = Kt[b0 + 64];
    r1 = x1 * cs - x2 * sn;
    r2 = x1 * sn + x2 * cs;
    split_bf16(r1, hh, ll); Kh[b0] = hh;      Kl[b0] = ll;
    split_bf16(r2, hh, ll); Kh[b0 + 64] = hh; Kl[b0 + 64] = ll;
}

// ---------------- row softmax ----------------
__global__ void softmax_kernel(const float* __restrict__ S_,
                               __nv_bfloat16* __restrict__ Ph, __nv_bfloat16* __restrict__ Pl)
{
    __shared__ float red[256];
    const float* p = S_ + (size_t)blockIdx.x * SEQ;
    int t = threadIdx.x;
    float v0 = p[t], v1 = p[t + 256];
    float m = fmaxf(v0, v1);
    red[t] = m; __syncthreads();
    for (int o = 128; o > 0; o >>= 1) {
        if (t < o) red[t] = fmaxf(red[t], red[t + o]);
        __syncthreads();
    }
    m = red[0]; __syncthreads();
    float e0 = expf(v0 - m), e1 = expf(v1 - m);
    red[t] = e0 + e1; __syncthreads();
    for (int o = 128; o > 0; o >>= 1) {
        if (t < o) red[t] += red[t + o];
        __syncthreads();
    }
    float inv = 1.f / red[0];
    size_t base = (size_t)blockIdx.x * SEQ;
    __nv_bfloat16 hh, ll;
    split_bf16(e0 * inv, hh, ll); Ph[base + t] = hh;       Pl[base + t] = ll;
    split_bf16(e1 * inv, hh, ll); Ph[base + t + 256] = hh; Pl[base + t + 256] = ll;
}

// ---------------- swiglu ----------------
__global__ void swiglu_kernel(float* __restrict__ G, const float* __restrict__ U,
                              __nv_bfloat16* __restrict__ Gh, __nv_bfloat16* __restrict__ Gl)
{
    size_t i = (size_t)blockIdx.x * blockDim.x + threadIdx.x;
    if (i >= (size_t)MTOK * FFDIM) return;
    float g = G[i];
    float sig = 1.f / (1.f + expf(-g));
    float v = g * sig * U[i];
    G[i] = v;
    __nv_bfloat16 hh, ll;
    split_bf16(v, hh, ll);
    Gh[i] = hh; Gl[i] = ll;
}

// ---------------- reps extraction + L2 normalize ----------------
__global__ void reps_kernel(const float* __restrict__ X, const int* __restrict__ mT,
                            const int* __restrict__ mM, float* __restrict__ R_)
{
    __shared__ int ired[256];
    __shared__ float fred[256];
    __shared__ int sidx;
    int bb = blockIdx.x;
    const int* mask = (bb < 4) ? mT : mM;
    int b = bb & 3;
    int t = threadIdx.x;
    int s = 0;
    for (int j = t; j < SEQ; j += 256) s += mask[b * SEQ + j];
    ired[t] = s; __syncthreads();
    for (int o = 128; o > 0; o >>= 1) {
        if (t < o) ired[t] += ired[t + o];
        __syncthreads();
    }
    if (t == 0) {
        int last = mask[0 * SEQ + 511] + mask[1 * SEQ + 511] +
                   mask[2 * SEQ + 511] + mask[3 * SEQ + 511];
        sidx = (last == BATCH) ? (SEQ - 1) : (ired[0] - 1);
    }
    __syncthreads();
    const float* row = X + (size_t)(bb * SEQ + sidx) * DMODEL;
    float ss = 0.f;
    for (int j = t; j < DMODEL; j += 256) { float v = row[j]; ss += v * v; }
    fred[t] = ss; __syncthreads();
    for (int o = 128; o > 0; o >>= 1) {
        if (t < o) fred[t] += fred[t + o];
        __syncthreads();
    }
    float inv = 1.f / sqrtf(fred[0]);
    for (int j = t; j < DMODEL; j += 256) R_[bb * DMODEL + j] = row[j] * inv;
}

// ---------------- contrastive loss ----------------
__global__ void loss_kernel(const float* __restrict__ R_, float* __restrict__ out)
{
    __shared__ float sims[16];
    int tid = threadIdx.x;
    int warp = tid >> 5, lane = tid & 31;
    for (int p = warp; p < 16; p += 8) {
        int i = p >> 2, j = p & 3;
        const float* a = R_ + i * DMODEL;
        const float* bR = R_ + (4 + j) * DMODEL;
        float d = 0.f;
        for (int k2 = lane; k2 < DMODEL; k2 += 32) d += a[k2] * bR[k2];
        #pragma unroll
        for (int o = 16; o > 0; o >>= 1) d += __shfl_xor_sync(0xffffffff, d, o);
        if (lane == 0) sims[p] = d * 20.f;
    }
    __syncthreads();
    if (tid == 0) {
        float loss = 0.f;
        for (int i = 0; i < 4; i++) {
            float m = -1e30f;
            for (int j = 0; j < 4; j++) m = fmaxf(m, sims[i * 4 + j]);
            float sum = 0.f;
            for (int j = 0; j < 4; j++) sum += expf(sims[i * 4 + j] - m);
            loss += (logf(sum) + m) - sims[i * 4 + i];
        }
        out[0] = loss * 0.25f;
    }
}

// ---------------- host driver ----------------
static void* symaddr_raw(const void* sym)
{
    void* p = nullptr;
    cudaGetSymbolAddress(&p, sym);
    return p;
}

extern "C" void kernel_launch(void* const* d_in, const int* in_sizes, int n_in,
                              void* d_out, int out_size)
{
    const int*   idT = (const int*)d_in[0];
    const int*   mT  = (const int*)d_in[1];
    const int*   idM = (const int*)d_in[2];
    const int*   mM  = (const int*)d_in[3];
    const float* emb = (const float*)d_in[4];
    const float* ln1 = (const float*)d_in[5];
    const float* ln2 = (const float*)d_in[6];
    const float* lnf = (const float*)d_in[7];
    const float* Wq = (const float*)d_in[8],  *Aq = (const float*)d_in[9],  *Bq = (const float*)d_in[10];
    const float* Wk = (const float*)d_in[11], *Ak = (const float*)d_in[12], *Bk = (const float*)d_in[13];
    const float* Wv = (const float*)d_in[14], *Av = (const float*)d_in[15], *Bv = (const float*)d_in[16];
    const float* Wo = (const float*)d_in[17], *Ao = (const float*)d_in[18], *Bo = (const float*)d_in[19];
    const float* Wg = (const float*)d_in[20], *Ag = (const float*)d_in[21], *Bg = (const float*)d_in[22];
    const float* Wu = (const float*)d_in[23], *Au = (const float*)d_in[24], *Bu = (const float*)d_in[25];
    const float* Wd = (const float*)d_in[26], *Ad = (const float*)d_in[27], *Bd = (const float*)d_in[28];

    float* h  = (float*)symaddr_raw(g_h);
    float* x  = (float*)symaddr_raw(g_x);
    float* q  = (float*)symaddr_raw(g_q);
    float* k  = (float*)symaddr_raw(g_k);
    float* v  = (float*)symaddr_raw(g_v);
    float* o  = (float*)symaddr_raw(g_o);
    float* sc = (float*)symaddr_raw(g_sc);
    float* gg = (float*)symaddr_raw(g_gate);
    float* uu = (float*)symaddr_raw(g_up);
    float* t0 = (float*)symaddr_raw(g_t);
    float* t1 = t0 + MTOK * RLORA;
    float* t2 = t0 + 2 * MTOK * RLORA;
    float* rp = (float*)symaddr_raw(g_reps);
    __nv_bfloat16* ah  = (__nv_bfloat16*)symaddr_raw(g_ah);
    __nv_bfloat16* al  = (__nv_bfloat16*)symaddr_raw(g_al);
    __nv_bfloat16* wh  = (__nv_bfloat16*)symaddr_raw(g_wh);
    __nv_bfloat16* wl  = (__nv_bfloat16*)symaddr_raw(g_wl);
    __nv_bfloat16* qh  = (__nv_bfloat16*)symaddr_raw(g_qh);
    __nv_bfloat16* ql  = (__nv_bfloat16*)symaddr_raw(g_ql);
    __nv_bfloat16* kh  = (__nv_bfloat16*)symaddr_raw(g_kh);
    __nv_bfloat16* kl  = (__nv_bfloat16*)symaddr_raw(g_kl);
    __nv_bfloat16* ph  = (__nv_bfloat16*)symaddr_raw(g_ph);
    __nv_bfloat16* pl  = (__nv_bfloat16*)symaddr_raw(g_pl);
    __nv_bfloat16* vth = (__nv_bfloat16*)symaddr_raw(g_vth);
    __nv_bfloat16* vtl = (__nv_bfloat16*)symaddr_raw(g_vtl);

    cudaFuncSetAttribute(gemm_tc,    cudaFuncAttributeMaxDynamicSharedMemorySize, GSMEM);
    cudaFuncSetAttribute(scores_mma, cudaFuncAttributeMaxDynamicSharedMemorySize, SCSM);
    cudaFuncSetAttribute(attnv_mma,  cudaFuncAttributeMaxDynamicSharedMemorySize, AVSM);

    const size_t DD = (size_t)DMODEL * DMODEL;
    const size_t DF = (size_t)DMODEL * FFDIM;
    const size_t LSTR = 4 * DD + 3 * DF;
    const dim3 tD(DMODEL / 32, DMODEL / 32), tB(32, 8);
    const dim3 tF(FFDIM / 32, DMODEL / 32);
    const dim3 tFd(DMODEL / 32, FFDIM / 32);
    const dim3 gD(DMODEL / 128, MTOK / 128);
    const dim3 gF(FFDIM / 128, MTOK / 128);

    // ---- prologue: gemm_tc at launch slots 3 and 5 for ncu ----
    transpose_split<<<tD, tB>>>(Wq, wh, wl, DMODEL, DMODEL);                          // 0
    embed_rms<<<MTOK, 256>>>(idT, idM, emb, ln1, h, x, ah, al);                       // 1
    lora_fast<3><<<MTOK / 8, 256>>>(x, DMODEL, Aq, Ak, Av, t0, t1, t2);               // 2
    gemm_tc<<<gD, 256, GSMEM>>>(ah, al, wh, wl, q, MTOK, DMODEL, DMODEL, t0, Bq, 0);  // 3
    transpose_split<<<tD, tB>>>(Wk, wh + DD, wl + DD, DMODEL, DMODEL);                // 4
    gemm_tc<<<gD, 256, GSMEM>>>(ah, al, wh + DD, wl + DD, k, MTOK, DMODEL, DMODEL, t1, Bk, 0); // 5
    transpose_split<<<tD, tB>>>(Wv, wh + 2 * DD, wl + 2 * DD, DMODEL, DMODEL);        // 6
    gemm_tc<<<gD, 256, GSMEM>>>(ah, al, wh + 2 * DD, wl + 2 * DD, v, MTOK, DMODEL, DMODEL, t2, Bv, 0); // 7

    // remaining transposes
    transpose_split<<<tD, tB>>>(Wo, wh + 3 * DD, wl + 3 * DD, DMODEL, DMODEL);
    transpose_split<<<tF, tB>>>(Wg, wh + 4 * DD, wl + 4 * DD, DMODEL, FFDIM);
    transpose_split<<<tF, tB>>>(Wu, wh + 4 * DD + DF, wl + 4 * DD + DF, DMODEL, FFDIM);
    transpose_split<<<tFd, tB>>>(Wd, wh + 4 * DD + 2 * DF, wl + 4 * DD + 2 * DF, FFDIM, DMODEL);
    for (int l = 1; l < LAYERS; l++) {
        size_t off = (size_t)l * LSTR;
        transpose_split<<<tD, tB>>>(Wq + l * DD, wh + off,          wl + off,          DMODEL, DMODEL);
        transpose_split<<<tD, tB>>>(Wk + l * DD, wh + off + DD,     wl + off + DD,     DMODEL, DMODEL);
        transpose_split<<<tD, tB>>>(Wv + l * DD, wh + off + 2 * DD, wl + off + 2 * DD, DMODEL, DMODEL);
        transpose_split<<<tD, tB>>>(Wo + l * DD, wh + off + 3 * DD, wl + off + 3 * DD, DMODEL, DMODEL);
        transpose_split<<<tF, tB>>>(Wg + l * DF, wh + off + 4 * DD, wl + off + 4 * DD, DMODEL, FFDIM);
        transpose_split<<<tF, tB>>>(Wu + l * DF, wh + off + 4 * DD + DF, wl + off + 4 * DD + DF, DMODEL, FFDIM);
        transpose_split<<<tFd, tB>>>(Wd + l * DF, wh + off + 4 * DD + 2 * DF, wl + off + 4 * DD + 2 * DF, FFDIM, DMODEL);
    }

    for (int l = 0; l < LAYERS; l++) {
        size_t off = (size_t)l * LSTR;
        const __nv_bfloat16 *Wq_h = wh + off,               *Wq_l = wl + off;
        const __nv_bfloat16 *Wk_h = wh + off + DD,          *Wk_l = wl + off + DD;
        const __nv_bfloat16 *Wv_h = wh + off + 2 * DD,      *Wv_l = wl + off + 2 * DD;
        const __nv_bfloat16 *Wo_h = wh + off + 3 * DD,      *Wo_l = wl + off + 3 * DD;
        const __nv_bfloat16 *Wg_h = wh + off + 4 * DD,      *Wg_l = wl + off + 4 * DD;
        const __nv_bfloat16 *Wu_h = wh + off + 4 * DD + DF, *Wu_l = wl + off + 4 * DD + DF;
        const __nv_bfloat16 *Wd_h = wh + off + 4 * DD + 2 * DF, *Wd_l = wl + off + 4 * DD + 2 * DF;
        const float* Bq_l = Bq + (size_t)l * RLORA * DMODEL;
        const float* Bk_l = Bk + (size_t)l * RLORA * DMODEL;
        const float* Bv_l = Bv + (size_t)l * RLORA * DMODEL;
        const float* Bo_l = Bo + (size_t)l * RLORA * DMODEL;
        const float* Bg_l = Bg + (size_t)l * RLORA * FFDIM;
        const float* Bu_l = Bu + (size_t)l * RLORA * FFDIM;
        const float* Bd_l = Bd + (size_t)l * RLORA * DMODEL;

        if (l > 0) {
            rmsnorm_kernel<<<MTOK, 256>>>(h, ln1 + l * DMODEL, x, ah, al);
            lora_fast<3><<<MTOK / 8, 256>>>(x, DMODEL, Aq + l * DMODEL * RLORA,
                                            Ak + l * DMODEL * RLORA, Av + l * DMODEL * RLORA,
                                            t0, t1, t2);
            gemm_tc<<<gD, 256, GSMEM>>>(ah, al, Wq_h, Wq_l, q, MTOK, DMODEL, DMODEL, t0, Bq_l, 0);
            gemm_tc<<<gD, 256, GSMEM>>>(ah, al, Wk_h, Wk_l, k, MTOK, DMODEL, DMODEL, t1, Bk_l, 0);
            gemm_tc<<<gD, 256, GSMEM>>>(ah, al, Wv_h, Wv_l, v, MTOK, DMODEL, DMODEL, t2, Bv_l, 0);
        }

        rope_kernel<<<(MTOK * NHEAD * 64 + 255) / 256, 256>>>(q, k, qh, ql, kh, kl);
        vsplit_t<<<dim3(MTOK / 32, DMODEL / 32), tB>>>(v, vth, vtl);

        scores_mma<<<dim3(4, 4, BB * NHEAD), 256, SCSM>>>(qh, ql, kh, kl, mT, mM, sc);
        softmax_kernel<<<BB * NHEAD * SEQ, 256>>>(sc, ph, pl);
        attnv_mma<<<dim3(1, 4, BB * NHEAD), 256, AVSM>>>(ph, pl, vth, vtl, o, ah, al);

        lora_fast<1><<<MTOK / 8, 256>>>(o, DMODEL, Ao + (size_t)l * DMODEL * RLORA,
                                        nullptr, nullptr, t0, nullptr, nullptr);
        gemm_tc<<<gD, 256, GSMEM>>>(ah, al, Wo_h, Wo_l, h, MTOK, DMODEL, DMODEL, t0, Bo_l, 1);

        rmsnorm_kernel<<<MTOK, 256>>>(h, ln2 + l * DMODEL, x, ah, al);
        lora_fast<2><<<MTOK / 8, 256>>>(x, DMODEL, Ag + (size_t)l * DMODEL * RLORA,
                                        Au + (size_t)l * DMODEL * RLORA, nullptr,
                                        t0, t1, nullptr);
        gemm_tc<<<gF, 256, GSMEM>>>(ah, al, Wg_h, Wg_l, gg, MTOK, FFDIM, DMODEL, t0, Bg_l, 0);
        gemm_tc<<<gF, 256, GSMEM>>>(ah, al, Wu_h, Wu_l, uu, MTOK, FFDIM, DMODEL, t1, Bu_l, 0);

        swiglu_kernel<<<(int)(((size_t)MTOK * FFDIM + 255) / 256), 256>>>(gg, uu, ah, al);

        lora_fast<1><<<MTOK / 8, 256>>>(gg, FFDIM, Ad + (size_t)l * FFDIM * RLORA,
                                        nullptr, nullptr, t0, nullptr, nullptr);
        gemm_tc<<<gD, 256, GSMEM>>>(ah, al, Wd_h, Wd_l, h, MTOK, DMODEL, FFDIM, t0, Bd_l, 1);
    }

    rmsnorm_kernel<<<MTOK, 256>>>(h, lnf, x, ah, al);
    reps_kernel<<<BB, 256>>>(x, mT, mM, rp);
    loss_kernel<<<1, 256>>>(rp, (float*)d_out);
}

// round 8
// speedup vs baseline: 4.3025x; 1.1374x over previous
#include <cuda_runtime.h>
#include <cuda_bf16.h>
#include <math.h>
#include <stdint.h>

// Problem constants
#define LAYERS 2
#define DMODEL 2048
#define NHEAD  16
#define HDIM   128
#define FFDIM  5632
#define RLORA  16
#define BATCH  4
#define SEQ    512
#define BB     8
#define MTOK   (BB*SEQ)
#define LORA_SCALE 1.4f
#define SCALE_QK 0.08838834764831845f

// ---------------- scratch ----------------
__device__ float g_h   [MTOK * DMODEL];
__device__ float g_x   [MTOK * DMODEL];
__device__ float g_q   [MTOK * DMODEL];
__device__ float g_k   [MTOK * DMODEL];
__device__ float g_v   [MTOK * DMODEL];
__device__ float g_o   [MTOK * DMODEL];
__device__ float g_sc  [BB * NHEAD * SEQ * SEQ];
__device__ float g_gate[MTOK * FFDIM];
__device__ float g_up  [MTOK * FFDIM];
__device__ float g_t   [3 * MTOK * RLORA];
__device__ float g_reps[BB * DMODEL];
__device__ __nv_bfloat16 g_ah[MTOK * FFDIM];
__device__ __nv_bfloat16 g_al[MTOK * FFDIM];
__device__ __nv_bfloat16 g_wh[2 * (4 * DMODEL * DMODEL + 3 * DMODEL * FFDIM)];
__device__ __nv_bfloat16 g_wl[2 * (4 * DMODEL * DMODEL + 3 * DMODEL * FFDIM)];
__device__ __nv_bfloat16 g_qh[MTOK * DMODEL];
__device__ __nv_bfloat16 g_ql[MTOK * DMODEL];
__device__ __nv_bfloat16 g_kh[MTOK * DMODEL];
__device__ __nv_bfloat16 g_kl[MTOK * DMODEL];
__device__ __nv_bfloat16 g_ph[BB * NHEAD * SEQ * SEQ];
__device__ __nv_bfloat16 g_pl[BB * NHEAD * SEQ * SEQ];
__device__ __nv_bfloat16 g_vth[MTOK * DMODEL];
__device__ __nv_bfloat16 g_vtl[MTOK * DMODEL];

// =================== helpers ===================
__device__ __forceinline__ uint32_t smem_u32(const void* p) {
    uint32_t a;
    asm("{ .reg .u64 t; cvta.to.shared.u64 t, %1; cvt.u32.u64 %0, t; }" : "=r"(a) : "l"(p));
    return a;
}
__device__ __forceinline__ void cp_async16(uint32_t saddr, const void* gptr) {
    asm volatile("cp.async.cg.shared.global [%0], [%1], 16;" :: "r"(saddr), "l"(gptr));
}
__device__ __forceinline__ void cp_commit() { asm volatile("cp.async.commit_group;"); }
template <int NWAIT>
__device__ __forceinline__ void cp_wait() {
    asm volatile("cp.async.wait_group %0;" :: "n"(NWAIT));
}
__device__ __forceinline__ void mma16(float* d, const uint32_t* a, uint32_t b0, uint32_t b1) {
    asm volatile(
        "mma.sync.aligned.m16n8k16.row.col.f32.bf16.bf16.f32 "
        "{%0,%1,%2,%3}, {%4,%5,%6,%7}, {%8,%9}, {%0,%1,%2,%3};"
        : "+f"(d[0]), "+f"(d[1]), "+f"(d[2]), "+f"(d[3])
        : "r"(a[0]), "r"(a[1]), "r"(a[2]), "r"(a[3]), "r"(b0), "r"(b1));
}
__device__ __forceinline__ void ldm_x4(uint32_t* r, uint32_t addr) {
    asm volatile("ldmatrix.sync.aligned.m8n8.x4.shared.b16 {%0,%1,%2,%3}, [%4];"
                 : "=r"(r[0]), "=r"(r[1]), "=r"(r[2]), "=r"(r[3]) : "r"(addr));
}
__device__ __forceinline__ void split_bf16(float v, __nv_bfloat16& h, __nv_bfloat16& l) {
    h = __float2bfloat16(v);
    l = __float2bfloat16(v - __bfloat162float(h));
}

#define SMSB   80
#define ARRB   10240
#define STGB   40960
#define LA_OFF 81920
#define LB_OFF 88064
#define GSMEM  94208
#define SCSM   82432
#define AVSM   81920

#define COMPUTE_STAGE(stbase)                                                     \
    _Pragma("unroll")                                                             \
    for (int ks = 0; ks < 32; ks += 16) {                                         \
        uint32_t ahf[2][4], alf[2][4];                                            \
        {                                                                         \
            int grp = lane >> 3, r8 = lane & 7;                                   \
            int mm = (grp & 1) * 8 + r8;                                          \
            int koff = (grp >> 1) * 8;                                            \
            _Pragma("unroll")                                                     \
            for (int mt = 0; mt < 2; mt++) {                                      \
                uint32_t ad = (stbase) + (wm * 32 + mt * 16 + mm) * SMSB + (ks + koff) * 2; \
                ldm_x4(ahf[mt], ad);                                              \
                ldm_x4(alf[mt], ad + ARRB);                                       \
            }                                                                     \
        }                                                                         \
        _Pragma("unroll")                                                         \
        for (int np = 0; np < 4; np++) {                                          \
            int grp = lane >> 3, r8 = lane & 7;                                   \
            int nn = (grp >> 1) * 8 + r8;                                         \
            int koff = (grp & 1) * 8;                                             \
            uint32_t bd = (stbase) + 2 * ARRB + (wn * 64 + np * 16 + nn) * SMSB + (ks + koff) * 2; \
            uint32_t bh[4], bl[4];                                                \
            ldm_x4(bh, bd);                                                       \
            ldm_x4(bl, bd + ARRB);                                                \
            _Pragma("unroll")                                                     \
            for (int mt = 0; mt < 2; mt++) {                                      \
                mma16(d[mt][np * 2],     ahf[mt], bh[0], bh[1]);                  \
                mma16(d[mt][np * 2],     ahf[mt], bl[0], bl[1]);                  \
                mma16(d[mt][np * 2],     alf[mt], bh[0], bh[1]);                  \
                mma16(d[mt][np * 2 + 1], ahf[mt], bh[2], bh[3]);                  \
                mma16(d[mt][np * 2 + 1], ahf[mt], bl[2], bl[3]);                  \
                mma16(d[mt][np * 2 + 1], alf[mt], bh[2], bh[3]);                  \
            }                                                                     \
        }                                                                         \
    }

#define ISSUE_STAGE(kt, aH, aL, bH, bL, LDA, LDB)                                 \
    {                                                                             \
        const int k0_ = (kt) << 5;                                                \
        const int buf_ = (kt) & 1;                                                \
        _Pragma("unroll")                                                         \
        for (int j = 0; j < 8; j++) {                                             \
            int e = tid + j * 256;                                                \
            int arr = e >> 9;                                                     \
            int i = e & 511;                                                      \
            int row = i >> 2;                                                     \
            int cg = (i & 3) << 3;                                                \
            const __nv_bfloat16* gp;                                              \
            if (arr == 0)      gp = (aH) + (size_t)row * (LDA) + k0_ + cg;        \
            else if (arr == 1) gp = (aL) + (size_t)row * (LDA) + k0_ + cg;        \
            else if (arr == 2) gp = (bH) + (size_t)row * (LDB) + k0_ + cg;        \
            else               gp = (bL) + (size_t)row * (LDB) + k0_ + cg;        \
            cp_async16(sb + buf_ * STGB + arr * ARRB + row * SMSB + cg * 2, gp);  \
        }                                                                         \
        cp_commit();                                                              \
    }

// =================== main GEMM with fused LoRA + residual ===================
__global__ __launch_bounds__(256, 2)
void gemm_tc(const __nv_bfloat16* __restrict__ Agh, const __nv_bfloat16* __restrict__ Agl,
             const __nv_bfloat16* __restrict__ Wgh, const __nv_bfloat16* __restrict__ Wgl,
             float* __restrict__ C, int M, int N, int K,
             const float* __restrict__ lT, const float* __restrict__ lB, int accum)
{
    extern __shared__ char smc[];
    const int tid  = threadIdx.x;
    const int wid  = tid >> 5;
    const int lane = tid & 31;
    const int t4   = lane & 3;
    const int g    = lane >> 2;
    const int wm   = wid >> 1;
    const int wn   = wid & 1;
    const int bm   = blockIdx.y * 128;
    const int bn   = blockIdx.x * 128;
    const uint32_t sb = smem_u32(smc);

    __nv_bfloat16* la = (__nv_bfloat16*)(smc + LA_OFF);
    __nv_bfloat16* lb = (__nv_bfloat16*)(smc + LB_OFF);
    for (int i = tid; i < 2048; i += 256) {
        int row = i >> 4, r = i & 15;
        la[row * 24 + r] = __float2bfloat16(LORA_SCALE * lT[(size_t)(bm + row) * RLORA + r]);
        lb[row * 24 + r] = __float2bfloat16(lB[(size_t)r * N + bn + row]);
    }

    float d[2][8][4];
    #pragma unroll
    for (int mt = 0; mt < 2; mt++)
        #pragma unroll
        for (int nt = 0; nt < 8; nt++)
            #pragma unroll
            for (int j = 0; j < 4; j++) d[mt][nt][j] = 0.f;

    const __nv_bfloat16* aH = Agh + (size_t)bm * K;
    const __nv_bfloat16* aL = Agl + (size_t)bm * K;
    const __nv_bfloat16* bH = Wgh + (size_t)bn * K;
    const __nv_bfloat16* bL = Wgl + (size_t)bn * K;

    const int nk = K >> 5;
    ISSUE_STAGE(0, aH, aL, bH, bL, K, K);
    for (int kt = 0; kt < nk; kt++) {
        if (kt + 1 < nk) { ISSUE_STAGE(kt + 1, aH, aL, bH, bL, K, K); cp_wait<1>(); }
        else             cp_wait<0>();
        __syncthreads();
        const uint32_t st = sb + (kt & 1) * STGB;
        COMPUTE_STAGE(st)
        __syncthreads();
    }

    // LoRA tail (hi-only, K=16)
    {
        uint32_t a[2][4];
        #pragma unroll
        for (int mt = 0; mt < 2; mt++) {
            const char* pa = (const char*)la + (wm * 32 + mt * 16 + g) * 48 + t4 * 4;
            a[mt][0] = *(const uint32_t*)(pa);
            a[mt][1] = *(const uint32_t*)(pa + 8 * 48);
            a[mt][2] = *(const uint32_t*)(pa + 16);
            a[mt][3] = *(const uint32_t*)(pa + 8 * 48 + 16);
        }
        #pragma unroll
        for (int nt = 0; nt < 8; nt++) {
            const char* pb = (const char*)lb + (wn * 64 + nt * 8 + g) * 48 + t4 * 4;
            uint32_t b0 = *(const uint32_t*)(pb);
            uint32_t b1 = *(const uint32_t*)(pb + 16);
            #pragma unroll
            for (int mt = 0; mt < 2; mt++) mma16(d[mt][nt], a[mt], b0, b1);
        }
    }

    #pragma unroll
    for (int mt = 0; mt < 2; mt++) {
        const int r0 = bm + wm * 32 + mt * 16 + g;
        #pragma unroll
        for (int nt = 0; nt < 8; nt++) {
            const int c0 = bn + wn * 64 + nt * 8 + 2 * t4;
            float2 v0 = make_float2(d[mt][nt][0], d[mt][nt][1]);
            float2 v1 = make_float2(d[mt][nt][2], d[mt][nt][3]);
            float* p0 = C + (size_t)r0 * N + c0;
            float* p1 = C + (size_t)(r0 + 8) * N + c0;
            if (accum) {
                float2 o0 = *(const float2*)p0;
                float2 o1 = *(const float2*)p1;
                v0.x += o0.x; v0.y += o0.y;
                v1.x += o1.x; v1.y += o1.y;
            }
            *(float2*)p0 = v0;
            *(float2*)p1 = v1;
        }
    }
}

// =================== scores ===================
__global__ __launch_bounds__(256, 2)
void scores_mma(const __nv_bfloat16* __restrict__ Qh, const __nv_bfloat16* __restrict__ Ql,
                const __nv_bfloat16* __restrict__ Kh, const __nv_bfloat16* __restrict__ Kl,
                const int* __restrict__ mT, const int* __restrict__ mM,
                float* __restrict__ S_)
{
    extern __shared__ char smc[];
    const int tid  = threadIdx.x;
    const int wid  = tid >> 5;
    const int lane = tid & 31;
    const int t4   = lane & 3;
    const int g    = lane >> 2;
    const int wm   = wid >> 1;
    const int wn   = wid & 1;
    const int z    = blockIdx.z;
    const int bb   = z >> 4;
    const int hh   = z & 15;
    const int bm   = blockIdx.y * 128;
    const int bn   = blockIdx.x * 128;
    const uint32_t sb = smem_u32(smc);
    int* msk = (int*)(smc + 2 * STGB);

    const int* mask = (bb < 4) ? (mT + bb * SEQ) : (mM + (bb - 4) * SEQ);
    if (tid < 128) msk[tid] = mask[bn + tid];

    float* Sbase = S_ + (size_t)z * SEQ * SEQ;

    if (bn > bm) {
        __syncthreads();
        for (int i = tid; i < 128 * 128; i += 256) {
            int r = i >> 7, c = i & 127;
            Sbase[(size_t)(bm + r) * SEQ + bn + c] = -1e9f;
        }
        return;
    }

    float d[2][8][4];
    #pragma unroll
    for (int mt = 0; mt < 2; mt++)
        #pragma unroll
        for (int nt = 0; nt < 8; nt++)
            #pragma unroll
            for (int j = 0; j < 4; j++) d[mt][nt][j] = 0.f;

    const __nv_bfloat16* aH = Qh + (size_t)(bb * SEQ + bm) * DMODEL + hh * HDIM;
    const __nv_bfloat16* aL = Ql + (size_t)(bb * SEQ + bm) * DMODEL + hh * HDIM;
    const __nv_bfloat16* bH = Kh + (size_t)(bb * SEQ + bn) * DMODEL + hh * HDIM;
    const __nv_bfloat16* bL = Kl + (size_t)(bb * SEQ + bn) * DMODEL + hh * HDIM;

    const int nk = HDIM >> 5;
    ISSUE_STAGE(0, aH, aL, bH, bL, DMODEL, DMODEL);
    for (int kt = 0; kt < nk; kt++) {
        if (kt + 1 < nk) { ISSUE_STAGE(kt + 1, aH, aL, bH, bL, DMODEL, DMODEL); cp_wait<1>(); }
        else             cp_wait<0>();
        __syncthreads();
        const uint32_t st = sb + (kt & 1) * STGB;
        COMPUTE_STAGE(st)
        __syncthreads();
    }

    #pragma unroll
    for (int mt = 0; mt < 2; mt++) {
        const int r0 = wm * 32 + mt * 16 + g;
        #pragma unroll
        for (int nt = 0; nt < 8; nt++) {
            const int c0 = wn * 64 + nt * 8 + 2 * t4;
            #pragma unroll
            for (int half = 0; half < 2; half++) {
                int r = r0 + half * 8;
                int sq = bm + r, sk0 = bn + c0;
                float va = d[mt][nt][half * 2], vb = d[mt][nt][half * 2 + 1];
                bool ok0 = (sk0 <= sq) && (msk[c0] > 0);
                bool ok1 = (sk0 + 1 <= sq) && (msk[c0 + 1] > 0);
                float2 out;
                out.x = va * SCALE_QK + (ok0 ? 0.f : -1e9f);
                out.y = vb * SCALE_QK + (ok1 ? 0.f : -1e9f);
                *(float2*)(Sbase + (size_t)sq * SEQ + sk0) = out;
            }
        }
    }
}

// =================== attnv (causal-truncated K loop) ===================
__global__ __launch_bounds__(256, 2)
void attnv_mma(const __nv_bfloat16* __restrict__ Ph, const __nv_bfloat16* __restrict__ Pl,
               const __nv_bfloat16* __restrict__ Vth, const __nv_bfloat16* __restrict__ Vtl,
               float* __restrict__ O,
               __nv_bfloat16* __restrict__ Oh, __nv_bfloat16* __restrict__ Ol)
{
    extern __shared__ char smc[];
    const int tid  = threadIdx.x;
    const int wid  = tid >> 5;
    const int lane = tid & 31;
    const int t4   = lane & 3;
    const int g    = lane >> 2;
    const int wm   = wid >> 1;
    const int wn   = wid & 1;
    const int z    = blockIdx.z;
    const int bb   = z >> 4;
    const int hh   = z & 15;
    const int bm   = blockIdx.y * 128;
    const uint32_t sb = smem_u32(smc);

    float d[2][8][4];
    #pragma unroll
    for (int mt = 0; mt < 2; mt++)
        #pragma unroll
        for (int nt = 0; nt < 8; nt++)
            #pragma unroll
            for (int j = 0; j < 4; j++) d[mt][nt][j] = 0.f;

    const __nv_bfloat16* aH = Ph + ((size_t)z * SEQ + bm) * SEQ;
    const __nv_bfloat16* aL = Pl + ((size_t)z * SEQ + bm) * SEQ;
    const __nv_bfloat16* bH = Vth + (size_t)z * HDIM * SEQ;
    const __nv_bfloat16* bL = Vtl + (size_t)z * HDIM * SEQ;

    // causal: P[bm..bm+127][k] == 0 for k >= bm+128 -> only (bm>>5)+4 stages
    const int nk = (bm >> 5) + 4;
    ISSUE_STAGE(0, aH, aL, bH, bL, SEQ, SEQ);
    for (int kt = 0; kt < nk; kt++) {
        if (kt + 1 < nk) { ISSUE_STAGE(kt + 1, aH, aL, bH, bL, SEQ, SEQ); cp_wait<1>(); }
        else             cp_wait<0>();
        __syncthreads();
        const uint32_t st = sb + (kt & 1) * STGB;
        COMPUTE_STAGE(st)
        __syncthreads();
    }

    #pragma unroll
    for (int mt = 0; mt < 2; mt++) {
        const int r0 = bm + wm * 32 + mt * 16 + g;
        #pragma unroll
        for (int nt = 0; nt < 8; nt++) {
            const int c0 = wn * 64 + nt * 8 + 2 * t4;
            #pragma unroll
            for (int half = 0; half < 2; half++) {
                int r = r0 + half * 8;
                size_t oidx = (size_t)(bb * SEQ + r) * DMODEL + hh * HDIM + c0;
                float va = d[mt][nt][half * 2], vb = d[mt][nt][half * 2 + 1];
                *(float2*)(O + oidx) = make_float2(va, vb);
                __nv_bfloat16 h0, l0, h1, l1;
                split_bf16(va, h0, l0);
                split_bf16(vb, h1, l1);
                Oh[oidx] = h0; Oh[oidx + 1] = h1;
                Ol[oidx] = l0; Ol[oidx + 1] = l1;
            }
        }
    }
}

// =================== fast LoRA-T ===================
#define LCH 512
template <int NM>
__global__ __launch_bounds__(256)
void lora_fast(const float* __restrict__ X, int K,
               const float* __restrict__ A0, const float* __restrict__ A1,
               const float* __restrict__ A2,
               float* __restrict__ T0, float* __restrict__ T1, float* __restrict__ T2)
{
    __shared__ float At[16 * 513];
    const int tid  = threadIdx.x;
    const int lane = tid & 31;
    const int warp = tid >> 5;
    const int row  = blockIdx.x * 8 + warp;

    const float* As[3] = {A0, A1, A2};
    float acc[NM][16];
    #pragma unroll
    for (int m = 0; m < NM; m++)
        #pragma unroll
        for (int r = 0; r < 16; r++) acc[m][r] = 0.f;

    for (int k0 = 0; k0 < K; k0 += LCH) {
        float xs[16];
        #pragma unroll
        for (int j = 0; j < 16; j++)
            xs[j] = X[(size_t)row * K + k0 + lane + 32 * j];
        #pragma unroll
        for (int m = 0; m < NM; m++) {
            __syncthreads();
            const float* Am = As[m];
            for (int i = tid; i < 16 * LCH; i += 256) {
                int k = i >> 4, r = i & 15;
                At[r * 513 + k] = Am[(size_t)(k0 + k) * RLORA + r];
            }
            __syncthreads();
            #pragma unroll
            for (int j = 0; j < 16; j++) {
                int k = lane + 32 * j;
                float xv = xs[j];
                #pragma unroll
                for (int r = 0; r < 16; r++)
                    acc[m][r] += xv * At[r * 513 + k];
            }
        }
    }

    float* Ts[3] = {T0, T1, T2};
    #pragma unroll
    for (int m = 0; m < NM; m++) {
        #pragma unroll
        for (int r = 0; r < 16; r++) {
            float v = acc[m][r];
            #pragma unroll
            for (int o = 16; o > 0; o >>= 1) v += __shfl_xor_sync(0xffffffffu, v, o);
            if (lane == 0) Ts[m][row * RLORA + r] = v;
        }
    }
}

// ---------------- weight transpose + split ----------------
__global__ void transpose_split(const float* __restrict__ W,
                                __nv_bfloat16* __restrict__ Wh, __nv_bfloat16* __restrict__ Wl,
                                int Kd, int Nd)
{
    __shared__ float tile[32][33];
    int n0 = blockIdx.x * 32, k0 = blockIdx.y * 32;
    int x = threadIdx.x, y = threadIdx.y;
    #pragma unroll
    for (int dy = 0; dy < 32; dy += 8)
        tile[y + dy][x] = W[(size_t)(k0 + y + dy) * Nd + n0 + x];
    __syncthreads();
    #pragma unroll
    for (int dy = 0; dy < 32; dy += 8) {
        float v = tile[x][y + dy];
        size_t o = (size_t)(n0 + y + dy) * Kd + k0 + x;
        __nv_bfloat16 h, l;
        split_bf16(v, h, l);
        Wh[o] = h; Wl[o] = l;
    }
}

// ---------------- V transpose + split per head ----------------
__global__ void vsplit_t(const float* __restrict__ V,
                         __nv_bfloat16* __restrict__ Vth, __nv_bfloat16* __restrict__ Vtl)
{
    __shared__ float tile[32][33];
    int tok0 = blockIdx.x * 32, d0 = blockIdx.y * 32;
    int x = threadIdx.x, y = threadIdx.y;
    #pragma unroll
    for (int dy = 0; dy < 32; dy += 8)
        tile[y + dy][x] = V[(size_t)(tok0 + y + dy) * DMODEL + d0 + x];
    __syncthreads();
    int bb = tok0 >> 9, s0 = tok0 & 511;
    int hh = d0 >> 7, dd0 = d0 & 127;
    size_t zb = ((size_t)(bb * NHEAD + hh)) * HDIM * SEQ;
    #pragma unroll
    for (int dy = 0; dy < 32; dy += 8) {
        float v = tile[x][y + dy];
        size_t oidx = zb + (size_t)(dd0 + y + dy) * SEQ + s0 + x;
        __nv_bfloat16 h, l;
        split_bf16(v, h, l);
        Vth[oidx] = h; Vtl[oidx] = l;
    }
}

// ---------------- fused embed + rmsnorm(ln1 layer0) ----------------
__global__ void embed_rms(const int* __restrict__ idT, const int* __restrict__ idM,
                          const float* __restrict__ E, const float* __restrict__ W,
                          float* __restrict__ H, float* __restrict__ X,
                          __nv_bfloat16* __restrict__ Xh, __nv_bfloat16* __restrict__ Xl)
{
    __shared__ float red[256];
    int t  = blockIdx.x;
    int bb = t >> 9;
    int s  = t & 511;
    int id = (bb < 4) ? idT[bb * SEQ + s] : idM[(bb - 4) * SEQ + s];
    const float* src = E + (size_t)id * DMODEL;
    int tid = threadIdx.x;
    float vals[8];
    float ss = 0.f;
    #pragma unroll
    for (int j = 0; j < 8; j++) {
        float v = src[tid + 256 * j];
        vals[j] = v;
        ss += v * v;
    }
    red[tid] = ss; __syncthreads();
    for (int o = 128; o > 0; o >>= 1) {
        if (tid < o) red[tid] += red[tid + o];
        __syncthreads();
    }
    float scale = rsqrtf(red[0] / (float)DMODEL + 1e-6f);
    size_t base = (size_t)t * DMODEL;
    #pragma unroll
    for (int j = 0; j < 8; j++) {
        int idx = tid + 256 * j;
        float v = vals[j];
        H[base + idx] = v;
        float xv = v * scale * W[idx];
        X[base + idx] = xv;
        __nv_bfloat16 hh, ll;
        split_bf16(xv, hh, ll);
        Xh[base + idx] = hh; Xl[base + idx] = ll;
    }
}

// ---------------- rmsnorm ----------------
__global__ void rmsnorm_kernel(const float* __restrict__ H, const float* __restrict__ W,
                               float* __restrict__ X,
                               __nv_bfloat16* __restrict__ Xh, __nv_bfloat16* __restrict__ Xl)
{
    __shared__ float red[256];
    int row = blockIdx.x;
    const float* h = H + (size_t)row * DMODEL;
    int tid = threadIdx.x;
    float vals[8];
    float s = 0.f;
    #pragma unroll
    for (int j = 0; j < 8; j++) {
        float v = h[tid + 256 * j];
        vals[j] = v;
        s += v * v;
    }
    red[tid] = s; __syncthreads();
    for (int o = 128; o > 0; o >>= 1) {
        if (tid < o) red[tid] += red[tid + o];
        __syncthreads();
    }
    float scale = rsqrtf(red[0] / (float)DMODEL + 1e-6f);
    size_t base = (size_t)row * DMODEL;
    #pragma unroll
    for (int j = 0; j < 8; j++) {
        int idx = tid + 256 * j;
        float v = vals[j] * scale * W[idx];
        X[base + idx] = v;
        __nv_bfloat16 hh, ll;
        split_bf16(v, hh, ll);
        Xh[base + idx] = hh; Xl[base + idx] = ll;
    }
}

// ---------------- RoPE ----------------
__global__ void rope_kernel(const float* __restrict__ Q, const float* __restrict__ Kt,
                            __nv_bfloat16* __restrict__ Qh, __nv_bfloat16* __restrict__ Ql,
                            __nv_bfloat16* __restrict__ Kh, __nv_bfloat16* __restrict__ Kl)
{
    int i = blockIdx.x * blockDim.x + threadIdx.x;
    if (i >= MTOK * NHEAD * 64) return;
    int d = i & 63;
    int h = (i >> 6) & 15;
    int t = i >> 10;
    int s = t & 511;
    float freq = expf(-(float)d * (logf(10000.f) / 64.f));
    float ang = (float)s * freq;
    float sn, cs;
    sincosf(ang, &sn, &cs);
    size_t b0 = (size_t)t * DMODEL + h * HDIM + d;
    __nv_bfloat16 hh, ll;
    float x1 = Q[b0], x2 = Q[b0 + 64];
    float r1 = x1 * cs - x2 * sn;
    float r2 = x1 * sn + x2 * cs;
    split_bf16(r1, hh, ll); Qh[b0] = hh;      Ql[b0] = ll;
    split_bf16(r2, hh, ll); Qh[b0 + 64] = hh; Ql[b0 + 64] = ll;
    x1 = Kt[b0]; x2 = Kt[b0 + 64];
    r1 = x1 * cs - x2 * sn;
    r2 = x1 * sn + x2 * cs;
    split_bf16(r1, hh, ll); Kh[b0] = hh;      Kl[b0] = ll;
    split_bf16(r2, hh, ll); Kh[b0 + 64] = hh; Kl[b0 + 64] = ll;
}

// ---------------- row softmax ----------------
__global__ void softmax_kernel(const float* __restrict__ S_,
                               __nv_bfloat16* __restrict__ Ph, __nv_bfloat16* __restrict__ Pl)
{
    __shared__ float red[256];
    const float* p = S_ + (size_t)blockIdx.x * SEQ;
    int t = threadIdx.x;
    float v0 = p[t], v1 = p[t + 256];
    float m = fmaxf(v0, v1);
    red[t] = m; __syncthreads();
    for (int o = 128; o > 0; o >>= 1) {
        if (t < o) red[t] = fmaxf(red[t], red[t + o]);
        __syncthreads();
    }
    m = red[0]; __syncthreads();
    float e0 = expf(v0 - m), e1 = expf(v1 - m);
    red[t] = e0 + e1; __syncthreads();
    for (int o = 128; o > 0; o >>= 1) {
        if (t < o) red[t] += red[t + o];
        __syncthreads();
    }
    float inv = 1.f / red[0];
    size_t base = (size_t)blockIdx.x * SEQ;
    __nv_bfloat16 hh, ll;
    split_bf16(e0 * inv, hh, ll); Ph[base + t] = hh;       Pl[base + t] = ll;
    split_bf16(e1 * inv, hh, ll); Ph[base + t + 256] = hh; Pl[base + t + 256] = ll;
}

// ---------------- swiglu ----------------
__global__ void swiglu_kernel(float* __restrict__ G, const float* __restrict__ U,
                              __nv_bfloat16* __restrict__ Gh, __nv_bfloat16* __restrict__ Gl)
{
    size_t i = (size_t)blockIdx.x * blockDim.x + threadIdx.x;
    if (i >= (size_t)MTOK * FFDIM) return;
    float g = G[i];
    float sig = 1.f / (1.f + expf(-g));
    float v = g * sig * U[i];
    G[i] = v;
    __nv_bfloat16 hh, ll;
    split_bf16(v, hh, ll);
    Gh[i] = hh; Gl[i] = ll;
}

// ---------------- reps extraction + L2 normalize ----------------
__global__ void reps_kernel(const float* __restrict__ X, const int* __restrict__ mT,
                            const int* __restrict__ mM, float* __restrict__ R_)
{
    __shared__ int ired[256];
    __shared__ float fred[256];
    __shared__ int sidx;
    int bb = blockIdx.x;
    const int* mask = (bb < 4) ? mT : mM;
    int b = bb & 3;
    int t = threadIdx.x;
    int s = 0;
    for (int j = t; j < SEQ; j += 256) s += mask[b * SEQ + j];
    ired[t] = s; __syncthreads();
    for (int o = 128; o > 0; o >>= 1) {
        if (t < o) ired[t] += ired[t + o];
        __syncthreads();
    }
    if (t == 0) {
        int last = mask[0 * SEQ + 511] + mask[1 * SEQ + 511] +
                   mask[2 * SEQ + 511] + mask[3 * SEQ + 511];
        sidx = (last == BATCH) ? (SEQ - 1) : (ired[0] - 1);
    }
    __syncthreads();
    const float* row = X + (size_t)(bb * SEQ + sidx) * DMODEL;
    float ss = 0.f;
    for (int j = t; j < DMODEL; j += 256) { float v = row[j]; ss += v * v; }
    fred[t] = ss; __syncthreads();
    for (int o = 128; o > 0; o >>= 1) {
        if (t < o) fred[t] += fred[t + o];
        __syncthreads();
    }
    float inv = 1.f / sqrtf(fred[0]);
    for (int j = t; j < DMODEL; j += 256) R_[bb * DMODEL + j] = row[j] * inv;
}

// ---------------- contrastive loss ----------------
__global__ void loss_kernel(const float* __restrict__ R_, float* __restrict__ out)
{
    __shared__ float sims[16];
    int tid = threadIdx.x;
    int warp = tid >> 5, lane = tid & 31;
    for (int p = warp; p < 16; p += 8) {
        int i = p >> 2, j = p & 3;
        const float* a = R_ + i * DMODEL;
        const float* bR = R_ + (4 + j) * DMODEL;
        float d = 0.f;
        for (int k2 = lane; k2 < DMODEL; k2 += 32) d += a[k2] * bR[k2];
        #pragma unroll
        for (int o = 16; o > 0; o >>= 1) d += __shfl_xor_sync(0xffffffff, d, o);
        if (lane == 0) sims[p] = d * 20.f;
    }
    __syncthreads();
    if (tid == 0) {
        float loss = 0.f;
        for (int i = 0; i < 4; i++) {
            float m = -1e30f;
            for (int j = 0; j < 4; j++) m = fmaxf(m, sims[i * 4 + j]);
            float sum = 0.f;
            for (int j = 0; j < 4; j++) sum += expf(sims[i * 4 + j] - m);
            loss += (logf(sum) + m) - sims[i * 4 + i];
        }
        out[0] = loss * 0.25f;
    }
}

// ---------------- host driver ----------------
static void* symaddr_raw(const void* sym)
{
    void* p = nullptr;
    cudaGetSymbolAddress(&p, sym);
    return p;
}

extern "C" void kernel_launch(void* const* d_in, const int* in_sizes, int n_in,
                              void* d_out, int out_size)
{
    const int*   idT = (const int*)d_in[0];
    const int*   mT  = (const int*)d_in[1];
    const int*   idM = (const int*)d_in[2];
    const int*   mM  = (const int*)d_in[3];
    const float* emb = (const float*)d_in[4];
    const float* ln1 = (const float*)d_in[5];
    const float* ln2 = (const float*)d_in[6];
    const float* lnf = (const float*)d_in[7];
    const float* Wq = (const float*)d_in[8],  *Aq = (const float*)d_in[9],  *Bq = (const float*)d_in[10];
    const float* Wk = (const float*)d_in[11], *Ak = (const float*)d_in[12], *Bk = (const float*)d_in[13];
    const float* Wv = (const float*)d_in[14], *Av = (const float*)d_in[15], *Bv = (const float*)d_in[16];
    const float* Wo = (const float*)d_in[17], *Ao = (const float*)d_in[18], *Bo = (const float*)d_in[19];
    const float* Wg = (const float*)d_in[20], *Ag = (const float*)d_in[21], *Bg = (const float*)d_in[22];
    const float* Wu = (const float*)d_in[23], *Au = (const float*)d_in[24], *Bu = (const float*)d_in[25];
    const float* Wd = (const float*)d_in[26], *Ad = (const float*)d_in[27], *Bd = (const float*)d_in[28];

    float* h  = (float*)symaddr_raw(g_h);
    float* x  = (float*)symaddr_raw(g_x);
    float* q  = (float*)symaddr_raw(g_q);
    float* k  = (float*)symaddr_raw(g_k);
    float* v  = (float*)symaddr_raw(g_v);
    float* o  = (float*)symaddr_raw(g_o);
    float* sc = (float*)symaddr_raw(g_sc);
    float* gg = (float*)symaddr_raw(g_gate);
    float* uu = (float*)symaddr_raw(g_up);
    float* t0 = (float*)symaddr_raw(g_t);
    float* t1 = t0 + MTOK * RLORA;
    float* t2 = t0 + 2 * MTOK * RLORA;
    float* rp = (float*)symaddr_raw(g_reps);
    __nv_bfloat16* ah  = (__nv_bfloat16*)symaddr_raw(g_ah);
    __nv_bfloat16* al  = (__nv_bfloat16*)symaddr_raw(g_al);
    __nv_bfloat16* wh  = (__nv_bfloat16*)symaddr_raw(g_wh);
    __nv_bfloat16* wl  = (__nv_bfloat16*)symaddr_raw(g_wl);
    __nv_bfloat16* qh  = (__nv_bfloat16*)symaddr_raw(g_qh);
    __nv_bfloat16* ql  = (__nv_bfloat16*)symaddr_raw(g_ql);
    __nv_bfloat16* kh  = (__nv_bfloat16*)symaddr_raw(g_kh);
    __nv_bfloat16* kl  = (__nv_bfloat16*)symaddr_raw(g_kl);
    __nv_bfloat16* ph  = (__nv_bfloat16*)symaddr_raw(g_ph);
    __nv_bfloat16* pl  = (__nv_bfloat16*)symaddr_raw(g_pl);
    __nv_bfloat16* vth = (__nv_bfloat16*)symaddr_raw(g_vth);
    __nv_bfloat16* vtl = (__nv_bfloat16*)symaddr_raw(g_vtl);

    cudaFuncSetAttribute(gemm_tc,    cudaFuncAttributeMaxDynamicSharedMemorySize, GSMEM);
    cudaFuncSetAttribute(scores_mma, cudaFuncAttributeMaxDynamicSharedMemorySize, SCSM);
    cudaFuncSetAttribute(attnv_mma,  cudaFuncAttributeMaxDynamicSharedMemorySize, AVSM);

    const size_t DD = (size_t)DMODEL * DMODEL;
    const size_t DF = (size_t)DMODEL * FFDIM;
    const size_t LSTR = 4 * DD + 3 * DF;
    const dim3 tD(DMODEL / 32, DMODEL / 32), tB(32, 8);
    const dim3 tF(FFDIM / 32, DMODEL / 32);
    const dim3 tFd(DMODEL / 32, FFDIM / 32);
    const dim3 gD(DMODEL / 128, MTOK / 128);
    const dim3 gF(FFDIM / 128, MTOK / 128);

    // ---- prologue: gemm_tc at launch slots 3 and 5 for ncu ----
    transpose_split<<<tD, tB>>>(Wq, wh, wl, DMODEL, DMODEL);                          // 0
    embed_rms<<<MTOK, 256>>>(idT, idM, emb, ln1, h, x, ah, al);                       // 1
    lora_fast<3><<<MTOK / 8, 256>>>(x, DMODEL, Aq, Ak, Av, t0, t1, t2);               // 2
    gemm_tc<<<gD, 256, GSMEM>>>(ah, al, wh, wl, q, MTOK, DMODEL, DMODEL, t0, Bq, 0);  // 3
    transpose_split<<<tD, tB>>>(Wk, wh + DD, wl + DD, DMODEL, DMODEL);                // 4
    gemm_tc<<<gD, 256, GSMEM>>>(ah, al, wh + DD, wl + DD, k, MTOK, DMODEL, DMODEL, t1, Bk, 0); // 5
    transpose_split<<<tD, tB>>>(Wv, wh + 2 * DD, wl + 2 * DD, DMODEL, DMODEL);        // 6
    gemm_tc<<<gD, 256, GSMEM>>>(ah, al, wh + 2 * DD, wl + 2 * DD, v, MTOK, DMODEL, DMODEL, t2, Bv, 0); // 7

    // remaining transposes
    transpose_split<<<tD, tB>>>(Wo, wh + 3 * DD, wl + 3 * DD, DMODEL, DMODEL);
    transpose_split<<<tF, tB>>>(Wg, wh + 4 * DD, wl + 4 * DD, DMODEL, FFDIM);
    transpose_split<<<tF, tB>>>(Wu, wh + 4 * DD + DF, wl + 4 * DD + DF, DMODEL, FFDIM);
    transpose_split<<<tFd, tB>>>(Wd, wh + 4 * DD + 2 * DF, wl + 4 * DD + 2 * DF, FFDIM, DMODEL);
    for (int l = 1; l < LAYERS; l++) {
        size_t off = (size_t)l * LSTR;
        transpose_split<<<tD, tB>>>(Wq + l * DD, wh + off,          wl + off,          DMODEL, DMODEL);
        transpose_split<<<tD, tB>>>(Wk + l * DD, wh + off + DD,     wl + off + DD,     DMODEL, DMODEL);
        transpose_split<<<tD, tB>>>(Wv + l * DD, wh + off + 2 * DD, wl + off + 2 * DD, DMODEL, DMODEL);
        transpose_split<<<tD, tB>>>(Wo + l * DD, wh + off + 3 * DD, wl + off + 3 * DD, DMODEL, DMODEL);
        transpose_split<<<tF, tB>>>(Wg + l * DF, wh + off + 4 * DD, wl + off + 4 * DD, DMODEL, FFDIM);
        transpose_split<<<tF, tB>>>(Wu + l * DF, wh + off + 4 * DD + DF, wl + off + 4 * DD + DF, DMODEL, FFDIM);
        transpose_split<<<tFd, tB>>>(Wd + l * DF, wh + off + 4 * DD + 2 * DF, wl + off + 4 * DD + 2 * DF, FFDIM, DMODEL);
    }

    for (int l = 0; l < LAYERS; l++) {
        size_t off = (size_t)l * LSTR;
        const __nv_bfloat16 *Wq_h = wh + off,               *Wq_l = wl + off;
        const __nv_bfloat16 *Wk_h = wh + off + DD,          *Wk_l = wl + off + DD;
        const __nv_bfloat16 *Wv_h = wh + off + 2 * DD,      *Wv_l = wl + off + 2 * DD;
        const __nv_bfloat16 *Wo_h = wh + off + 3 * DD,      *Wo_l = wl + off + 3 * DD;
        const __nv_bfloat16 *Wg_h = wh + off + 4 * DD,      *Wg_l = wl + off + 4 * DD;
        const __nv_bfloat16 *Wu_h = wh + off + 4 * DD + DF, *Wu_l = wl + off + 4 * DD + DF;
        const __nv_bfloat16 *Wd_h = wh + off + 4 * DD + 2 * DF, *Wd_l = wl + off + 4 * DD + 2 * DF;
        const float* Bq_l = Bq + (size_t)l * RLORA * DMODEL;
        const float* Bk_l = Bk + (size_t)l * RLORA * DMODEL;
        const float* Bv_l = Bv + (size_t)l * RLORA * DMODEL;
        const float* Bo_l = Bo + (size_t)l * RLORA * DMODEL;
        const float* Bg_l = Bg + (size_t)l * RLORA * FFDIM;
        const float* Bu_l = Bu + (size_t)l * RLORA * FFDIM;
        const float* Bd_l = Bd + (size_t)l * RLORA * DMODEL;

        if (l > 0) {
            rmsnorm_kernel<<<MTOK, 256>>>(h, ln1 + l * DMODEL, x, ah, al);
            lora_fast<3><<<MTOK / 8, 256>>>(x, DMODEL, Aq + l * DMODEL * RLORA,
                                            Ak + l * DMODEL * RLORA, Av + l * DMODEL * RLORA,
                                            t0, t1, t2);
            gemm_tc<<<gD, 256, GSMEM>>>(ah, al, Wq_h, Wq_l, q, MTOK, DMODEL, DMODEL, t0, Bq_l, 0);
            gemm_tc<<<gD, 256, GSMEM>>>(ah, al, Wk_h, Wk_l, k, MTOK, DMODEL, DMODEL, t1, Bk_l, 0);
            gemm_tc<<<gD, 256, GSMEM>>>(ah, al, Wv_h, Wv_l, v, MTOK, DMODEL, DMODEL, t2, Bv_l, 0);
        }

        rope_kernel<<<(MTOK * NHEAD * 64 + 255) / 256, 256>>>(q, k, qh, ql, kh, kl);
        vsplit_t<<<dim3(MTOK / 32, DMODEL / 32), tB>>>(v, vth, vtl);

        scores_mma<<<dim3(4, 4, BB * NHEAD), 256, SCSM>>>(qh, ql, kh, kl, mT, mM, sc);
        softmax_kernel<<<BB * NHEAD * SEQ, 256>>>(sc, ph, pl);
        attnv_mma<<<dim3(1, 4, BB * NHEAD), 256, AVSM>>>(ph, pl, vth, vtl, o, ah, al);

        lora_fast<1><<<MTOK / 8, 256>>>(o, DMODEL, Ao + (size_t)l * DMODEL * RLORA,
                                        nullptr, nullptr, t0, nullptr, nullptr);
        gemm_tc<<<gD, 256, GSMEM>>>(ah, al, Wo_h, Wo_l, h, MTOK, DMODEL, DMODEL, t0, Bo_l, 1);

        rmsnorm_kernel<<<MTOK, 256>>>(h, ln2 + l * DMODEL, x, ah, al);
        lora_fast<2><<<MTOK / 8, 256>>>(x, DMODEL, Ag + (size_t)l * DMODEL * RLORA,
                                        Au + (size_t)l * DMODEL * RLORA, nullptr,
                                        t0, t1, nullptr);
        gemm_tc<<<gF, 256, GSMEM>>>(ah, al, Wg_h, Wg_l, gg, MTOK, FFDIM, DMODEL, t0, Bg_l, 0);
        gemm_tc<<<gF, 256, GSMEM>>>(ah, al, Wu_h, Wu_l, uu, MTOK, FFDIM, DMODEL, t1, Bu_l, 0);

        swiglu_kernel<<<(int)(((size_t)MTOK * FFDIM + 255) / 256), 256>>>(gg, uu, ah, al);

        lora_fast<1><<<MTOK / 8, 256>>>(gg, FFDIM, Ad + (size_t)l * FFDIM * RLORA,
                                        nullptr, nullptr, t0, nullptr, nullptr);
        gemm_tc<<<gD, 256, GSMEM>>>(ah, al, Wd_h, Wd_l, h, MTOK, DMODEL, FFDIM, t0, Bd_l, 1);
    }

    rmsnorm_kernel<<<MTOK, 256>>>(h, lnf, x, ah, al);
    reps_kernel<<<BB, 256>>>(x, mT, mM, rp);
    loss_kernel<<<1, 256>>>(rp, (float*)d_out);
}

// round 9
// speedup vs baseline: 4.3428x; 1.0094x over previous
#include <cuda_runtime.h>
#include <cuda_bf16.h>
#include <math.h>
#include <stdint.h>

// Problem constants
#define LAYERS 2
#define DMODEL 2048
#define NHEAD  16
#define HDIM   128
#define FFDIM  5632
#define RLORA  16
#define BATCH  4
#define SEQ    512
#define BB     8
#define MTOK   (BB*SEQ)
#define LORA_SCALE 1.4f
#define SCALE_QK 0.08838834764831845f

// ---------------- scratch ----------------
__device__ float g_h   [MTOK * DMODEL];
__device__ float g_x   [MTOK * DMODEL];
__device__ float g_q   [MTOK * DMODEL];
__device__ float g_k   [MTOK * DMODEL];
__device__ float g_v   [MTOK * DMODEL];
__device__ float g_o   [MTOK * DMODEL];
__device__ float g_sc  [BB * NHEAD * SEQ * SEQ];
__device__ float g_gate[MTOK * FFDIM];
__device__ float g_up  [MTOK * FFDIM];
__device__ float g_t   [3 * MTOK * RLORA];
__device__ float g_reps[BB * DMODEL];
__device__ __nv_bfloat16 g_ah[MTOK * FFDIM];
__device__ __nv_bfloat16 g_al[MTOK * FFDIM];
__device__ __nv_bfloat16 g_wh[2 * (4 * DMODEL * DMODEL + 3 * DMODEL * FFDIM)];
__device__ __nv_bfloat16 g_wl[2 * (4 * DMODEL * DMODEL + 3 * DMODEL * FFDIM)];
__device__ __nv_bfloat16 g_qh[MTOK * DMODEL];
__device__ __nv_bfloat16 g_ql[MTOK * DMODEL];
__device__ __nv_bfloat16 g_kh[MTOK * DMODEL];
__device__ __nv_bfloat16 g_kl[MTOK * DMODEL];
__device__ __nv_bfloat16 g_ph[BB * NHEAD * SEQ * SEQ];
__device__ __nv_bfloat16 g_pl[BB * NHEAD * SEQ * SEQ];
__device__ __nv_bfloat16 g_vth[MTOK * DMODEL];
__device__ __nv_bfloat16 g_vtl[MTOK * DMODEL];

// =================== helpers ===================
__device__ __forceinline__ uint32_t smem_u32(const void* p) {
    uint32_t a;
    asm("{ .reg .u64 t; cvta.to.shared.u64 t, %1; cvt.u32.u64 %0, t; }" : "=r"(a) : "l"(p));
    return a;
}
__device__ __forceinline__ void cp_async16(uint32_t saddr, const void* gptr) {
    asm volatile("cp.async.cg.shared.global [%0], [%1], 16;" :: "r"(saddr), "l"(gptr));
}
__device__ __forceinline__ void cp_commit() { asm volatile("cp.async.commit_group;"); }
template <int NWAIT>
__device__ __forceinline__ void cp_wait() {
    asm volatile("cp.async.wait_group %0;" :: "n"(NWAIT));
}
__device__ __forceinline__ void mma16(float* d, const uint32_t* a, uint32_t b0, uint32_t b1) {
    asm volatile(
        "mma.sync.aligned.m16n8k16.row.col.f32.bf16.bf16.f32 "
        "{%0,%1,%2,%3}, {%4,%5,%6,%7}, {%8,%9}, {%0,%1,%2,%3};"
        : "+f"(d[0]), "+f"(d[1]), "+f"(d[2]), "+f"(d[3])
        : "r"(a[0]), "r"(a[1]), "r"(a[2]), "r"(a[3]), "r"(b0), "r"(b1));
}
__device__ __forceinline__ void ldm_x4(uint32_t* r, uint32_t addr) {
    asm volatile("ldmatrix.sync.aligned.m8n8.x4.shared.b16 {%0,%1,%2,%3}, [%4];"
                 : "=r"(r[0]), "=r"(r[1]), "=r"(r[2]), "=r"(r[3]) : "r"(addr));
}
__device__ __forceinline__ void split_bf16(float v, __nv_bfloat16& h, __nv_bfloat16& l) {
    h = __float2bfloat16(v);
    l = __float2bfloat16(v - __bfloat162float(h));
}

// 4-stage pipeline, BK=16. Per-stage arrays: 128 rows x 16 bf16, 48B row stride
// (j*3 mod 8 bank permutation -> ldmatrix conflict-free).
#define SMSB16  48
#define ARRB16  6144
#define STGB16  24576
#define NSTAGE  4
#define LA_OFF  98304
#define LB_OFF  104448
#define GSMEM   110592
#define SCSM    98816    // stages + mask[128]
#define AVSM    98304    // stages only

// ---- compute one 128x16 stage (bf16x3) ----
#define COMPUTE16(stbase)                                                         \
    {                                                                             \
        uint32_t ahf[2][4], alf[2][4];                                            \
        int grp = lane >> 3, r8 = lane & 7;                                       \
        int mm = (grp & 1) * 8 + r8;                                              \
        int koff = (grp >> 1) * 8;                                                \
        _Pragma("unroll")                                                         \
        for (int mt = 0; mt < 2; mt++) {                                          \
            uint32_t ad = (stbase) + (wm * 32 + mt * 16 + mm) * SMSB16 + koff * 2;\
            ldm_x4(ahf[mt], ad);                                                  \
            ldm_x4(alf[mt], ad + ARRB16);                                         \
        }                                                                         \
        _Pragma("unroll")                                                         \
        for (int np = 0; np < 4; np++) {                                          \
            int nn = (grp >> 1) * 8 + r8;                                         \
            int koffb = (grp & 1) * 8;                                            \
            uint32_t bd = (stbase) + 2 * ARRB16 + (wn * 64 + np * 16 + nn) * SMSB16 + koffb * 2; \
            uint32_t bh[4], bl[4];                                                \
            ldm_x4(bh, bd);                                                       \
            ldm_x4(bl, bd + ARRB16);                                              \
            _Pragma("unroll")                                                     \
            for (int mt = 0; mt < 2; mt++) {                                      \
                mma16(d[mt][np * 2],     ahf[mt], bh[0], bh[1]);                  \
                mma16(d[mt][np * 2],     ahf[mt], bl[0], bl[1]);                  \
                mma16(d[mt][np * 2],     alf[mt], bh[0], bh[1]);                  \
                mma16(d[mt][np * 2 + 1], ahf[mt], bh[2], bh[3]);                  \
                mma16(d[mt][np * 2 + 1], ahf[mt], bl[2], bl[3]);                  \
                mma16(d[mt][np * 2 + 1], alf[mt], bh[2], bh[3]);                  \
            }                                                                     \
        }                                                                         \
    }

// ---- issue one 128x16 stage of 4 arrays via cp.async ----
#define ISSUE16(kt, aH, aL, bH, bL, LDA, LDB)                                     \
    {                                                                             \
        const int k0_ = (kt) << 4;                                                \
        const int buf_ = (kt) & (NSTAGE - 1);                                     \
        _Pragma("unroll")                                                         \
        for (int j = 0; j < 4; j++) {                                             \
            int e = tid + j * 256;                                                \
            int arr = e >> 8;                                                     \
            int i = e & 255;                                                      \
            int row = i >> 1;                                                     \
            int cg = (i & 1) << 3;                                                \
            const __nv_bfloat16* gp;                                              \
            if (arr == 0)      gp = (aH) + (size_t)row * (LDA) + k0_ + cg;        \
            else if (arr == 1) gp = (aL) + (size_t)row * (LDA) + k0_ + cg;        \
            else if (arr == 2) gp = (bH) + (size_t)row * (LDB) + k0_ + cg;        \
            else               gp = (bL) + (size_t)row * (LDB) + k0_ + cg;        \
            cp_async16(sb + buf_ * STGB16 + arr * ARRB16 + row * SMSB16 + cg * 2, gp); \
        }                                                                         \
        cp_commit();                                                              \
    }

// ---- full multistage mainloop (requires nk >= 3) ----
#define MAINLOOP(nk, aH, aL, bH, bL, LDA, LDB)                                    \
    {                                                                             \
        ISSUE16(0, aH, aL, bH, bL, LDA, LDB);                                     \
        ISSUE16(1, aH, aL, bH, bL, LDA, LDB);                                     \
        ISSUE16(2, aH, aL, bH, bL, LDA, LDB);                                     \
        for (int kt = 0; kt < (nk); kt++) {                                       \
            cp_wait<2>();                                                         \
            __syncthreads();                                                      \
            const uint32_t st_ = sb + (kt & (NSTAGE - 1)) * STGB16;               \
            COMPUTE16(st_)                                                        \
            if (kt + 3 < (nk)) { ISSUE16(kt + 3, aH, aL, bH, bL, LDA, LDB); }     \
            else               { cp_commit(); }                                   \
        }                                                                         \
        cp_wait<0>();                                                             \
        __syncthreads();                                                          \
    }

// =================== main GEMM with fused LoRA + residual ===================
__global__ __launch_bounds__(256, 2)
void gemm_tc(const __nv_bfloat16* __restrict__ Agh, const __nv_bfloat16* __restrict__ Agl,
             const __nv_bfloat16* __restrict__ Wgh, const __nv_bfloat16* __restrict__ Wgl,
             float* __restrict__ C, int M, int N, int K,
             const float* __restrict__ lT, const float* __restrict__ lB, int accum)
{
    extern __shared__ char smc[];
    const int tid  = threadIdx.x;
    const int wid  = tid >> 5;
    const int lane = tid & 31;
    const int t4   = lane & 3;
    const int g    = lane >> 2;
    const int wm   = wid >> 1;
    const int wn   = wid & 1;
    const int bm   = blockIdx.y * 128;
    const int bn   = blockIdx.x * 128;
    const uint32_t sb = smem_u32(smc);

    __nv_bfloat16* la = (__nv_bfloat16*)(smc + LA_OFF);
    __nv_bfloat16* lb = (__nv_bfloat16*)(smc + LB_OFF);
    for (int i = tid; i < 2048; i += 256) {
        int row = i >> 4, r = i & 15;
        la[row * 24 + r] = __float2bfloat16(LORA_SCALE * lT[(size_t)(bm + row) * RLORA + r]);
        lb[row * 24 + r] = __float2bfloat16(lB[(size_t)r * N + bn + row]);
    }

    float d[2][8][4];
    #pragma unroll
    for (int mt = 0; mt < 2; mt++)
        #pragma unroll
        for (int nt = 0; nt < 8; nt++)
            #pragma unroll
            for (int j = 0; j < 4; j++) d[mt][nt][j] = 0.f;

    const __nv_bfloat16* aH = Agh + (size_t)bm * K;
    const __nv_bfloat16* aL = Agl + (size_t)bm * K;
    const __nv_bfloat16* bH = Wgh + (size_t)bn * K;
    const __nv_bfloat16* bL = Wgl + (size_t)bn * K;

    const int nk = K >> 4;
    MAINLOOP(nk, aH, aL, bH, bL, K, K)

    // LoRA tail (hi-only, K=16)
    {
        uint32_t a[2][4];
        #pragma unroll
        for (int mt = 0; mt < 2; mt++) {
            const char* pa = (const char*)la + (wm * 32 + mt * 16 + g) * 48 + t4 * 4;
            a[mt][0] = *(const uint32_t*)(pa);
            a[mt][1] = *(const uint32_t*)(pa + 8 * 48);
            a[mt][2] = *(const uint32_t*)(pa + 16);
            a[mt][3] = *(const uint32_t*)(pa + 8 * 48 + 16);
        }
        #pragma unroll
        for (int nt = 0; nt < 8; nt++) {
            const char* pb = (const char*)lb + (wn * 64 + nt * 8 + g) * 48 + t4 * 4;
            uint32_t b0 = *(const uint32_t*)(pb);
            uint32_t b1 = *(const uint32_t*)(pb + 16);
            #pragma unroll
            for (int mt = 0; mt < 2; mt++) mma16(d[mt][nt], a[mt], b0, b1);
        }
    }

    #pragma unroll
    for (int mt = 0; mt < 2; mt++) {
        const int r0 = bm + wm * 32 + mt * 16 + g;
        #pragma unroll
        for (int nt = 0; nt < 8; nt++) {
            const int c0 = bn + wn * 64 + nt * 8 + 2 * t4;
            float2 v0 = make_float2(d[mt][nt][0], d[mt][nt][1]);
            float2 v1 = make_float2(d[mt][nt][2], d[mt][nt][3]);
            float* p0 = C + (size_t)r0 * N + c0;
            float* p1 = C + (size_t)(r0 + 8) * N + c0;
            if (accum) {
                float2 o0 = *(const float2*)p0;
                float2 o1 = *(const float2*)p1;
                v0.x += o0.x; v0.y += o0.y;
                v1.x += o1.x; v1.y += o1.y;
            }
            *(float2*)p0 = v0;
            *(float2*)p1 = v1;
        }
    }
}

// =================== scores ===================
__global__ __launch_bounds__(256, 2)
void scores_mma(const __nv_bfloat16* __restrict__ Qh, const __nv_bfloat16* __restrict__ Ql,
                const __nv_bfloat16* __restrict__ Kh, const __nv_bfloat16* __restrict__ Kl,
                const int* __restrict__ mT, const int* __restrict__ mM,
                float* __restrict__ S_)
{
    extern __shared__ char smc[];
    const int tid  = threadIdx.x;
    const int wid  = tid >> 5;
    const int lane = tid & 31;
    const int t4   = lane & 3;
    const int g    = lane >> 2;
    const int wm   = wid >> 1;
    const int wn   = wid & 1;
    const int z    = blockIdx.z;
    const int bb   = z >> 4;
    const int hh   = z & 15;
    const int bm   = blockIdx.y * 128;
    const int bn   = blockIdx.x * 128;
    const uint32_t sb = smem_u32(smc);
    int* msk = (int*)(smc + NSTAGE * STGB16);

    const int* mask = (bb < 4) ? (mT + bb * SEQ) : (mM + (bb - 4) * SEQ);
    if (tid < 128) msk[tid] = mask[bn + tid];

    float* Sbase = S_ + (size_t)z * SEQ * SEQ;

    if (bn > bm) {
        __syncthreads();
        for (int i = tid; i < 128 * 128; i += 256) {
            int r = i >> 7, c = i & 127;
            Sbase[(size_t)(bm + r) * SEQ + bn + c] = -1e9f;
        }
        return;
    }

    float d[2][8][4];
    #pragma unroll
    for (int mt = 0; mt < 2; mt++)
        #pragma unroll
        for (int nt = 0; nt < 8; nt++)
            #pragma unroll
            for (int j = 0; j < 4; j++) d[mt][nt][j] = 0.f;

    const __nv_bfloat16* aH = Qh + (size_t)(bb * SEQ + bm) * DMODEL + hh * HDIM;
    const __nv_bfloat16* aL = Ql + (size_t)(bb * SEQ + bm) * DMODEL + hh * HDIM;
    const __nv_bfloat16* bH = Kh + (size_t)(bb * SEQ + bn) * DMODEL + hh * HDIM;
    const __nv_bfloat16* bL = Kl + (size_t)(bb * SEQ + bn) * DMODEL + hh * HDIM;

    const int nk = HDIM >> 4;   // 8
    MAINLOOP(nk, aH, aL, bH, bL, DMODEL, DMODEL)

    #pragma unroll
    for (int mt = 0; mt < 2; mt++) {
        const int r0 = wm * 32 + mt * 16 + g;
        #pragma unroll
        for (int nt = 0; nt < 8; nt++) {
            const int c0 = wn * 64 + nt * 8 + 2 * t4;
            #pragma unroll
            for (int half = 0; half < 2; half++) {
                int r = r0 + half * 8;
                int sq = bm + r, sk0 = bn + c0;
                float va = d[mt][nt][half * 2], vb = d[mt][nt][half * 2 + 1];
                bool ok0 = (sk0 <= sq) && (msk[c0] > 0);
                bool ok1 = (sk0 + 1 <= sq) && (msk[c0 + 1] > 0);
                float2 out;
                out.x = va * SCALE_QK + (ok0 ? 0.f : -1e9f);
                out.y = vb * SCALE_QK + (ok1 ? 0.f : -1e9f);
                *(float2*)(Sbase + (size_t)sq * SEQ + sk0) = out;
            }
        }
    }
}

// =================== attnv (causal-truncated K loop) ===================
__global__ __launch_bounds__(256, 2)
void attnv_mma(const __nv_bfloat16* __restrict__ Ph, const __nv_bfloat16* __restrict__ Pl,
               const __nv_bfloat16* __restrict__ Vth, const __nv_bfloat16* __restrict__ Vtl,
               float* __restrict__ O,
               __nv_bfloat16* __restrict__ Oh, __nv_bfloat16* __restrict__ Ol)
{
    extern __shared__ char smc[];
    const int tid  = threadIdx.x;
    const int wid  = tid >> 5;
    const int lane = tid & 31;
    const int t4   = lane & 3;
    const int g    = lane >> 2;
    const int wm   = wid >> 1;
    const int wn   = wid & 1;
    const int z    = blockIdx.z;
    const int bb   = z >> 4;
    const int hh   = z & 15;
    const int bm   = blockIdx.y * 128;
    const uint32_t sb = smem_u32(smc);

    float d[2][8][4];
    #pragma unroll
    for (int mt = 0; mt < 2; mt++)
        #pragma unroll
        for (int nt = 0; nt < 8; nt++)
            #pragma unroll
            for (int j = 0; j < 4; j++) d[mt][nt][j] = 0.f;

    const __nv_bfloat16* aH = Ph + ((size_t)z * SEQ + bm) * SEQ;
    const __nv_bfloat16* aL = Pl + ((size_t)z * SEQ + bm) * SEQ;
    const __nv_bfloat16* bH = Vth + (size_t)z * HDIM * SEQ;
    const __nv_bfloat16* bL = Vtl + (size_t)z * HDIM * SEQ;

    // causal: P[bm..bm+127][k] == 0 for k >= bm+128
    const int nk = (bm >> 4) + 8;
    MAINLOOP(nk, aH, aL, bH, bL, SEQ, SEQ)

    #pragma unroll
    for (int mt = 0; mt < 2; mt++) {
        const int r0 = bm + wm * 32 + mt * 16 + g;
        #pragma unroll
        for (int nt = 0; nt < 8; nt++) {
            const int c0 = wn * 64 + nt * 8 + 2 * t4;
            #pragma unroll
            for (int half = 0; half < 2; half++) {
                int r = r0 + half * 8;
                size_t oidx = (size_t)(bb * SEQ + r) * DMODEL + hh * HDIM + c0;
                float va = d[mt][nt][half * 2], vb = d[mt][nt][half * 2 + 1];
                *(float2*)(O + oidx) = make_float2(va, vb);
                __nv_bfloat16 h0, l0, h1, l1;
                split_bf16(va, h0, l0);
                split_bf16(vb, h1, l1);
                Oh[oidx] = h0; Oh[oidx + 1] = h1;
                Ol[oidx] = l0; Ol[oidx + 1] = l1;
            }
        }
    }
}

// =================== fast LoRA-T ===================
#define LCH 512
template <int NM>
__global__ __launch_bounds__(256)
void lora_fast(const float* __restrict__ X, int K,
               const float* __restrict__ A0, const float* __restrict__ A1,
               const float* __restrict__ A2,
               float* __restrict__ T0, float* __restrict__ T1, float* __restrict__ T2)
{
    __shared__ float At[16 * 513];
    const int tid  = threadIdx.x;
    const int lane = tid & 31;
    const int warp = tid >> 5;
    const int row  = blockIdx.x * 8 + warp;

    const float* As[3] = {A0, A1, A2};
    float acc[NM][16];
    #pragma unroll
    for (int m = 0; m < NM; m++)
        #pragma unroll
        for (int r = 0; r < 16; r++) acc[m][r] = 0.f;

    for (int k0 = 0; k0 < K; k0 += LCH) {
        float xs[16];
        #pragma unroll
        for (int j = 0; j < 16; j++)
            xs[j] = X[(size_t)row * K + k0 + lane + 32 * j];
        #pragma unroll
        for (int m = 0; m < NM; m++) {
            __syncthreads();
            const float* Am = As[m];
            for (int i = tid; i < 16 * LCH; i += 256) {
                int k = i >> 4, r = i & 15;
                At[r * 513 + k] = Am[(size_t)(k0 + k) * RLORA + r];
            }
            __syncthreads();
            #pragma unroll
            for (int j = 0; j < 16; j++) {
                int k = lane + 32 * j;
                float xv = xs[j];
                #pragma unroll
                for (int r = 0; r < 16; r++)
                    acc[m][r] += xv * At[r * 513 + k];
            }
        }
    }

    float* Ts[3] = {T0, T1, T2};
    #pragma unroll
    for (int m = 0; m < NM; m++) {
        #pragma unroll
        for (int r = 0; r < 16; r++) {
            float v = acc[m][r];
            #pragma unroll
            for (int o = 16; o > 0; o >>= 1) v += __shfl_xor_sync(0xffffffffu, v, o);
            if (lane == 0) Ts[m][row * RLORA + r] = v;
        }
    }
}

// ---------------- weight transpose + split ----------------
__global__ void transpose_split(const float* __restrict__ W,
                                __nv_bfloat16* __restrict__ Wh, __nv_bfloat16* __restrict__ Wl,
                                int Kd, int Nd)
{
    __shared__ float tile[32][33];
    int n0 = blockIdx.x * 32, k0 = blockIdx.y * 32;
    int x = threadIdx.x, y = threadIdx.y;
    #pragma unroll
    for (int dy = 0; dy < 32; dy += 8)
        tile[y + dy][x] = W[(size_t)(k0 + y + dy) * Nd + n0 + x];
    __syncthreads();
    #pragma unroll
    for (int dy = 0; dy < 32; dy += 8) {
        float v = tile[x][y + dy];
        size_t o = (size_t)(n0 + y + dy) * Kd + k0 + x;
        __nv_bfloat16 h, l;
        split_bf16(v, h, l);
        Wh[o] = h; Wl[o] = l;
    }
}

// ---------------- V transpose + split per head ----------------
__global__ void vsplit_t(const float* __restrict__ V,
                         __nv_bfloat16* __restrict__ Vth, __nv_bfloat16* __restrict__ Vtl)
{
    __shared__ float tile[32][33];
    int tok0 = blockIdx.x * 32, d0 = blockIdx.y * 32;
    int x = threadIdx.x, y = threadIdx.y;
    #pragma unroll
    for (int dy = 0; dy < 32; dy += 8)
        tile[y + dy][x] = V[(size_t)(tok0 + y + dy) * DMODEL + d0 + x];
    __syncthreads();
    int bb = tok0 >> 9, s0 = tok0 & 511;
    int hh = d0 >> 7, dd0 = d0 & 127;
    size_t zb = ((size_t)(bb * NHEAD + hh)) * HDIM * SEQ;
    #pragma unroll
    for (int dy = 0; dy < 32; dy += 8) {
        float v = tile[x][y + dy];
        size_t oidx = zb + (size_t)(dd0 + y + dy) * SEQ + s0 + x;
        __nv_bfloat16 h, l;
        split_bf16(v, h, l);
        Vth[oidx] = h; Vtl[oidx] = l;
    }
}

// ---------------- fused embed + rmsnorm(ln1 layer0) ----------------
__global__ void embed_rms(const int* __restrict__ idT, const int* __restrict__ idM,
                          const float* __restrict__ E, const float* __restrict__ W,
                          float* __restrict__ H, float* __restrict__ X,
                          __nv_bfloat16* __restrict__ Xh, __nv_bfloat16* __restrict__ Xl)
{
    __shared__ float red[256];
    int t  = blockIdx.x;
    int bb = t >> 9;
    int s  = t & 511;
    int id = (bb < 4) ? idT[bb * SEQ + s] : idM[(bb - 4) * SEQ + s];
    const float* src = E + (size_t)id * DMODEL;
    int tid = threadIdx.x;
    float vals[8];
    float ss = 0.f;
    #pragma unroll
    for (int j = 0; j < 8; j++) {
        float v = src[tid + 256 * j];
        vals[j] = v;
        ss += v * v;
    }
    red[tid] = ss; __syncthreads();
    for (int o = 128; o > 0; o >>= 1) {
        if (tid < o) red[tid] += red[tid + o];
        __syncthreads();
    }
    float scale = rsqrtf(red[0] / (float)DMODEL + 1e-6f);
    size_t base = (size_t)t * DMODEL;
    #pragma unroll
    for (int j = 0; j < 8; j++) {
        int idx = tid + 256 * j;
        float v = vals[j];
        H[base + idx] = v;
        float xv = v * scale * W[idx];
        X[base + idx] = xv;
        __nv_bfloat16 hh, ll;
        split_bf16(xv, hh, ll);
        Xh[base + idx] = hh; Xl[base + idx] = ll;
    }
}

// ---------------- rmsnorm ----------------
__global__ void rmsnorm_kernel(const float* __restrict__ H, const float* __restrict__ W,
                               float* __restrict__ X,
                               __nv_bfloat16* __restrict__ Xh, __nv_bfloat16* __restrict__ Xl)
{
    __shared__ float red[256];
    int row = blockIdx.x;
    const float* h = H + (size_t)row * DMODEL;
    int tid = threadIdx.x;
    float vals[8];
    float s = 0.f;
    #pragma unroll
    for (int j = 0; j < 8; j++) {
        float v = h[tid + 256 * j];
        vals[j] = v;
        s += v * v;
    }
    red[tid] = s; __syncthreads();
    for (int o = 128; o > 0; o >>= 1) {
        if (tid < o) red[tid] += red[tid + o];
        __syncthreads();
    }
    float scale = rsqrtf(red[0] / (float)DMODEL + 1e-6f);
    size_t base = (size_t)row * DMODEL;
    #pragma unroll
    for (int j = 0; j < 8; j++) {
        int idx = tid + 256 * j;
        float v = vals[j] * scale * W[idx];
        X[base + idx] = v;
        __nv_bfloat16 hh, ll;
        split_bf16(v, hh, ll);
        Xh[base + idx] = hh; Xl[base + idx] = ll;
    }
}

// ---------------- RoPE ----------------
__global__ void rope_kernel(const float* __restrict__ Q, const float* __restrict__ Kt,
                            __nv_bfloat16* __restrict__ Qh, __nv_bfloat16* __restrict__ Ql,
                            __nv_bfloat16* __restrict__ Kh, __nv_bfloat16* __restrict__ Kl)
{
    int i = blockIdx.x * blockDim.x + threadIdx.x;
    if (i >= MTOK * NHEAD * 64) return;
    int d = i & 63;
    int h = (i >> 6) & 15;
    int t = i >> 10;
    int s = t & 511;
    float freq = expf(-(float)d * (logf(10000.f) / 64.f));
    float ang = (float)s * freq;
    float sn, cs;
    sincosf(ang, &sn, &cs);
    size_t b0 = (size_t)t * DMODEL + h * HDIM + d;
    __nv_bfloat16 hh, ll;
    float x1 = Q[b0], x2 = Q[b0 + 64];
    float r1 = x1 * cs - x2 * sn;
    float r2 = x1 * sn + x2 * cs;
    split_bf16(r1, hh, ll); Qh[b0] = hh;      Ql[b0] = ll;
    split_bf16(r2, hh, ll); Qh[b0 + 64] = hh; Ql[b0 + 64] = ll;
    x1 = Kt[b0]; x2 = Kt[b0 + 64];
    r1 = x1 * cs - x2 * sn;
    r2 = x1 * sn + x2 * cs;
    split_bf16(r1, hh, ll); Kh[b0] = hh;      Kl[b0] = ll;
    split_bf16(r2, hh, ll); Kh[b0 + 64] = hh; Kl[b0 + 64] = ll;
}

// ---------------- row softmax ----------------
__global__ void softmax_kernel(const float* __restrict__ S_,
                               __nv_bfloat16* __restrict__ Ph, __nv_bfloat16* __restrict__ Pl)
{
    __shared__ float red[256];
    const float* p = S_ + (size_t)blockIdx.x * SEQ;
    int t = threadIdx.x;
    float v0 = p[t], v1 = p[t + 256];
    float m = fmaxf(v0, v1);
    red[t] = m; __syncthreads();
    for (int o = 128; o > 0; o >>= 1) {
        if (t < o) red[t] = fmaxf(red[t], red[t + o]);
        __syncthreads();
    }
    m = red[0]; __syncthreads();
    float e0 = expf(v0 - m), e1 = expf(v1 - m);
    red[t] = e0 + e1; __syncthreads();
    for (int o = 128; o > 0; o >>= 1) {
        if (t < o) red[t] += red[t + o];
        __syncthreads();
    }
    float inv = 1.f / red[0];
    size_t base = (size_t)blockIdx.x * SEQ;
    __nv_bfloat16 hh, ll;
    split_bf16(e0 * inv, hh, ll); Ph[base + t] = hh;       Pl[base + t] = ll;
    split_bf16(e1 * inv, hh, ll); Ph[base + t + 256] = hh; Pl[base + t + 256] = ll;
}

// ---------------- swiglu ----------------
__global__ void swiglu_kernel(float* __restrict__ G, const float* __restrict__ U,
                              __nv_bfloat16* __restrict__ Gh, __nv_bfloat16* __restrict__ Gl)
{
    size_t i = (size_t)blockIdx.x * blockDim.x + threadIdx.x;
    if (i >= (size_t)MTOK * FFDIM) return;
    float g = G[i];
    float sig = 1.f / (1.f + expf(-g));
    float v = g * sig * U[i];
    G[i] = v;
    __nv_bfloat16 hh, ll;
    split_bf16(v, hh, ll);
    Gh[i] = hh; Gl[i] = ll;
}

// ---------------- reps extraction + L2 normalize ----------------
__global__ void reps_kernel(const float* __restrict__ X, const int* __restrict__ mT,
                            const int* __restrict__ mM, float* __restrict__ R_)
{
    __shared__ int ired[256];
    __shared__ float fred[256];
    __shared__ int sidx;
    int bb = blockIdx.x;
    const int* mask = (bb < 4) ? mT : mM;
    int b = bb & 3;
    int t = threadIdx.x;
    int s = 0;
    for (int j = t; j < SEQ; j += 256) s += mask[b * SEQ + j];
    ired[t] = s; __syncthreads();
    for (int o = 128; o > 0; o >>= 1) {
        if (t < o) ired[t] += ired[t + o];
        __syncthreads();
    }
    if (t == 0) {
        int last = mask[0 * SEQ + 511] + mask[1 * SEQ + 511] +
                   mask[2 * SEQ + 511] + mask[3 * SEQ + 511];
        sidx = (last == BATCH) ? (SEQ - 1) : (ired[0] - 1);
    }
    __syncthreads();
    const float* row = X + (size_t)(bb * SEQ + sidx) * DMODEL;
    float ss = 0.f;
    for (int j = t; j < DMODEL; j += 256) { float v = row[j]; ss += v * v; }
    fred[t] = ss; __syncthreads();
    for (int o = 128; o > 0; o >>= 1) {
        if (t < o) fred[t] += fred[t + o];
        __syncthreads();
    }
    float inv = 1.f / sqrtf(fred[0]);
    for (int j = t; j < DMODEL; j += 256) R_[bb * DMODEL + j] = row[j] * inv;
}

// ---------------- contrastive loss ----------------
__global__ void loss_kernel(const float* __restrict__ R_, float* __restrict__ out)
{
    __shared__ float sims[16];
    int tid = threadIdx.x;
    int warp = tid >> 5, lane = tid & 31;
    for (int p = warp; p < 16; p += 8) {
        int i = p >> 2, j = p & 3;
        const float* a = R_ + i * DMODEL;
        const float* bR = R_ + (4 + j) * DMODEL;
        float d = 0.f;
        for (int k2 = lane; k2 < DMODEL; k2 += 32) d += a[k2] * bR[k2];
        #pragma unroll
        for (int o = 16; o > 0; o >>= 1) d += __shfl_xor_sync(0xffffffff, d, o);
        if (lane == 0) sims[p] = d * 20.f;
    }
    __syncthreads();
    if (tid == 0) {
        float loss = 0.f;
        for (int i = 0; i < 4; i++) {
            float m = -1e30f;
            for (int j = 0; j < 4; j++) m = fmaxf(m, sims[i * 4 + j]);
            float sum = 0.f;
            for (int j = 0; j < 4; j++) sum += expf(sims[i * 4 + j] - m);
            loss += (logf(sum) + m) - sims[i * 4 + i];
        }
        out[0] = loss * 0.25f;
    }
}

// ---------------- host driver ----------------
static void* symaddr_raw(const void* sym)
{
    void* p = nullptr;
    cudaGetSymbolAddress(&p, sym);
    return p;
}

extern "C" void kernel_launch(void* const* d_in, const int* in_sizes, int n_in,
                              void* d_out, int out_size)
{
    const int*   idT = (const int*)d_in[0];
    const int*   mT  = (const int*)d_in[1];
    const int*   idM = (const int*)d_in[2];
    const int*   mM  = (const int*)d_in[3];
    const float* emb = (const float*)d_in[4];
    const float* ln1 = (const float*)d_in[5];
    const float* ln2 = (const float*)d_in[6];
    const float* lnf = (const float*)d_in[7];
    const float* Wq = (const float*)d_in[8],  *Aq = (const float*)d_in[9],  *Bq = (const float*)d_in[10];
    const float* Wk = (const float*)d_in[11], *Ak = (const float*)d_in[12], *Bk = (const float*)d_in[13];
    const float* Wv = (const float*)d_in[14], *Av = (const float*)d_in[15], *Bv = (const float*)d_in[16];
    const float* Wo = (const float*)d_in[17], *Ao = (const float*)d_in[18], *Bo = (const float*)d_in[19];
    const float* Wg = (const float*)d_in[20], *Ag = (const float*)d_in[21], *Bg = (const float*)d_in[22];
    const float* Wu = (const float*)d_in[23], *Au = (const float*)d_in[24], *Bu = (const float*)d_in[25];
    const float* Wd = (const float*)d_in[26], *Ad = (const float*)d_in[27], *Bd = (const float*)d_in[28];

    float* h  = (float*)symaddr_raw(g_h);
    float* x  = (float*)symaddr_raw(g_x);
    float* q  = (float*)symaddr_raw(g_q);
    float* k  = (float*)symaddr_raw(g_k);
    float* v  = (float*)symaddr_raw(g_v);
    float* o  = (float*)symaddr_raw(g_o);
    float* sc = (float*)symaddr_raw(g_sc);
    float* gg = (float*)symaddr_raw(g_gate);
    float* uu = (float*)symaddr_raw(g_up);
    float* t0 = (float*)symaddr_raw(g_t);
    float* t1 = t0 + MTOK * RLORA;
    float* t2 = t0 + 2 * MTOK * RLORA;
    float* rp = (float*)symaddr_raw(g_reps);
    __nv_bfloat16* ah  = (__nv_bfloat16*)symaddr_raw(g_ah);
    __nv_bfloat16* al  = (__nv_bfloat16*)symaddr_raw(g_al);
    __nv_bfloat16* wh  = (__nv_bfloat16*)symaddr_raw(g_wh);
    __nv_bfloat16* wl  = (__nv_bfloat16*)symaddr_raw(g_wl);
    __nv_bfloat16* qh  = (__nv_bfloat16*)symaddr_raw(g_qh);
    __nv_bfloat16* ql  = (__nv_bfloat16*)symaddr_raw(g_ql);
    __nv_bfloat16* kh  = (__nv_bfloat16*)symaddr_raw(g_kh);
    __nv_bfloat16* kl  = (__nv_bfloat16*)symaddr_raw(g_kl);
    __nv_bfloat16* ph  = (__nv_bfloat16*)symaddr_raw(g_ph);
    __nv_bfloat16* pl  = (__nv_bfloat16*)symaddr_raw(g_pl);
    __nv_bfloat16* vth = (__nv_bfloat16*)symaddr_raw(g_vth);
    __nv_bfloat16* vtl = (__nv_bfloat16*)symaddr_raw(g_vtl);

    cudaFuncSetAttribute(gemm_tc,    cudaFuncAttributeMaxDynamicSharedMemorySize, GSMEM);
    cudaFuncSetAttribute(scores_mma, cudaFuncAttributeMaxDynamicSharedMemorySize, SCSM);
    cudaFuncSetAttribute(attnv_mma,  cudaFuncAttributeMaxDynamicSharedMemorySize, AVSM);

    const size_t DD = (size_t)DMODEL * DMODEL;
    const size_t DF = (size_t)DMODEL * FFDIM;
    const size_t LSTR = 4 * DD + 3 * DF;
    const dim3 tD(DMODEL / 32, DMODEL / 32), tB(32, 8);
    const dim3 tF(FFDIM / 32, DMODEL / 32);
    const dim3 tFd(DMODEL / 32, FFDIM / 32);
    const dim3 gD(DMODEL / 128, MTOK / 128);
    const dim3 gF(FFDIM / 128, MTOK / 128);

    // ---- prologue: gemm_tc at launch slots 3 and 5 for ncu ----
    transpose_split<<<tD, tB>>>(Wq, wh, wl, DMODEL, DMODEL);                          // 0
    embed_rms<<<MTOK, 256>>>(idT, idM, emb, ln1, h, x, ah, al);                       // 1
    lora_fast<3><<<MTOK / 8, 256>>>(x, DMODEL, Aq, Ak, Av, t0, t1, t2);               // 2
    gemm_tc<<<gD, 256, GSMEM>>>(ah, al, wh, wl, q, MTOK, DMODEL, DMODEL, t0, Bq, 0);  // 3
    transpose_split<<<tD, tB>>>(Wk, wh + DD, wl + DD, DMODEL, DMODEL);                // 4
    gemm_tc<<<gD, 256, GSMEM>>>(ah, al, wh + DD, wl + DD, k, MTOK, DMODEL, DMODEL, t1, Bk, 0); // 5
    transpose_split<<<tD, tB>>>(Wv, wh + 2 * DD, wl + 2 * DD, DMODEL, DMODEL);        // 6
    gemm_tc<<<gD, 256, GSMEM>>>(ah, al, wh + 2 * DD, wl + 2 * DD, v, MTOK, DMODEL, DMODEL, t2, Bv, 0); // 7

    // remaining transposes
    transpose_split<<<tD, tB>>>(Wo, wh + 3 * DD, wl + 3 * DD, DMODEL, DMODEL);
    transpose_split<<<tF, tB>>>(Wg, wh + 4 * DD, wl + 4 * DD, DMODEL, FFDIM);
    transpose_split<<<tF, tB>>>(Wu, wh + 4 * DD + DF, wl + 4 * DD + DF, DMODEL, FFDIM);
    transpose_split<<<tFd, tB>>>(Wd, wh + 4 * DD + 2 * DF, wl + 4 * DD + 2 * DF, FFDIM, DMODEL);
    for (int l = 1; l < LAYERS; l++) {
        size_t off = (size_t)l * LSTR;
        transpose_split<<<tD, tB>>>(Wq + l * DD, wh + off,          wl + off,          DMODEL, DMODEL);
        transpose_split<<<tD, tB>>>(Wk + l * DD, wh + off + DD,     wl + off + DD,     DMODEL, DMODEL);
        transpose_split<<<tD, tB>>>(Wv + l * DD, wh + off + 2 * DD, wl + off + 2 * DD, DMODEL, DMODEL);
        transpose_split<<<tD, tB>>>(Wo + l * DD, wh + off + 3 * DD, wl + off + 3 * DD, DMODEL, DMODEL);
        transpose_split<<<tF, tB>>>(Wg + l * DF, wh + off + 4 * DD, wl + off + 4 * DD, DMODEL, FFDIM);
        transpose_split<<<tF, tB>>>(Wu + l * DF, wh + off + 4 * DD + DF, wl + off + 4 * DD + DF, DMODEL, FFDIM);
        transpose_split<<<tFd, tB>>>(Wd + l * DF, wh + off + 4 * DD + 2 * DF, wl + off + 4 * DD + 2 * DF, FFDIM, DMODEL);
    }

    for (int l = 0; l < LAYERS; l++) {
        size_t off = (size_t)l * LSTR;
        const __nv_bfloat16 *Wq_h = wh + off,               *Wq_l = wl + off;
        const __nv_bfloat16 *Wk_h = wh + off + DD,          *Wk_l = wl + off + DD;
        const __nv_bfloat16 *Wv_h = wh + off + 2 * DD,      *Wv_l = wl + off + 2 * DD;
        const __nv_bfloat16 *Wo_h = wh + off + 3 * DD,      *Wo_l = wl + off + 3 * DD;
        const __nv_bfloat16 *Wg_h = wh + off + 4 * DD,      *Wg_l = wl + off + 4 * DD;
        const __nv_bfloat16 *Wu_h = wh + off + 4 * DD + DF, *Wu_l = wl + off + 4 * DD + DF;
        const __nv_bfloat16 *Wd_h = wh + off + 4 * DD + 2 * DF, *Wd_l = wl + off + 4 * DD + 2 * DF;
        const float* Bq_l = Bq + (size_t)l * RLORA * DMODEL;
        const float* Bk_l = Bk + (size_t)l * RLORA * DMODEL;
        const float* Bv_l = Bv + (size_t)l * RLORA * DMODEL;
        const float* Bo_l = Bo + (size_t)l * RLORA * DMODEL;
        const float* Bg_l = Bg + (size_t)l * RLORA * FFDIM;
        const float* Bu_l = Bu + (size_t)l * RLORA * FFDIM;
        const float* Bd_l = Bd + (size_t)l * RLORA * DMODEL;

        if (l > 0) {
            rmsnorm_kernel<<<MTOK, 256>>>(h, ln1 + l * DMODEL, x, ah, al);
            lora_fast<3><<<MTOK / 8, 256>>>(x, DMODEL, Aq + l * DMODEL * RLORA,
                                            Ak + l * DMODEL * RLORA, Av + l * DMODEL * RLORA,
                                            t0, t1, t2);
            gemm_tc<<<gD, 256, GSMEM>>>(ah, al, Wq_h, Wq_l, q, MTOK, DMODEL, DMODEL, t0, Bq_l, 0);
            gemm_tc<<<gD, 256, GSMEM>>>(ah, al, Wk_h, Wk_l, k, MTOK, DMODEL, DMODEL, t1, Bk_l, 0);
            gemm_tc<<<gD, 256, GSMEM>>>(ah, al, Wv_h, Wv_l, v, MTOK, DMODEL, DMODEL, t2, Bv_l, 0);
        }

        rope_kernel<<<(MTOK * NHEAD * 64 + 255) / 256, 256>>>(q, k, qh, ql, kh, kl);
        vsplit_t<<<dim3(MTOK / 32, DMODEL / 32), tB>>>(v, vth, vtl);

        scores_mma<<<dim3(4, 4, BB * NHEAD), 256, SCSM>>>(qh, ql, kh, kl, mT, mM, sc);
        softmax_kernel<<<BB * NHEAD * SEQ, 256>>>(sc, ph, pl);
        attnv_mma<<<dim3(1, 4, BB * NHEAD), 256, AVSM>>>(ph, pl, vth, vtl, o, ah, al);

        lora_fast<1><<<MTOK / 8, 256>>>(o, DMODEL, Ao + (size_t)l * DMODEL * RLORA,
                                        nullptr, nullptr, t0, nullptr, nullptr);
        gemm_tc<<<gD, 256, GSMEM>>>(ah, al, Wo_h, Wo_l, h, MTOK, DMODEL, DMODEL, t0, Bo_l, 1);

        rmsnorm_kernel<<<MTOK, 256>>>(h, ln2 + l * DMODEL, x, ah, al);
        lora_fast<2><<<MTOK / 8, 256>>>(x, DMODEL, Ag + (size_t)l * DMODEL * RLORA,
                                        Au + (size_t)l * DMODEL * RLORA, nullptr,
                                        t0, t1, nullptr);
        gemm_tc<<<gF, 256, GSMEM>>>(ah, al, Wg_h, Wg_l, gg, MTOK, FFDIM, DMODEL, t0, Bg_l, 0);
        gemm_tc<<<gF, 256, GSMEM>>>(ah, al, Wu_h, Wu_l, uu, MTOK, FFDIM, DMODEL, t1, Bu_l, 0);

        swiglu_kernel<<<(int)(((size_t)MTOK * FFDIM + 255) / 256), 256>>>(gg, uu, ah, al);

        lora_fast<1><<<MTOK / 8, 256>>>(gg, FFDIM, Ad + (size_t)l * FFDIM * RLORA,
                                        nullptr, nullptr, t0, nullptr, nullptr);
        gemm_tc<<<gD, 256, GSMEM>>>(ah, al, Wd_h, Wd_l, h, MTOK, DMODEL, FFDIM, t0, Bd_l, 1);
    }

    rmsnorm_kernel<<<MTOK, 256>>>(h, lnf, x, ah, al);
    reps_kernel<<<BB, 256>>>(x, mT, mM, rp);
    loss_kernel<<<1, 256>>>(rp, (float*)d_out);
}

// round 10
// speedup vs baseline: 4.3438x; 1.0002x over previous
#include <cuda_runtime.h>
#include <cuda_bf16.h>
#include <math.h>
#include <stdint.h>

// Problem constants
#define LAYERS 2
#define DMODEL 2048
#define NHEAD  16
#define HDIM   128
#define FFDIM  5632
#define RLORA  16
#define BATCH  4
#define SEQ    512
#define BB     8
#define MTOK   (BB*SEQ)
#define LORA_SCALE 1.4f
#define SCALE_QK 0.08838834764831845f

// ---------------- scratch ----------------
__device__ float g_h   [MTOK * DMODEL];
__device__ float g_x   [MTOK * DMODEL];
__device__ float g_q   [MTOK * DMODEL];
__device__ float g_k   [MTOK * DMODEL];
__device__ float g_v   [MTOK * DMODEL];
__device__ float g_o   [MTOK * DMODEL];
__device__ float g_sc  [BB * NHEAD * SEQ * SEQ];
__device__ float g_gate[MTOK * FFDIM];
__device__ float g_up  [MTOK * FFDIM];
__device__ float g_t   [3 * MTOK * RLORA];
__device__ float g_reps[BB * DMODEL];
__device__ __nv_bfloat16 g_ah[MTOK * FFDIM];
__device__ __nv_bfloat16 g_al[MTOK * FFDIM];
__device__ __nv_bfloat16 g_wh[2 * (4 * DMODEL * DMODEL + 3 * DMODEL * FFDIM)];
__device__ __nv_bfloat16 g_wl[2 * (4 * DMODEL * DMODEL + 3 * DMODEL * FFDIM)];
__device__ __nv_bfloat16 g_qh[MTOK * DMODEL];
__device__ __nv_bfloat16 g_ql[MTOK * DMODEL];
__device__ __nv_bfloat16 g_kh[MTOK * DMODEL];
__device__ __nv_bfloat16 g_kl[MTOK * DMODEL];
__device__ __nv_bfloat16 g_ph[BB * NHEAD * SEQ * SEQ];
__device__ __nv_bfloat16 g_pl[BB * NHEAD * SEQ * SEQ];
__device__ __nv_bfloat16 g_vth[MTOK * DMODEL];
__device__ __nv_bfloat16 g_vtl[MTOK * DMODEL];

// =================== helpers ===================
__device__ __forceinline__ uint32_t smem_u32(const void* p) {
    uint32_t a;
    asm("{ .reg .u64 t; cvta.to.shared.u64 t, %1; cvt.u32.u64 %0, t; }" : "=r"(a) : "l"(p));
    return a;
}
__device__ __forceinline__ void cp_async16(uint32_t saddr, const void* gptr) {
    asm volatile("cp.async.cg.shared.global [%0], [%1], 16;" :: "r"(saddr), "l"(gptr));
}
__device__ __forceinline__ void cp_commit() { asm volatile("cp.async.commit_group;"); }
template <int NWAIT>
__device__ __forceinline__ void cp_wait() {
    asm volatile("cp.async.wait_group %0;" :: "n"(NWAIT));
}
__device__ __forceinline__ void mma16(float* d, const uint32_t* a, uint32_t b0, uint32_t b1) {
    asm volatile(
        "mma.sync.aligned.m16n8k16.row.col.f32.bf16.bf16.f32 "
        "{%0,%1,%2,%3}, {%4,%5,%6,%7}, {%8,%9}, {%0,%1,%2,%3};"
        : "+f"(d[0]), "+f"(d[1]), "+f"(d[2]), "+f"(d[3])
        : "r"(a[0]), "r"(a[1]), "r"(a[2]), "r"(a[3]), "r"(b0), "r"(b1));
}
__device__ __forceinline__ void ldm_x4(uint32_t* r, uint32_t addr) {
    asm volatile("ldmatrix.sync.aligned.m8n8.x4.shared.b16 {%0,%1,%2,%3}, [%4];"
                 : "=r"(r[0]), "=r"(r[1]), "=r"(r[2]), "=r"(r[3]) : "r"(addr));
}
__device__ __forceinline__ void split_bf16(float v, __nv_bfloat16& h, __nv_bfloat16& l) {
    h = __float2bfloat16(v);
    l = __float2bfloat16(v - __bfloat162float(h));
}

// 4-stage pipeline, BK=16. Per-stage arrays: 128 rows x 16 bf16, 48B row stride.
#define SMSB16  48
#define ARRB16  6144
#define STGB16  24576
#define NSTAGE  4
#define LA_OFF  98304
#define LB_OFF  104448
#define GSMEM   110592
#define SCSM    98816    // stages + mask[128]
#define AVSM    98304    // stages only

// ---- compute one 128x16 stage (bf16x3), accumulator-interleaved ----
// Per np: 12 MMAs emitted variant-major so same-accumulator reuse distance = 4.
#define COMPUTE16(stbase)                                                         \
    {                                                                             \
        uint32_t ahf[2][4], alf[2][4];                                            \
        int grp = lane >> 3, r8 = lane & 7;                                       \
        int mm = (grp & 1) * 8 + r8;                                              \
        int koff = (grp >> 1) * 8;                                                \
        _Pragma("unroll")                                                         \
        for (int mt = 0; mt < 2; mt++) {                                          \
            uint32_t ad = (stbase) + (wm * 32 + mt * 16 + mm) * SMSB16 + koff * 2;\
            ldm_x4(ahf[mt], ad);                                                  \
            ldm_x4(alf[mt], ad + ARRB16);                                         \
        }                                                                         \
        _Pragma("unroll")                                                         \
        for (int np = 0; np < 4; np++) {                                          \
            int nn = (grp >> 1) * 8 + r8;                                         \
            int koffb = (grp & 1) * 8;                                            \
            uint32_t bd = (stbase) + 2 * ARRB16 + (wn * 64 + np * 16 + nn) * SMSB16 + koffb * 2; \
            uint32_t bh[4], bl[4];                                                \
            ldm_x4(bh, bd);                                                       \
            ldm_x4(bl, bd + ARRB16);                                              \
            /* variant 1: Ah * Bh  (4 independent accumulators) */                \
            mma16(d[0][np * 2],     ahf[0], bh[0], bh[1]);                        \
            mma16(d[0][np * 2 + 1], ahf[0], bh[2], bh[3]);                        \
            mma16(d[1][np * 2],     ahf[1], bh[0], bh[1]);                        \
            mma16(d[1][np * 2 + 1], ahf[1], bh[2], bh[3]);                        \
            /* variant 2: Ah * Bl */                                              \
            mma16(d[0][np * 2],     ahf[0], bl[0], bl[1]);                        \
            mma16(d[0][np * 2 + 1], ahf[0], bl[2], bl[3]);                        \
            mma16(d[1][np * 2],     ahf[1], bl[0], bl[1]);                        \
            mma16(d[1][np * 2 + 1], ahf[1], bl[2], bl[3]);                        \
            /* variant 3: Al * Bh */                                              \
            mma16(d[0][np * 2],     alf[0], bh[0], bh[1]);                        \
            mma16(d[0][np * 2 + 1], alf[0], bh[2], bh[3]);                        \
            mma16(d[1][np * 2],     alf[1], bh[0], bh[1]);                        \
            mma16(d[1][np * 2 + 1], alf[1], bh[2], bh[3]);                        \
        }                                                                         \
    }

// ---- issue one 128x16 stage of 4 arrays via cp.async ----
#define ISSUE16(kt, aH, aL, bH, bL, LDA, LDB)                                     \
    {                                                                             \
        const int k0_ = (kt) << 4;                                                \
        const int buf_ = (kt) & (NSTAGE - 1);                                     \
        _Pragma("unroll")                                                         \
        for (int j = 0; j < 4; j++) {                                             \
            int e = tid + j * 256;                                                \
            int arr = e >> 8;                                                     \
            int i = e & 255;                                                      \
            int row = i >> 1;                                                     \
            int cg = (i & 1) << 3;                                                \
            const __nv_bfloat16* gp;                                              \
            if (arr == 0)      gp = (aH) + (size_t)row * (LDA) + k0_ + cg;        \
            else if (arr == 1) gp = (aL) + (size_t)row * (LDA) + k0_ + cg;        \
            else if (arr == 2) gp = (bH) + (size_t)row * (LDB) + k0_ + cg;        \
            else               gp = (bL) + (size_t)row * (LDB) + k0_ + cg;        \
            cp_async16(sb + buf_ * STGB16 + arr * ARRB16 + row * SMSB16 + cg * 2, gp); \
        }                                                                         \
        cp_commit();                                                              \
    }

// ---- full multistage mainloop (requires nk >= 3) ----
#define MAINLOOP(nk, aH, aL, bH, bL, LDA, LDB)                                    \
    {                                                                             \
        ISSUE16(0, aH, aL, bH, bL, LDA, LDB);                                     \
        ISSUE16(1, aH, aL, bH, bL, LDA, LDB);                                     \
        ISSUE16(2, aH, aL, bH, bL, LDA, LDB);                                     \
        for (int kt = 0; kt < (nk); kt++) {                                       \
            cp_wait<2>();                                                         \
            __syncthreads();                                                      \
            const uint32_t st_ = sb + (kt & (NSTAGE - 1)) * STGB16;               \
            COMPUTE16(st_)                                                        \
            if (kt + 3 < (nk)) { ISSUE16(kt + 3, aH, aL, bH, bL, LDA, LDB); }     \
            else               { cp_commit(); }                                   \
        }                                                                         \
        cp_wait<0>();                                                             \
        __syncthreads();                                                          \
    }

// =================== main GEMM with fused LoRA + residual ===================
__global__ __launch_bounds__(256, 2)
void gemm_tc(const __nv_bfloat16* __restrict__ Agh, const __nv_bfloat16* __restrict__ Agl,
             const __nv_bfloat16* __restrict__ Wgh, const __nv_bfloat16* __restrict__ Wgl,
             float* __restrict__ C, int M, int N, int K,
             const float* __restrict__ lT, const float* __restrict__ lB, int accum)
{
    extern __shared__ char smc[];
    const int tid  = threadIdx.x;
    const int wid  = tid >> 5;
    const int lane = tid & 31;
    const int t4   = lane & 3;
    const int g    = lane >> 2;
    const int wm   = wid >> 1;
    const int wn   = wid & 1;
    const int bm   = blockIdx.y * 128;
    const int bn   = blockIdx.x * 128;
    const uint32_t sb = smem_u32(smc);

    __nv_bfloat16* la = (__nv_bfloat16*)(smc + LA_OFF);
    __nv_bfloat16* lb = (__nv_bfloat16*)(smc + LB_OFF);
    for (int i = tid; i < 2048; i += 256) {
        int row = i >> 4, r = i & 15;
        la[row * 24 + r] = __float2bfloat16(LORA_SCALE * lT[(size_t)(bm + row) * RLORA + r]);
        lb[row * 24 + r] = __float2bfloat16(lB[(size_t)r * N + bn + row]);
    }

    float d[2][8][4];
    #pragma unroll
    for (int mt = 0; mt < 2; mt++)
        #pragma unroll
        for (int nt = 0; nt < 8; nt++)
            #pragma unroll
            for (int j = 0; j < 4; j++) d[mt][nt][j] = 0.f;

    const __nv_bfloat16* aH = Agh + (size_t)bm * K;
    const __nv_bfloat16* aL = Agl + (size_t)bm * K;
    const __nv_bfloat16* bH = Wgh + (size_t)bn * K;
    const __nv_bfloat16* bL = Wgl + (size_t)bn * K;

    const int nk = K >> 4;
    MAINLOOP(nk, aH, aL, bH, bL, K, K)

    // LoRA tail (hi-only, K=16)
    {
        uint32_t a[2][4];
        #pragma unroll
        for (int mt = 0; mt < 2; mt++) {
            const char* pa = (const char*)la + (wm * 32 + mt * 16 + g) * 48 + t4 * 4;
            a[mt][0] = *(const uint32_t*)(pa);
            a[mt][1] = *(const uint32_t*)(pa + 8 * 48);
            a[mt][2] = *(const uint32_t*)(pa + 16);
            a[mt][3] = *(const uint32_t*)(pa + 8 * 48 + 16);
        }
        #pragma unroll
        for (int nt = 0; nt < 8; nt++) {
            const char* pb = (const char*)lb + (wn * 64 + nt * 8 + g) * 48 + t4 * 4;
            uint32_t b0 = *(const uint32_t*)(pb);
            uint32_t b1 = *(const uint32_t*)(pb + 16);
            #pragma unroll
            for (int mt = 0; mt < 2; mt++) mma16(d[mt][nt], a[mt], b0, b1);
        }
    }

    #pragma unroll
    for (int mt = 0; mt < 2; mt++) {
        const int r0 = bm + wm * 32 + mt * 16 + g;
        #pragma unroll
        for (int nt = 0; nt < 8; nt++) {
            const int c0 = bn + wn * 64 + nt * 8 + 2 * t4;
            float2 v0 = make_float2(d[mt][nt][0], d[mt][nt][1]);
            float2 v1 = make_float2(d[mt][nt][2], d[mt][nt][3]);
            float* p0 = C + (size_t)r0 * N + c0;
            float* p1 = C + (size_t)(r0 + 8) * N + c0;
            if (accum) {
                float2 o0 = *(const float2*)p0;
                float2 o1 = *(const float2*)p1;
                v0.x += o0.x; v0.y += o0.y;
                v1.x += o1.x; v1.y += o1.y;
            }
            *(float2*)p0 = v0;
            *(float2*)p1 = v1;
        }
    }
}

// =================== scores ===================
__global__ __launch_bounds__(256, 2)
void scores_mma(const __nv_bfloat16* __restrict__ Qh, const __nv_bfloat16* __restrict__ Ql,
                const __nv_bfloat16* __restrict__ Kh, const __nv_bfloat16* __restrict__ Kl,
                const int* __restrict__ mT, const int* __restrict__ mM,
                float* __restrict__ S_)
{
    extern __shared__ char smc[];
    const int tid  = threadIdx.x;
    const int wid  = tid >> 5;
    const int lane = tid & 31;
    const int t4   = lane & 3;
    const int g    = lane >> 2;
    const int wm   = wid >> 1;
    const int wn   = wid & 1;
    const int z    = blockIdx.z;
    const int bb   = z >> 4;
    const int hh   = z & 15;
    const int bm   = blockIdx.y * 128;
    const int bn   = blockIdx.x * 128;
    const uint32_t sb = smem_u32(smc);
    int* msk = (int*)(smc + NSTAGE * STGB16);

    const int* mask = (bb < 4) ? (mT + bb * SEQ) : (mM + (bb - 4) * SEQ);
    if (tid < 128) msk[tid] = mask[bn + tid];

    float* Sbase = S_ + (size_t)z * SEQ * SEQ;

    if (bn > bm) {
        __syncthreads();
        for (int i = tid; i < 128 * 128; i += 256) {
            int r = i >> 7, c = i & 127;
            Sbase[(size_t)(bm + r) * SEQ + bn + c] = -1e9f;
        }
        return;
    }

    float d[2][8][4];
    #pragma unroll
    for (int mt = 0; mt < 2; mt++)
        #pragma unroll
        for (int nt = 0; nt < 8; nt++)
            #pragma unroll
            for (int j = 0; j < 4; j++) d[mt][nt][j] = 0.f;

    const __nv_bfloat16* aH = Qh + (size_t)(bb * SEQ + bm) * DMODEL + hh * HDIM;
    const __nv_bfloat16* aL = Ql + (size_t)(bb * SEQ + bm) * DMODEL + hh * HDIM;
    const __nv_bfloat16* bH = Kh + (size_t)(bb * SEQ + bn) * DMODEL + hh * HDIM;
    const __nv_bfloat16* bL = Kl + (size_t)(bb * SEQ + bn) * DMODEL + hh * HDIM;

    const int nk = HDIM >> 4;   // 8
    MAINLOOP(nk, aH, aL, bH, bL, DMODEL, DMODEL)

    #pragma unroll
    for (int mt = 0; mt < 2; mt++) {
        const int r0 = wm * 32 + mt * 16 + g;
        #pragma unroll
        for (int nt = 0; nt < 8; nt++) {
            const int c0 = wn * 64 + nt * 8 + 2 * t4;
            #pragma unroll
            for (int half = 0; half < 2; half++) {
                int r = r0 + half * 8;
                int sq = bm + r, sk0 = bn + c0;
                float va = d[mt][nt][half * 2], vb = d[mt][nt][half * 2 + 1];
                bool ok0 = (sk0 <= sq) && (msk[c0] > 0);
                bool ok1 = (sk0 + 1 <= sq) && (msk[c0 + 1] > 0);
                float2 out;
                out.x = va * SCALE_QK + (ok0 ? 0.f : -1e9f);
                out.y = vb * SCALE_QK + (ok1 ? 0.f : -1e9f);
                *(float2*)(Sbase + (size_t)sq * SEQ + sk0) = out;
            }
        }
    }
}

// =================== attnv (causal-truncated K loop) ===================
__global__ __launch_bounds__(256, 2)
void attnv_mma(const __nv_bfloat16* __restrict__ Ph, const __nv_bfloat16* __restrict__ Pl,
               const __nv_bfloat16* __restrict__ Vth, const __nv_bfloat16* __restrict__ Vtl,
               float* __restrict__ O,
               __nv_bfloat16* __restrict__ Oh, __nv_bfloat16* __restrict__ Ol)
{
    extern __shared__ char smc[];
    const int tid  = threadIdx.x;
    const int wid  = tid >> 5;
    const int lane = tid & 31;
    const int t4   = lane & 3;
    const int g    = lane >> 2;
    const int wm   = wid >> 1;
    const int wn   = wid & 1;
    const int z    = blockIdx.z;
    const int bb   = z >> 4;
    const int hh   = z & 15;
    const int bm   = blockIdx.y * 128;
    const uint32_t sb = smem_u32(smc);

    float d[2][8][4];
    #pragma unroll
    for (int mt = 0; mt < 2; mt++)
        #pragma unroll
        for (int nt = 0; nt < 8; nt++)
            #pragma unroll
            for (int j = 0; j < 4; j++) d[mt][nt][j] = 0.f;

    const __nv_bfloat16* aH = Ph + ((size_t)z * SEQ + bm) * SEQ;
    const __nv_bfloat16* aL = Pl + ((size_t)z * SEQ + bm) * SEQ;
    const __nv_bfloat16* bH = Vth + (size_t)z * HDIM * SEQ;
    const __nv_bfloat16* bL = Vtl + (size_t)z * HDIM * SEQ;

    // causal: P[bm..bm+127][k] == 0 for k >= bm+128
    const int nk = (bm >> 4) + 8;
    MAINLOOP(nk, aH, aL, bH, bL, SEQ, SEQ)

    #pragma unroll
    for (int mt = 0; mt < 2; mt++) {
        const int r0 = bm + wm * 32 + mt * 16 + g;
        #pragma unroll
        for (int nt = 0; nt < 8; nt++) {
            const int c0 = wn * 64 + nt * 8 + 2 * t4;
            #pragma unroll
            for (int half = 0; half < 2; half++) {
                int r = r0 + half * 8;
                size_t oidx = (size_t)(bb * SEQ + r) * DMODEL + hh * HDIM + c0;
                float va = d[mt][nt][half * 2], vb = d[mt][nt][half * 2 + 1];
                *(float2*)(O + oidx) = make_float2(va, vb);
                __nv_bfloat16 h0, l0, h1, l1;
                split_bf16(va, h0, l0);
                split_bf16(vb, h1, l1);
                Oh[oidx] = h0; Oh[oidx + 1] = h1;
                Ol[oidx] = l0; Ol[oidx + 1] = l1;
            }
        }
    }
}

// =================== fast LoRA-T ===================
#define LCH 512
template <int NM>
__global__ __launch_bounds__(256)
void lora_fast(const float* __restrict__ X, int K,
               const float* __restrict__ A0, const float* __restrict__ A1,
               const float* __restrict__ A2,
               float* __restrict__ T0, float* __restrict__ T1, float* __restrict__ T2)
{
    __shared__ float At[16 * 513];
    const int tid  = threadIdx.x;
    const int lane = tid & 31;
    const int warp = tid >> 5;
    const int row  = blockIdx.x * 8 + warp;

    const float* As[3] = {A0, A1, A2};
    float acc[NM][16];
    #pragma unroll
    for (int m = 0; m < NM; m++)
        #pragma unroll
        for (int r = 0; r < 16; r++) acc[m][r] = 0.f;

    for (int k0 = 0; k0 < K; k0 += LCH) {
        float xs[16];
        #pragma unroll
        for (int j = 0; j < 16; j++)
            xs[j] = X[(size_t)row * K + k0 + lane + 32 * j];
        #pragma unroll
        for (int m = 0; m < NM; m++) {
            __syncthreads();
            const float* Am = As[m];
            for (int i = tid; i < 16 * LCH; i += 256) {
                int k = i >> 4, r = i & 15;
                At[r * 513 + k] = Am[(size_t)(k0 + k) * RLORA + r];
            }
            __syncthreads();
            #pragma unroll
            for (int j = 0; j < 16; j++) {
                int k = lane + 32 * j;
                float xv = xs[j];
                #pragma unroll
                for (int r = 0; r < 16; r++)
                    acc[m][r] += xv * At[r * 513 + k];
            }
        }
    }

    float* Ts[3] = {T0, T1, T2};
    #pragma unroll
    for (int m = 0; m < NM; m++) {
        #pragma unroll
        for (int r = 0; r < 16; r++) {
            float v = acc[m][r];
            #pragma unroll
            for (int o = 16; o > 0; o >>= 1) v += __shfl_xor_sync(0xffffffffu, v, o);
            if (lane == 0) Ts[m][row * RLORA + r] = v;
        }
    }
}

// ---------------- weight transpose + split ----------------
__global__ void transpose_split(const float* __restrict__ W,
                                __nv_bfloat16* __restrict__ Wh, __nv_bfloat16* __restrict__ Wl,
                                int Kd, int Nd)
{
    __shared__ float tile[32][33];
    int n0 = blockIdx.x * 32, k0 = blockIdx.y * 32;
    int x = threadIdx.x, y = threadIdx.y;
    #pragma unroll
    for (int dy = 0; dy < 32; dy += 8)
        tile[y + dy][x] = W[(size_t)(k0 + y + dy) * Nd + n0 + x];
    __syncthreads();
    #pragma unroll
    for (int dy = 0; dy < 32; dy += 8) {
        float v = tile[x][y + dy];
        size_t o = (size_t)(n0 + y + dy) * Kd + k0 + x;
        __nv_bfloat16 h, l;
        split_bf16(v, h, l);
        Wh[o] = h; Wl[o] = l;
    }
}

// ---------------- V transpose + split per head ----------------
__global__ void vsplit_t(const float* __restrict__ V,
                         __nv_bfloat16* __restrict__ Vth, __nv_bfloat16* __restrict__ Vtl)
{
    __shared__ float tile[32][33];
    int tok0 = blockIdx.x * 32, d0 = blockIdx.y * 32;
    int x = threadIdx.x, y = threadIdx.y;
    #pragma unroll
    for (int dy = 0; dy < 32; dy += 8)
        tile[y + dy][x] = V[(size_t)(tok0 + y + dy) * DMODEL + d0 + x];
    __syncthreads();
    int bb = tok0 >> 9, s0 = tok0 & 511;
    int hh = d0 >> 7, dd0 = d0 & 127;
    size_t zb = ((size_t)(bb * NHEAD + hh)) * HDIM * SEQ;
    #pragma unroll
    for (int dy = 0; dy < 32; dy += 8) {
        float v = tile[x][y + dy];
        size_t oidx = zb + (size_t)(dd0 + y + dy) * SEQ + s0 + x;
        __nv_bfloat16 h, l;
        split_bf16(v, h, l);
        Vth[oidx] = h; Vtl[oidx] = l;
    }
}

// ---------------- fused embed + rmsnorm(ln1 layer0) ----------------
__global__ void embed_rms(const int* __restrict__ idT, const int* __restrict__ idM,
                          const float* __restrict__ E, const float* __restrict__ W,
                          float* __restrict__ H, float* __restrict__ X,
                          __nv_bfloat16* __restrict__ Xh, __nv_bfloat16* __restrict__ Xl)
{
    __shared__ float red[256];
    int t  = blockIdx.x;
    int bb = t >> 9;
    int s  = t & 511;
    int id = (bb < 4) ? idT[bb * SEQ + s] : idM[(bb - 4) * SEQ + s];
    const float* src = E + (size_t)id * DMODEL;
    int tid = threadIdx.x;
    float vals[8];
    float ss = 0.f;
    #pragma unroll
    for (int j = 0; j < 8; j++) {
        float v = src[tid + 256 * j];
        vals[j] = v;
        ss += v * v;
    }
    red[tid] = ss; __syncthreads();
    for (int o = 128; o > 0; o >>= 1) {
        if (tid < o) red[tid] += red[tid + o];
        __syncthreads();
    }
    float scale = rsqrtf(red[0] / (float)DMODEL + 1e-6f);
    size_t base = (size_t)t * DMODEL;
    #pragma unroll
    for (int j = 0; j < 8; j++) {
        int idx = tid + 256 * j;
        float v = vals[j];
        H[base + idx] = v;
        float xv = v * scale * W[idx];
        X[base + idx] = xv;
        __nv_bfloat16 hh, ll;
        split_bf16(xv, hh, ll);
        Xh[base + idx] = hh; Xl[base + idx] = ll;
    }
}

// ---------------- rmsnorm ----------------
__global__ void rmsnorm_kernel(const float* __restrict__ H, const float* __restrict__ W,
                               float* __restrict__ X,
                               __nv_bfloat16* __restrict__ Xh, __nv_bfloat16* __restrict__ Xl)
{
    __shared__ float red[256];
    int row = blockIdx.x;
    const float* h = H + (size_t)row * DMODEL;
    int tid = threadIdx.x;
    float vals[8];
    float s = 0.f;
    #pragma unroll
    for (int j = 0; j < 8; j++) {
        float v = h[tid + 256 * j];
        vals[j] = v;
        s += v * v;
    }
    red[tid] = s; __syncthreads();
    for (int o = 128; o > 0; o >>= 1) {
        if (tid < o) red[tid] += red[tid + o];
        __syncthreads();
    }
    float scale = rsqrtf(red[0] / (float)DMODEL + 1e-6f);
    size_t base = (size_t)row * DMODEL;
    #pragma unroll
    for (int j = 0; j < 8; j++) {
        int idx = tid + 256 * j;
        float v = vals[j] * scale * W[idx];
        X[base + idx] = v;
        __nv_bfloat16 hh, ll;
        split_bf16(v, hh, ll);
        Xh[base + idx] = hh; Xl[base + idx] = ll;
    }
}

// ---------------- RoPE ----------------
__global__ void rope_kernel(const float* __restrict__ Q, const float* __restrict__ Kt,
                            __nv_bfloat16* __restrict__ Qh, __nv_bfloat16* __restrict__ Ql,
                            __nv_bfloat16* __restrict__ Kh, __nv_bfloat16* __restrict__ Kl)
{
    int i = blockIdx.x * blockDim.x + threadIdx.x;
    if (i >= MTOK * NHEAD * 64) return;
    int d = i & 63;
    int h = (i >> 6) & 15;
    int t = i >> 10;
    int s = t & 511;
    float freq = expf(-(float)d * (logf(10000.f) / 64.f));
    float ang = (float)s * freq;
    float sn, cs;
    sincosf(ang, &sn, &cs);
    size_t b0 = (size_t)t * DMODEL + h * HDIM + d;
    __nv_bfloat16 hh, ll;
    float x1 = Q[b0], x2 = Q[b0 + 64];
    float r1 = x1 * cs - x2 * sn;
    float r2 = x1 * sn + x2 * cs;
    split_bf16(r1, hh, ll); Qh[b0] = hh;      Ql[b0] = ll;
    split_bf16(r2, hh, ll); Qh[b0 + 64] = hh; Ql[b0 + 64] = ll;
    x1 = Kt[b0]; x2 = Kt[b0 + 64];
    r1 = x1 * cs - x2 * sn;
    r2 = x1 * sn + x2 * cs;
    split_bf16(r1, hh, ll); Kh[b0] = hh;      Kl[b0] = ll;
    split_bf16(r2, hh, ll); Kh[b0 + 64] = hh; Kl[b0 + 64] = ll;
}

// ---------------- row softmax ----------------
__global__ void softmax_kernel(const float* __restrict__ S_,
                               __nv_bfloat16* __restrict__ Ph, __nv_bfloat16* __restrict__ Pl)
{
    __shared__ float red[256];
    const float* p = S_ + (size_t)blockIdx.x * SEQ;
    int t = threadIdx.x;
    float v0 = p[t], v1 = p[t + 256];
    float m = fmaxf(v0, v1);
    red[t] = m; __syncthreads();
    for (int o = 128; o > 0; o >>= 1) {
        if (t < o) red[t] = fmaxf(red[t], red[t + o]);
        __syncthreads();
    }
    m = red[0]; __syncthreads();
    float e0 = expf(v0 - m), e1 = expf(v1 - m);
    red[t] = e0 + e1; __syncthreads();
    for (int o = 128; o > 0; o >>= 1) {
        if (t < o) red[t] += red[t + o];
        __syncthreads();
    }
    float inv = 1.f / red[0];
    size_t base = (size_t)blockIdx.x * SEQ;
    __nv_bfloat16 hh, ll;
    split_bf16(e0 * inv, hh, ll); Ph[base + t] = hh;       Pl[base + t] = ll;
    split_bf16(e1 * inv, hh, ll); Ph[base + t + 256] = hh; Pl[base + t + 256] = ll;
}

// ---------------- swiglu ----------------
__global__ void swiglu_kernel(float* __restrict__ G, const float* __restrict__ U,
                              __nv_bfloat16* __restrict__ Gh, __nv_bfloat16* __restrict__ Gl)
{
    size_t i = (size_t)blockIdx.x * blockDim.x + threadIdx.x;
    if (i >= (size_t)MTOK * FFDIM) return;
    float g = G[i];
    float sig = 1.f / (1.f + expf(-g));
    float v = g * sig * U[i];
    G[i] = v;
    __nv_bfloat16 hh, ll;
    split_bf16(v, hh, ll);
    Gh[i] = hh; Gl[i] = ll;
}

// ---------------- reps extraction + L2 normalize ----------------
__global__ void reps_kernel(const float* __restrict__ X, const int* __restrict__ mT,
                            const int* __restrict__ mM, float* __restrict__ R_)
{
    __shared__ int ired[256];
    __shared__ float fred[256];
    __shared__ int sidx;
    int bb = blockIdx.x;
    const int* mask = (bb < 4) ? mT : mM;
    int b = bb & 3;
    int t = threadIdx.x;
    int s = 0;
    for (int j = t; j < SEQ; j += 256) s += mask[b * SEQ + j];
    ired[t] = s; __syncthreads();
    for (int o = 128; o > 0; o >>= 1) {
        if (t < o) ired[t] += ired[t + o];
        __syncthreads();
    }
    if (t == 0) {
        int last = mask[0 * SEQ + 511] + mask[1 * SEQ + 511] +
                   mask[2 * SEQ + 511] + mask[3 * SEQ + 511];
        sidx = (last == BATCH) ? (SEQ - 1) : (ired[0] - 1);
    }
    __syncthreads();
    const float* row = X + (size_t)(bb * SEQ + sidx) * DMODEL;
    float ss = 0.f;
    for (int j = t; j < DMODEL; j += 256) { float v = row[j]; ss += v * v; }
    fred[t] = ss; __syncthreads();
    for (int o = 128; o > 0; o >>= 1) {
        if (t < o) fred[t] += fred[t + o];
        __syncthreads();
    }
    float inv = 1.f / sqrtf(fred[0]);
    for (int j = t; j < DMODEL; j += 256) R_[bb * DMODEL + j] = row[j] * inv;
}

// ---------------- contrastive loss ----------------
__global__ void loss_kernel(const float* __restrict__ R_, float* __restrict__ out)
{
    __shared__ float sims[16];
    int tid = threadIdx.x;
    int warp = tid >> 5, lane = tid & 31;
    for (int p = warp; p < 16; p += 8) {
        int i = p >> 2, j = p & 3;
        const float* a = R_ + i * DMODEL;
        const float* bR = R_ + (4 + j) * DMODEL;
        float d = 0.f;
        for (int k2 = lane; k2 < DMODEL; k2 += 32) d += a[k2] * bR[k2];
        #pragma unroll
        for (int o = 16; o > 0; o >>= 1) d += __shfl_xor_sync(0xffffffff, d, o);
        if (lane == 0) sims[p] = d * 20.f;
    }
    __syncthreads();
    if (tid == 0) {
        float loss = 0.f;
        for (int i = 0; i < 4; i++) {
            float m = -1e30f;
            for (int j = 0; j < 4; j++) m = fmaxf(m, sims[i * 4 + j]);
            float sum = 0.f;
            for (int j = 0; j < 4; j++) sum += expf(sims[i * 4 + j] - m);
            loss += (logf(sum) + m) - sims[i * 4 + i];
        }
        out[0] = loss * 0.25f;
    }
}

// ---------------- host driver ----------------
static void* symaddr_raw(const void* sym)
{
    void* p = nullptr;
    cudaGetSymbolAddress(&p, sym);
    return p;
}

extern "C" void kernel_launch(void* const* d_in, const int* in_sizes, int n_in,
                              void* d_out, int out_size)
{
    const int*   idT = (const int*)d_in[0];
    const int*   mT  = (const int*)d_in[1];
    const int*   idM = (const int*)d_in[2];
    const int*   mM  = (const int*)d_in[3];
    const float* emb = (const float*)d_in[4];
    const float* ln1 = (const float*)d_in[5];
    const float* ln2 = (const float*)d_in[6];
    const float* lnf = (const float*)d_in[7];
    const float* Wq = (const float*)d_in[8],  *Aq = (const float*)d_in[9],  *Bq = (const float*)d_in[10];
    const float* Wk = (const float*)d_in[11], *Ak = (const float*)d_in[12], *Bk = (const float*)d_in[13];
    const float* Wv = (const float*)d_in[14], *Av = (const float*)d_in[15], *Bv = (const float*)d_in[16];
    const float* Wo = (const float*)d_in[17], *Ao = (const float*)d_in[18], *Bo = (const float*)d_in[19];
    const float* Wg = (const float*)d_in[20], *Ag = (const float*)d_in[21], *Bg = (const float*)d_in[22];
    const float* Wu = (const float*)d_in[23], *Au = (const float*)d_in[24], *Bu = (const float*)d_in[25];
    const float* Wd = (const float*)d_in[26], *Ad = (const float*)d_in[27], *Bd = (const float*)d_in[28];

    float* h  = (float*)symaddr_raw(g_h);
    float* x  = (float*)symaddr_raw(g_x);
    float* q  = (float*)symaddr_raw(g_q);
    float* k  = (float*)symaddr_raw(g_k);
    float* v  = (float*)symaddr_raw(g_v);
    float* o  = (float*)symaddr_raw(g_o);
    float* sc = (float*)symaddr_raw(g_sc);
    float* gg = (float*)symaddr_raw(g_gate);
    float* uu = (float*)symaddr_raw(g_up);
    float* t0 = (float*)symaddr_raw(g_t);
    float* t1 = t0 + MTOK * RLORA;
    float* t2 = t0 + 2 * MTOK * RLORA;
    float* rp = (float*)symaddr_raw(g_reps);
    __nv_bfloat16* ah  = (__nv_bfloat16*)symaddr_raw(g_ah);
    __nv_bfloat16* al  = (__nv_bfloat16*)symaddr_raw(g_al);
    __nv_bfloat16* wh  = (__nv_bfloat16*)symaddr_raw(g_wh);
    __nv_bfloat16* wl  = (__nv_bfloat16*)symaddr_raw(g_wl);
    __nv_bfloat16* qh  = (__nv_bfloat16*)symaddr_raw(g_qh);
    __nv_bfloat16* ql  = (__nv_bfloat16*)symaddr_raw(g_ql);
    __nv_bfloat16* kh  = (__nv_bfloat16*)symaddr_raw(g_kh);
    __nv_bfloat16* kl  = (__nv_bfloat16*)symaddr_raw(g_kl);
    __nv_bfloat16* ph  = (__nv_bfloat16*)symaddr_raw(g_ph);
    __nv_bfloat16* pl  = (__nv_bfloat16*)symaddr_raw(g_pl);
    __nv_bfloat16* vth = (__nv_bfloat16*)symaddr_raw(g_vth);
    __nv_bfloat16* vtl = (__nv_bfloat16*)symaddr_raw(g_vtl);

    cudaFuncSetAttribute(gemm_tc,    cudaFuncAttributeMaxDynamicSharedMemorySize, GSMEM);
    cudaFuncSetAttribute(scores_mma, cudaFuncAttributeMaxDynamicSharedMemorySize, SCSM);
    cudaFuncSetAttribute(attnv_mma,  cudaFuncAttributeMaxDynamicSharedMemorySize, AVSM);

    const size_t DD = (size_t)DMODEL * DMODEL;
    const size_t DF = (size_t)DMODEL * FFDIM;
    const size_t LSTR = 4 * DD + 3 * DF;
    const dim3 tD(DMODEL / 32, DMODEL / 32), tB(32, 8);
    const dim3 tF(FFDIM / 32, DMODEL / 32);
    const dim3 tFd(DMODEL / 32, FFDIM / 32);
    const dim3 gD(DMODEL / 128, MTOK / 128);
    const dim3 gF(FFDIM / 128, MTOK / 128);

    // ---- prologue: gemm_tc at launch slots 3 and 5 for ncu ----
    transpose_split<<<tD, tB>>>(Wq, wh, wl, DMODEL, DMODEL);                          // 0
    embed_rms<<<MTOK, 256>>>(idT, idM, emb, ln1, h, x, ah, al);                       // 1
    lora_fast<3><<<MTOK / 8, 256>>>(x, DMODEL, Aq, Ak, Av, t0, t1, t2);               // 2
    gemm_tc<<<gD, 256, GSMEM>>>(ah, al, wh, wl, q, MTOK, DMODEL, DMODEL, t0, Bq, 0);  // 3
    transpose_split<<<tD, tB>>>(Wk, wh + DD, wl + DD, DMODEL, DMODEL);                // 4
    gemm_tc<<<gD, 256, GSMEM>>>(ah, al, wh + DD, wl + DD, k, MTOK, DMODEL, DMODEL, t1, Bk, 0); // 5
    transpose_split<<<tD, tB>>>(Wv, wh + 2 * DD, wl + 2 * DD, DMODEL, DMODEL);        // 6
    gemm_tc<<<gD, 256, GSMEM>>>(ah, al, wh + 2 * DD, wl + 2 * DD, v, MTOK, DMODEL, DMODEL, t2, Bv, 0); // 7

    // remaining transposes
    transpose_split<<<tD, tB>>>(Wo, wh + 3 * DD, wl + 3 * DD, DMODEL, DMODEL);
    transpose_split<<<tF, tB>>>(Wg, wh + 4 * DD, wl + 4 * DD, DMODEL, FFDIM);
    transpose_split<<<tF, tB>>>(Wu, wh + 4 * DD + DF, wl + 4 * DD + DF, DMODEL, FFDIM);
    transpose_split<<<tFd, tB>>>(Wd, wh + 4 * DD + 2 * DF, wl + 4 * DD + 2 * DF, FFDIM, DMODEL);
    for (int l = 1; l < LAYERS; l++) {
        size_t off = (size_t)l * LSTR;
        transpose_split<<<tD, tB>>>(Wq + l * DD, wh + off,          wl + off,          DMODEL, DMODEL);
        transpose_split<<<tD, tB>>>(Wk + l * DD, wh + off + DD,     wl + off + DD,     DMODEL, DMODEL);
        transpose_split<<<tD, tB>>>(Wv + l * DD, wh + off + 2 * DD, wl + off + 2 * DD, DMODEL, DMODEL);
        transpose_split<<<tD, tB>>>(Wo + l * DD, wh + off + 3 * DD, wl + off + 3 * DD, DMODEL, DMODEL);
        transpose_split<<<tF, tB>>>(Wg + l * DF, wh + off + 4 * DD, wl + off + 4 * DD, DMODEL, FFDIM);
        transpose_split<<<tF, tB>>>(Wu + l * DF, wh + off + 4 * DD + DF, wl + off + 4 * DD + DF, DMODEL, FFDIM);
        transpose_split<<<tFd, tB>>>(Wd + l * DF, wh + off + 4 * DD + 2 * DF, wl + off + 4 * DD + 2 * DF, FFDIM, DMODEL);
    }

    for (int l = 0; l < LAYERS; l++) {
        size_t off = (size_t)l * LSTR;
        const __nv_bfloat16 *Wq_h = wh + off,               *Wq_l = wl + off;
        const __nv_bfloat16 *Wk_h = wh + off + DD,          *Wk_l = wl + off + DD;
        const __nv_bfloat16 *Wv_h = wh + off + 2 * DD,      *Wv_l = wl + off + 2 * DD;
        const __nv_bfloat16 *Wo_h = wh + off + 3 * DD,      *Wo_l = wl + off + 3 * DD;
        const __nv_bfloat16 *Wg_h = wh + off + 4 * DD,      *Wg_l = wl + off + 4 * DD;
        const __nv_bfloat16 *Wu_h = wh + off + 4 * DD + DF, *Wu_l = wl + off + 4 * DD + DF;
        const __nv_bfloat16 *Wd_h = wh + off + 4 * DD + 2 * DF, *Wd_l = wl + off + 4 * DD + 2 * DF;
        const float* Bq_l = Bq + (size_t)l * RLORA * DMODEL;
        const float* Bk_l = Bk + (size_t)l * RLORA * DMODEL;
        const float* Bv_l = Bv + (size_t)l * RLORA * DMODEL;
        const float* Bo_l = Bo + (size_t)l * RLORA * DMODEL;
        const float* Bg_l = Bg + (size_t)l * RLORA * FFDIM;
        const float* Bu_l = Bu + (size_t)l * RLORA * FFDIM;
        const float* Bd_l = Bd + (size_t)l * RLORA * DMODEL;

        if (l > 0) {
            rmsnorm_kernel<<<MTOK, 256>>>(h, ln1 + l * DMODEL, x, ah, al);
            lora_fast<3><<<MTOK / 8, 256>>>(x, DMODEL, Aq + l * DMODEL * RLORA,
                                            Ak + l * DMODEL * RLORA, Av + l * DMODEL * RLORA,
                                            t0, t1, t2);
            gemm_tc<<<gD, 256, GSMEM>>>(ah, al, Wq_h, Wq_l, q, MTOK, DMODEL, DMODEL, t0, Bq_l, 0);
            gemm_tc<<<gD, 256, GSMEM>>>(ah, al, Wk_h, Wk_l, k, MTOK, DMODEL, DMODEL, t1, Bk_l, 0);
            gemm_tc<<<gD, 256, GSMEM>>>(ah, al, Wv_h, Wv_l, v, MTOK, DMODEL, DMODEL, t2, Bv_l, 0);
        }

        rope_kernel<<<(MTOK * NHEAD * 64 + 255) / 256, 256>>>(q, k, qh, ql, kh, kl);
        vsplit_t<<<dim3(MTOK / 32, DMODEL / 32), tB>>>(v, vth, vtl);

        scores_mma<<<dim3(4, 4, BB * NHEAD), 256, SCSM>>>(qh, ql, kh, kl, mT, mM, sc);
        softmax_kernel<<<BB * NHEAD * SEQ, 256>>>(sc, ph, pl);
        attnv_mma<<<dim3(1, 4, BB * NHEAD), 256, AVSM>>>(ph, pl, vth, vtl, o, ah, al);

        lora_fast<1><<<MTOK / 8, 256>>>(o, DMODEL, Ao + (size_t)l * DMODEL * RLORA,
                                        nullptr, nullptr, t0, nullptr, nullptr);
        gemm_tc<<<gD, 256, GSMEM>>>(ah, al, Wo_h, Wo_l, h, MTOK, DMODEL, DMODEL, t0, Bo_l, 1);

        rmsnorm_kernel<<<MTOK, 256>>>(h, ln2 + l * DMODEL, x, ah, al);
        lora_fast<2><<<MTOK / 8, 256>>>(x, DMODEL, Ag + (size_t)l * DMODEL * RLORA,
                                        Au + (size_t)l * DMODEL * RLORA, nullptr,
                                        t0, t1, nullptr);
        gemm_tc<<<gF, 256, GSMEM>>>(ah, al, Wg_h, Wg_l, gg, MTOK, FFDIM, DMODEL, t0, Bg_l, 0);
        gemm_tc<<<gF, 256, GSMEM>>>(ah, al, Wu_h, Wu_l, uu, MTOK, FFDIM, DMODEL, t1, Bu_l, 0);

        swiglu_kernel<<<(int)(((size_t)MTOK * FFDIM + 255) / 256), 256>>>(gg, uu, ah, al);

        lora_fast<1><<<MTOK / 8, 256>>>(gg, FFDIM, Ad + (size_t)l * FFDIM * RLORA,
                                        nullptr, nullptr, t0, nullptr, nullptr);
        gemm_tc<<<gD, 256, GSMEM>>>(ah, al, Wd_h, Wd_l, h, MTOK, DMODEL, FFDIM, t0, Bd_l, 1);
    }

    rmsnorm_kernel<<<MTOK, 256>>>(h, lnf, x, ah, al);
    reps_kernel<<<BB, 256>>>(x, mT, mM, rp);
    loss_kernel<<<1, 256>>>(rp, (float*)d_out);
}